// round 5
// baseline (speedup 1.0000x reference)
#include <cuda_runtime.h>
#include <cuda_bf16.h>
#include <cstdint>

#define HID 4096
#define MROWS 2048
#define NKV 512
#define VECD 64
#define NHEAD 16
#define NBH 64            // B * NHEAD
#define SDUP 2048         // S * DUP per (b,h)

// ---------------- scratch (device globals; allocation-free rule) ----------
__device__ float g_q[MROWS * HID];
__device__ float g_attnT[NBH * SDUP * VECD];       // attention out, [bh][sdup][vec]
__device__ __nv_bfloat16 g_qhi[NBH * SDUP * VECD], g_qlo[NBH * SDUP * VECD];
__device__ __nv_bfloat16 g_khi[NBH * NKV * VECD], g_klo[NBH * NKV * VECD];
__device__ __nv_bfloat16 g_vhi[NBH * VECD * NKV], g_vlo[NBH * VECD * NKV];  // [bh][vec][n]
__device__ __nv_bfloat16 g_ehi[MROWS * HID], g_elo[MROWS * HID];
__device__ __nv_bfloat16 g_lnhi[MROWS * HID], g_lnlo[MROWS * HID];
__device__ __nv_bfloat16 g_wqhi[HID * HID], g_wqlo[HID * HID];
__device__ __nv_bfloat16 g_wrehi[HID * HID], g_wrelo[HID * HID];

// ---------------- PTX helpers ----------------------------------------------
__device__ __forceinline__ uint32_t smem_u32(const void* p) {
    uint32_t a;
    asm("{ .reg .u64 t; cvta.to.shared.u64 t, %1; cvt.u32.u64 %0, t; }" : "=r"(a) : "l"(p));
    return a;
}
#define CP_ASYNC16(dst, src) \
    asm volatile("cp.async.cg.shared.global [%0], [%1], 16;" :: "r"(dst), "l"(src))
#define CP_COMMIT() asm volatile("cp.async.commit_group;" ::: "memory")
#define CP_WAIT2()  asm volatile("cp.async.wait_group 2;" ::: "memory")
#define CP_WAIT0()  asm volatile("cp.async.wait_group 0;" ::: "memory")

#define LDSM4(r0, r1, r2, r3, addr)                                          \
    asm volatile("ldmatrix.sync.aligned.m8n8.x4.shared.b16 {%0,%1,%2,%3}, [%4];" \
                 : "=r"(r0), "=r"(r1), "=r"(r2), "=r"(r3) : "r"(addr))
#define LDSM2(r0, r1, addr)                                                  \
    asm volatile("ldmatrix.sync.aligned.m8n8.x2.shared.b16 {%0,%1}, [%2];"   \
                 : "=r"(r0), "=r"(r1) : "r"(addr))

__device__ __forceinline__ void mma16816(float* c, const uint32_t* a, const uint32_t* b) {
    asm volatile(
        "mma.sync.aligned.m16n8k16.row.col.f32.bf16.bf16.f32 "
        "{%0,%1,%2,%3}, {%4,%5,%6,%7}, {%8,%9}, {%0,%1,%2,%3};"
        : "+f"(c[0]), "+f"(c[1]), "+f"(c[2]), "+f"(c[3])
        : "r"(a[0]), "r"(a[1]), "r"(a[2]), "r"(a[3]), "r"(b[0]), "r"(b[1]));
}

__device__ __forceinline__ uint32_t pack_bf16(float a, float b) {
    __nv_bfloat162 t = __floats2bfloat162_rn(a, b);
    return *(uint32_t*)&t;
}

// swizzled byte offset within a 128x32 bf16 tile (64B rows, 16B chunks) — GEMM
__device__ __forceinline__ uint32_t sw_off(int r, int c16) {
    return (uint32_t)(r * 64 + ((c16 ^ ((r >> 1) & 3)) << 4));
}
// swizzle for 128B rows (8 chunks) or 256B rows (16 chunks): x = c ^ (r&7)
__device__ __forceinline__ uint32_t sw128(int r, int c16) {
    return (uint32_t)(r * 128 + ((c16 ^ (r & 7)) << 4));
}
__device__ __forceinline__ uint32_t sw256(int r, int c16) {
    return (uint32_t)(r * 256 + ((c16 ^ (r & 7)) << 4));
}

// ---------------------------------------------------------------------------
// bf16-split tensor-core GEMM (unchanged from R3, proven)
// ---------------------------------------------------------------------------
#define GEMM_STAGE_BYTES 32768
#define GEMM_SMEM (3 * GEMM_STAGE_BYTES)
__global__ __launch_bounds__(256, 2)
void gemm_mma_kernel(const __nv_bfloat16* __restrict__ Ahi, const __nv_bfloat16* __restrict__ Alo,
                     const __nv_bfloat16* __restrict__ Bhi, const __nv_bfloat16* __restrict__ Blo,
                     const float* __restrict__ bias, float* __restrict__ C,
                     int M, int N, int K) {
    extern __shared__ char smraw[];
    const uint32_t sbase = smem_u32(smraw);
    const int tid = threadIdx.x;
    const int lane = tid & 31;
    const int warp = tid >> 5;
    const int wm = warp & 1;
    const int wn = warp >> 1;

    const int row0 = blockIdx.y * 128;
    const int col0 = blockIdx.x * 128;
    const __nv_bfloat16* srcs[4] = {Ahi + (size_t)row0 * K, Alo + (size_t)row0 * K,
                                    Bhi + (size_t)col0 * K, Blo + (size_t)col0 * K};
    const int nk = K / 32;

    auto load_stage = [&](int kc, int st) {
        const int kbase = kc * 32;
        const uint32_t stg = sbase + st * GEMM_STAGE_BYTES;
#pragma unroll
        for (int t = 0; t < 4; t++) {
            const __nv_bfloat16* s = srcs[t];
#pragma unroll
            for (int it = 0; it < 2; it++) {
                int idx = tid + it * 256;
                int r = idx >> 2, c = idx & 3;
                uint32_t dst = stg + t * 8192 + sw_off(r, c);
                CP_ASYNC16(dst, s + (size_t)r * K + kbase + c * 8);
            }
        }
    };

    float acc[4][4][4];
#pragma unroll
    for (int i = 0; i < 4; i++)
#pragma unroll
        for (int j = 0; j < 4; j++)
#pragma unroll
            for (int k = 0; k < 4; k++) acc[i][j][k] = 0.f;

    load_stage(0, 0); CP_COMMIT();
    load_stage(1, 1); CP_COMMIT();

    for (int kc = 0; kc < nk; kc++) {
        const int ps = kc + 2;
        if (ps < nk) load_stage(ps, ps % 3);
        CP_COMMIT();
        CP_WAIT2();
        __syncthreads();

        const uint32_t stg = sbase + (kc % 3) * GEMM_STAGE_BYTES;
        const uint32_t sAhi = stg, sAlo = stg + 8192, sBhi = stg + 16384, sBlo = stg + 24576;

#pragma unroll
        for (int ks = 0; ks < 2; ks++) {
            uint32_t ah[4][4], al[4][4], bf[4][2];
            const int arow = lane & 15;
            const int ac = ks * 2 + (lane >> 4);
            const int brow = lane & 7;
            const int bc = ks * 2 + ((lane >> 3) & 1);
#pragma unroll
            for (int mt = 0; mt < 4; mt++) {
                int r = wm * 64 + mt * 16 + arow;
                LDSM4(ah[mt][0], ah[mt][1], ah[mt][2], ah[mt][3], sAhi + sw_off(r, ac));
            }
#pragma unroll
            for (int mt = 0; mt < 4; mt++) {
                int r = wm * 64 + mt * 16 + arow;
                LDSM4(al[mt][0], al[mt][1], al[mt][2], al[mt][3], sAlo + sw_off(r, ac));
            }
#pragma unroll
            for (int nt = 0; nt < 4; nt++) {
                int r = wn * 32 + nt * 8 + brow;
                LDSM2(bf[nt][0], bf[nt][1], sBhi + sw_off(r, bc));
            }
#pragma unroll
            for (int mt = 0; mt < 4; mt++)
#pragma unroll
                for (int nt = 0; nt < 4; nt++) {
                    mma16816(acc[mt][nt], ah[mt], bf[nt]);
                    mma16816(acc[mt][nt], al[mt], bf[nt]);
                }
#pragma unroll
            for (int nt = 0; nt < 4; nt++) {
                int r = wn * 32 + nt * 8 + brow;
                LDSM2(bf[nt][0], bf[nt][1], sBlo + sw_off(r, bc));
            }
#pragma unroll
            for (int mt = 0; mt < 4; mt++)
#pragma unroll
                for (int nt = 0; nt < 4; nt++)
                    mma16816(acc[mt][nt], ah[mt], bf[nt]);
        }
        __syncthreads();
    }

#pragma unroll
    for (int mt = 0; mt < 4; mt++) {
        int r = row0 + wm * 64 + mt * 16 + (lane >> 2);
#pragma unroll
        for (int nt = 0; nt < 4; nt++) {
            int c = col0 + wn * 32 + nt * 8 + (lane & 3) * 2;
            float b0 = __ldg(bias + c), b1 = __ldg(bias + c + 1);
            float2 v0 = make_float2(acc[mt][nt][0] + b0, acc[mt][nt][1] + b1);
            float2 v1 = make_float2(acc[mt][nt][2] + b0, acc[mt][nt][3] + b1);
            *(float2*)(C + (size_t)r * N + c) = v0;
            *(float2*)(C + (size_t)(r + 8) * N + c) = v1;
        }
    }
}

// ---------------------------------------------------------------------------
// fp32 -> bf16 hi/lo split
// ---------------------------------------------------------------------------
__global__ __launch_bounds__(256)
void split_kernel(const float4* __restrict__ x, __nv_bfloat162* __restrict__ hi,
                  __nv_bfloat162* __restrict__ lo, int n4) {
    int i = blockIdx.x * 256 + threadIdx.x;
    if (i >= n4) return;
    float4 v = x[i];
    __nv_bfloat16 h0 = __float2bfloat16(v.x), h1 = __float2bfloat16(v.y);
    __nv_bfloat16 h2 = __float2bfloat16(v.z), h3 = __float2bfloat16(v.w);
    __nv_bfloat16 l0 = __float2bfloat16(v.x - __bfloat162float(h0));
    __nv_bfloat16 l1 = __float2bfloat16(v.y - __bfloat162float(h1));
    __nv_bfloat16 l2 = __float2bfloat16(v.z - __bfloat162float(h2));
    __nv_bfloat16 l3 = __float2bfloat16(v.w - __bfloat162float(h3));
    hi[2 * i] = __halves2bfloat162(h0, h1);
    hi[2 * i + 1] = __halves2bfloat162(h2, h3);
    lo[2 * i] = __halves2bfloat162(l0, l1);
    lo[2 * i + 1] = __halves2bfloat162(l2, l3);
}

// ---------------------------------------------------------------------------
// Q prep: g_q fp32 (B,S,HID) -> qhi/qlo [bh][sdup][vec]  (one block per b,s,d)
// ---------------------------------------------------------------------------
__global__ __launch_bounds__(256)
void qprep_kernel(const float* __restrict__ q, __nv_bfloat16* __restrict__ qhi,
                  __nv_bfloat16* __restrict__ qlo) {
    __shared__ float sm[1024];
    int bid = blockIdx.x;              // (b*512+s)*4 + d
    int d = bid & 3;
    int bs = bid >> 2;                 // b*512+s
    int b = bs >> 9, s = bs & 511;
    const float* src = q + (size_t)bs * HID + d * 1024;
    int tid = threadIdx.x;
    *(float4*)&sm[tid * 4] = *(const float4*)(src + tid * 4);
    __syncthreads();
    // idx = h*64 + v
    int h = tid >> 4;                  // tid*4 -> idx = tid*4 : h = (tid*4)>>6 = tid>>4
    int v = (tid * 4) & 63;
    size_t dst = ((size_t)(b * 16 + h) * SDUP + (s * 4 + d)) * VECD + v;
    float x0 = sm[(v + 0) * 16 + h], x1 = sm[(v + 1) * 16 + h];
    float x2 = sm[(v + 2) * 16 + h], x3 = sm[(v + 3) * 16 + h];
    __nv_bfloat16 h0 = __float2bfloat16(x0), h1 = __float2bfloat16(x1);
    __nv_bfloat16 h2 = __float2bfloat16(x2), h3 = __float2bfloat16(x3);
    *(__nv_bfloat162*)(qhi + dst) = __halves2bfloat162(h0, h1);
    *(__nv_bfloat162*)(qhi + dst + 2) = __halves2bfloat162(h2, h3);
    __nv_bfloat16 l0 = __float2bfloat16(x0 - __bfloat162float(h0));
    __nv_bfloat16 l1 = __float2bfloat16(x1 - __bfloat162float(h1));
    __nv_bfloat16 l2 = __float2bfloat16(x2 - __bfloat162float(h2));
    __nv_bfloat16 l3 = __float2bfloat16(x3 - __bfloat162float(h3));
    *(__nv_bfloat162*)(qlo + dst) = __halves2bfloat162(l0, l1);
    *(__nv_bfloat162*)(qlo + dst + 2) = __halves2bfloat162(l2, l3);
}

// ---------------------------------------------------------------------------
// KV prep: keys/vals [b,n, v*16+h] -> khi/klo [bh][n][v], vhi/vlo [bh][v][n]
// one block per (b,n)
// ---------------------------------------------------------------------------
__global__ __launch_bounds__(256)
void kvprep_kernel(const float* __restrict__ keys, const float* __restrict__ vals,
                   __nv_bfloat16* __restrict__ khi, __nv_bfloat16* __restrict__ klo,
                   __nv_bfloat16* __restrict__ vhi, __nv_bfloat16* __restrict__ vlo) {
    __shared__ float sk[1024], sv[1024];
    int bid = blockIdx.x;              // b*512+n
    int b = bid >> 9, n = bid & 511;
    int tid = threadIdx.x;
    *(float4*)&sk[tid * 4] = *(const float4*)(keys + (size_t)bid * 1024 + tid * 4);
    *(float4*)&sv[tid * 4] = *(const float4*)(vals + (size_t)bid * 1024 + tid * 4);
    __syncthreads();
    int h = tid >> 4;
    int v = (tid * 4) & 63;
    // K: [bh][n][v]
    {
        size_t dst = ((size_t)(b * 16 + h) * NKV + n) * VECD + v;
        float x0 = sk[(v + 0) * 16 + h], x1 = sk[(v + 1) * 16 + h];
        float x2 = sk[(v + 2) * 16 + h], x3 = sk[(v + 3) * 16 + h];
        __nv_bfloat16 h0 = __float2bfloat16(x0), h1 = __float2bfloat16(x1);
        __nv_bfloat16 h2 = __float2bfloat16(x2), h3 = __float2bfloat16(x3);
        *(__nv_bfloat162*)(khi + dst) = __halves2bfloat162(h0, h1);
        *(__nv_bfloat162*)(khi + dst + 2) = __halves2bfloat162(h2, h3);
        __nv_bfloat16 l0 = __float2bfloat16(x0 - __bfloat162float(h0));
        __nv_bfloat16 l1 = __float2bfloat16(x1 - __bfloat162float(h1));
        __nv_bfloat16 l2 = __float2bfloat16(x2 - __bfloat162float(h2));
        __nv_bfloat16 l3 = __float2bfloat16(x3 - __bfloat162float(h3));
        *(__nv_bfloat162*)(klo + dst) = __halves2bfloat162(l0, l1);
        *(__nv_bfloat162*)(klo + dst + 2) = __halves2bfloat162(l2, l3);
    }
    // V: [bh][v][n] (scalar scattered stores)
#pragma unroll
    for (int j = 0; j < 4; j++) {
        float x = sv[(v + j) * 16 + h];
        __nv_bfloat16 hh = __float2bfloat16(x);
        __nv_bfloat16 ll = __float2bfloat16(x - __bfloat162float(hh));
        size_t dst = ((size_t)(b * 16 + h) * VECD + (v + j)) * NKV + n;
        vhi[dst] = hh;
        vlo[dst] = ll;
    }
}

// ---------------------------------------------------------------------------
// Tensor-core flash attention with bf16 hi/lo split.
// CTA: 256 thr (8 warps), 128 q-rows per CTA, online softmax over 4 chunks of 128.
// grid = (16 tiles, 64 bh)
// ---------------------------------------------------------------------------
#define ATT_SMEM (6 * 16384)
__global__ __launch_bounds__(256)
void attn_mma_kernel(const __nv_bfloat16* __restrict__ qhi, const __nv_bfloat16* __restrict__ qlo,
                     const __nv_bfloat16* __restrict__ khi, const __nv_bfloat16* __restrict__ klo,
                     const __nv_bfloat16* __restrict__ vhi, const __nv_bfloat16* __restrict__ vlo,
                     float* __restrict__ outT) {
    extern __shared__ char smraw[];
    const uint32_t sQhi = smem_u32(smraw);
    const uint32_t sQlo = sQhi + 16384;
    const uint32_t sKhi = sQhi + 32768;
    const uint32_t sKlo = sQhi + 49152;
    const uint32_t sVhi = sQhi + 65536;
    const uint32_t sVlo = sQhi + 81920;

    const int tid = threadIdx.x;
    const int lane = tid & 31;
    const int warp = tid >> 5;
    const int g = lane >> 2;        // row-in-8
    const int tq = lane & 3;        // col pair select
    const int bh = blockIdx.y;
    const int tile = blockIdx.x;
    const int wrow0 = warp * 16;

    // ---- load Q tile (async) ----
    const __nv_bfloat16* qh = qhi + ((size_t)bh * SDUP + tile * 128) * VECD;
    const __nv_bfloat16* ql = qlo + ((size_t)bh * SDUP + tile * 128) * VECD;
#pragma unroll
    for (int it = 0; it < 4; it++) {
        int idx = tid + it * 256;   // 0..1023
        int r = idx >> 3, c = idx & 7;
        CP_ASYNC16(sQhi + sw128(r, c), qh + (size_t)r * VECD + c * 8);
        CP_ASYNC16(sQlo + sw128(r, c), ql + (size_t)r * VECD + c * 8);
    }
    CP_COMMIT();

    const __nv_bfloat16* kh = khi + (size_t)bh * NKV * VECD;
    const __nv_bfloat16* kl = klo + (size_t)bh * NKV * VECD;
    const __nv_bfloat16* vh = vhi + (size_t)bh * VECD * NKV;
    const __nv_bfloat16* vl = vlo + (size_t)bh * VECD * NKV;

    float oa[8][4];
#pragma unroll
    for (int i = 0; i < 8; i++)
#pragma unroll
        for (int j = 0; j < 4; j++) oa[i][j] = 0.f;
    float m0 = -1e30f, m1 = -1e30f, l0 = 0.f, l1 = 0.f;

    for (int ck = 0; ck < 4; ck++) {
        const int n0 = ck * 128;
        __syncthreads();    // previous chunk compute done before overwrite
        // load K chunk [128][64] and V chunk [64][128]
#pragma unroll
        for (int it = 0; it < 4; it++) {
            int idx = tid + it * 256;
            int r = idx >> 3, c = idx & 7;
            CP_ASYNC16(sKhi + sw128(r, c), kh + (size_t)(n0 + r) * VECD + c * 8);
            CP_ASYNC16(sKlo + sw128(r, c), kl + (size_t)(n0 + r) * VECD + c * 8);
            int v = idx >> 4, cc = idx & 15;
            CP_ASYNC16(sVhi + sw256(v, cc), vh + (size_t)v * NKV + n0 + cc * 8);
            CP_ASYNC16(sVlo + sw256(v, cc), vl + (size_t)v * NKV + n0 + cc * 8);
        }
        CP_COMMIT();
        CP_WAIT0();
        __syncthreads();

        // ---- S = q k^T (3-product split) ----
        float S[16][4];
#pragma unroll
        for (int jt = 0; jt < 16; jt++)
#pragma unroll
            for (int j = 0; j < 4; j++) S[jt][j] = 0.f;

#pragma unroll
        for (int ks = 0; ks < 4; ks++) {
            uint32_t ah[4], al[4];
            int arow = wrow0 + (lane & 15);
            int ac = ks * 2 + (lane >> 4);
            uint32_t qoff = sw128(arow, ac);
            LDSM4(ah[0], ah[1], ah[2], ah[3], sQhi + qoff);
            LDSM4(al[0], al[1], al[2], al[3], sQlo + qoff);
#pragma unroll
            for (int jt = 0; jt < 16; jt++) {
                int brow = jt * 8 + (lane & 7);
                int bc = ks * 2 + ((lane >> 3) & 1);
                uint32_t koff = sw128(brow, bc);
                uint32_t b2h[2], b2l[2];
                LDSM2(b2h[0], b2h[1], sKhi + koff);
                LDSM2(b2l[0], b2l[1], sKlo + koff);
                mma16816(S[jt], ah, b2h);
                mma16816(S[jt], al, b2h);
                mma16816(S[jt], ah, b2l);
            }
        }

        // ---- online softmax ----
        float cm0 = -1e30f, cm1 = -1e30f;
#pragma unroll
        for (int jt = 0; jt < 16; jt++) {
            S[jt][0] *= 0.125f; S[jt][1] *= 0.125f;
            S[jt][2] *= 0.125f; S[jt][3] *= 0.125f;
            cm0 = fmaxf(cm0, fmaxf(S[jt][0], S[jt][1]));
            cm1 = fmaxf(cm1, fmaxf(S[jt][2], S[jt][3]));
        }
        cm0 = fmaxf(cm0, __shfl_xor_sync(0xffffffffu, cm0, 1));
        cm0 = fmaxf(cm0, __shfl_xor_sync(0xffffffffu, cm0, 2));
        cm1 = fmaxf(cm1, __shfl_xor_sync(0xffffffffu, cm1, 1));
        cm1 = fmaxf(cm1, __shfl_xor_sync(0xffffffffu, cm1, 2));
        float mn0 = fmaxf(m0, cm0), mn1 = fmaxf(m1, cm1);
        float sc0 = __expf(m0 - mn0), sc1 = __expf(m1 - mn1);
        m0 = mn0; m1 = mn1;
        l0 *= sc0; l1 *= sc1;
#pragma unroll
        for (int vt = 0; vt < 8; vt++) {
            oa[vt][0] *= sc0; oa[vt][1] *= sc0;
            oa[vt][2] *= sc1; oa[vt][3] *= sc1;
        }

        // ---- P = exp(S - m), split to bf16 hi/lo, P@V fused ----
        float cs0 = 0.f, cs1 = 0.f;
#pragma unroll
        for (int ks = 0; ks < 8; ks++) {
            uint32_t pah[4], pal[4];
#pragma unroll
            for (int half = 0; half < 2; half++) {
                int jt = ks * 2 + half;
                float p0 = __expf(S[jt][0] - m0);
                float p1 = __expf(S[jt][1] - m0);
                float p2 = __expf(S[jt][2] - m1);
                float p3 = __expf(S[jt][3] - m1);
                cs0 += p0 + p1;
                cs1 += p2 + p3;
                float h0 = __bfloat162float(__float2bfloat16(p0));
                float h1 = __bfloat162float(__float2bfloat16(p1));
                float h2 = __bfloat162float(__float2bfloat16(p2));
                float h3 = __bfloat162float(__float2bfloat16(p3));
                pah[half * 2 + 0] = pack_bf16(h0, h1);
                pah[half * 2 + 1] = pack_bf16(h2, h3);
                pal[half * 2 + 0] = pack_bf16(p0 - h0, p1 - h1);
                pal[half * 2 + 1] = pack_bf16(p2 - h2, p3 - h3);
            }
            // wait: frag order must be a0=rowg k0-7 half... reorder:
            // pah currently {h0h1(half0), h2h3(half0), h0h1(half1), h2h3(half1)} == {a0,a1,a2,a3} ✓
#pragma unroll
            for (int vt = 0; vt < 8; vt++) {
                int brow = vt * 8 + (lane & 7);
                int bc = ks * 2 + ((lane >> 3) & 1);
                uint32_t voff = sw256(brow, bc);
                uint32_t b2h[2], b2l[2];
                LDSM2(b2h[0], b2h[1], sVhi + voff);
                LDSM2(b2l[0], b2l[1], sVlo + voff);
                mma16816(oa[vt], pah, b2h);
                mma16816(oa[vt], pal, b2h);
                mma16816(oa[vt], pah, b2l);
            }
        }
        cs0 += __shfl_xor_sync(0xffffffffu, cs0, 1);
        cs0 += __shfl_xor_sync(0xffffffffu, cs0, 2);
        cs1 += __shfl_xor_sync(0xffffffffu, cs1, 1);
        cs1 += __shfl_xor_sync(0xffffffffu, cs1, 2);
        l0 += cs0; l1 += cs1;
    }

    // ---- epilogue ----
    float inv0 = 1.f / l0, inv1 = 1.f / l1;
    float* orow0 = outT + ((size_t)bh * SDUP + tile * 128 + wrow0 + g) * VECD;
    float* orow1 = orow0 + 8 * VECD;
#pragma unroll
    for (int vt = 0; vt < 8; vt++) {
        int v = vt * 8 + tq * 2;
        *(float2*)(orow0 + v) = make_float2(oa[vt][0] * inv0, oa[vt][1] * inv0);
        *(float2*)(orow1 + v) = make_float2(oa[vt][2] * inv1, oa[vt][3] * inv1);
    }
}

// ---------------------------------------------------------------------------
// LayerNorm: gathers from attnT [bh][sdup][vec], outputs bf16 hi/lo [row][HID]
// ---------------------------------------------------------------------------
__global__ __launch_bounds__(256)
void ln_gather_split_kernel(const float* __restrict__ attnT, const float* __restrict__ gam,
                            const float* __restrict__ bet, __nv_bfloat16* __restrict__ hi,
                            __nv_bfloat16* __restrict__ lo) {
    __shared__ float xs[HID];
    __shared__ float red[8];
    __shared__ float red2[8];
    const int row = blockIdx.x;        // b*512+s
    const int b = row >> 9, s = row & 511;
    const int tid = threadIdx.x;
    const int lane = tid & 31, w = tid >> 5;

    float lsum = 0.f;
#pragma unroll
    for (int it = 0; it < 4; it++) {
        int i = it * 1024 + tid * 4;
        int h = i >> 8, d = (i >> 6) & 3, v = i & 63;
        const float* src = attnT + ((size_t)(b * 16 + h) * SDUP + (s * 4 + d)) * VECD + v;
        float4 x = *(const float4*)src;
        *(float4*)&xs[i] = x;
        lsum += x.x + x.y + x.z + x.w;
    }
#pragma unroll
    for (int o = 16; o > 0; o >>= 1) lsum += __shfl_xor_sync(0xffffffffu, lsum, o);
    if (lane == 0) red[w] = lsum;
    __syncthreads();
    float tot = 0.f;
#pragma unroll
    for (int j = 0; j < 8; j++) tot += red[j];
    float mu = tot * (1.f / HID);

    float lv = 0.f;
    for (int i = tid; i < HID; i += 256) {
        float d = xs[i] - mu;
        lv += d * d;
    }
#pragma unroll
    for (int o = 16; o > 0; o >>= 1) lv += __shfl_xor_sync(0xffffffffu, lv, o);
    if (lane == 0) red2[w] = lv;
    __syncthreads();
    float tv = 0.f;
#pragma unroll
    for (int j = 0; j < 8; j++) tv += red2[j];
    float inv = rsqrtf(tv * (1.f / HID) + 1e-12f);

#pragma unroll
    for (int it = 0; it < 4; it++) {
        int i = it * 1024 + tid * 4;
        float4 xv = *(const float4*)&xs[i];
        float4 gv = *(const float4*)&gam[i];
        float4 bv = *(const float4*)&bet[i];
        float y0 = (xv.x - mu) * inv * gv.x + bv.x;
        float y1 = (xv.y - mu) * inv * gv.y + bv.y;
        float y2 = (xv.z - mu) * inv * gv.z + bv.z;
        float y3 = (xv.w - mu) * inv * gv.w + bv.w;
        __nv_bfloat16 h0 = __float2bfloat16(y0), h1 = __float2bfloat16(y1);
        __nv_bfloat16 h2 = __float2bfloat16(y2), h3 = __float2bfloat16(y3);
        __nv_bfloat16 l0 = __float2bfloat16(y0 - __bfloat162float(h0));
        __nv_bfloat16 l1 = __float2bfloat16(y1 - __bfloat162float(h1));
        __nv_bfloat16 l2 = __float2bfloat16(y2 - __bfloat162float(h2));
        __nv_bfloat16 l3 = __float2bfloat16(y3 - __bfloat162float(h3));
        size_t o = (size_t)row * HID + i;
        *(__nv_bfloat162*)(hi + o) = __halves2bfloat162(h0, h1);
        *(__nv_bfloat162*)(hi + o + 2) = __halves2bfloat162(h2, h3);
        *(__nv_bfloat162*)(lo + o) = __halves2bfloat162(l0, l1);
        *(__nv_bfloat162*)(lo + o + 2) = __halves2bfloat162(l2, l3);
    }
}

// ---------------------------------------------------------------------------
extern "C" void kernel_launch(void* const* d_in, const int* in_sizes, int n_in,
                              void* d_out, int out_size) {
    const float* emb  = (const float*)d_in[0];
    const float* keys = (const float*)d_in[1];
    const float* vals = (const float*)d_in[2];
    const float* Wq   = (const float*)d_in[3];
    const float* bq   = (const float*)d_in[4];
    const float* Wre  = (const float*)d_in[5];
    const float* bre  = (const float*)d_in[6];
    const float* ln_g = (const float*)d_in[7];
    const float* ln_b = (const float*)d_in[8];
    float* out = (float*)d_out;

    float *qbuf, *aT;
    __nv_bfloat16 *ehi, *elo, *lnhi, *lnlo, *wqhi, *wqlo, *wrehi, *wrelo;
    __nv_bfloat16 *qhi, *qlo, *khi, *klo, *vhi, *vlo;
    cudaGetSymbolAddress((void**)&qbuf, g_q);
    cudaGetSymbolAddress((void**)&aT, g_attnT);
    cudaGetSymbolAddress((void**)&ehi, g_ehi);
    cudaGetSymbolAddress((void**)&elo, g_elo);
    cudaGetSymbolAddress((void**)&lnhi, g_lnhi);
    cudaGetSymbolAddress((void**)&lnlo, g_lnlo);
    cudaGetSymbolAddress((void**)&wqhi, g_wqhi);
    cudaGetSymbolAddress((void**)&wqlo, g_wqlo);
    cudaGetSymbolAddress((void**)&wrehi, g_wrehi);
    cudaGetSymbolAddress((void**)&wrelo, g_wrelo);
    cudaGetSymbolAddress((void**)&qhi, g_qhi);
    cudaGetSymbolAddress((void**)&qlo, g_qlo);
    cudaGetSymbolAddress((void**)&khi, g_khi);
    cudaGetSymbolAddress((void**)&klo, g_klo);
    cudaGetSymbolAddress((void**)&vhi, g_vhi);
    cudaGetSymbolAddress((void**)&vlo, g_vlo);

    cudaFuncSetAttribute(gemm_mma_kernel, cudaFuncAttributeMaxDynamicSharedMemorySize, GEMM_SMEM);
    cudaFuncSetAttribute(attn_mma_kernel, cudaFuncAttributeMaxDynamicSharedMemorySize, ATT_SMEM);

    // input splits
    split_kernel<<<(MROWS * HID / 4 + 255) / 256, 256>>>((const float4*)emb,
        (__nv_bfloat162*)ehi, (__nv_bfloat162*)elo, MROWS * HID / 4);
    split_kernel<<<(HID * HID / 4 + 255) / 256, 256>>>((const float4*)Wq,
        (__nv_bfloat162*)wqhi, (__nv_bfloat162*)wqlo, HID * HID / 4);
    split_kernel<<<(HID * HID / 4 + 255) / 256, 256>>>((const float4*)Wre,
        (__nv_bfloat162*)wrehi, (__nv_bfloat162*)wrelo, HID * HID / 4);
    // K/V relayout + split
    kvprep_kernel<<<4 * NKV, 256>>>(keys, vals, khi, klo, vhi, vlo);
    // q projection
    gemm_mma_kernel<<<dim3(HID / 128, MROWS / 128), 256, GEMM_SMEM>>>(
        ehi, elo, wqhi, wqlo, bq, qbuf, MROWS, HID, HID);
    // q relayout + split
    qprep_kernel<<<MROWS * 4, 256>>>(qbuf, qhi, qlo);
    // attention (tensor cores)
    attn_mma_kernel<<<dim3(16, 64), 256, ATT_SMEM>>>(qhi, qlo, khi, klo, vhi, vlo, aT);
    // layernorm gather + split
    ln_gather_split_kernel<<<MROWS, 256>>>(aT, ln_g, ln_b, lnhi, lnlo);
    // output projection
    gemm_mma_kernel<<<dim3(HID / 128, MROWS / 128), 256, GEMM_SMEM>>>(
        lnhi, lnlo, wrehi, wrelo, bre, out, MROWS, HID, HID);
}

// round 6
// speedup vs baseline: 1.0151x; 1.0151x over previous
#include <cuda_runtime.h>
#include <cuda_bf16.h>
#include <cstdint>

#define HID 4096
#define MROWS 2048
#define NKV 512
#define VECD 64
#define NHEAD 16
#define NBH 64
#define SDUP 2048

// ---------------- scratch ----------------
__device__ float g_q[MROWS * HID];
__device__ float g_attnT[NBH * SDUP * VECD];
__device__ __nv_bfloat16 g_qhi[NBH * SDUP * VECD], g_qlo[NBH * SDUP * VECD];
__device__ __nv_bfloat16 g_khi[NBH * NKV * VECD], g_klo[NBH * NKV * VECD];
__device__ __nv_bfloat16 g_vhi[NBH * VECD * NKV], g_vlo[NBH * VECD * NKV];
__device__ __nv_bfloat16 g_ehi[MROWS * HID], g_elo[MROWS * HID];
__device__ __nv_bfloat16 g_lnhi[MROWS * HID], g_lnlo[MROWS * HID];
__device__ __nv_bfloat16 g_wqhi[HID * HID], g_wqlo[HID * HID];
__device__ __nv_bfloat16 g_wrehi[HID * HID], g_wrelo[HID * HID];

// ---------------- PTX helpers ----------------
__device__ __forceinline__ uint32_t smem_u32(const void* p) {
    uint32_t a;
    asm("{ .reg .u64 t; cvta.to.shared.u64 t, %1; cvt.u32.u64 %0, t; }" : "=r"(a) : "l"(p));
    return a;
}
#define CP_ASYNC16(dst, src) \
    asm volatile("cp.async.cg.shared.global [%0], [%1], 16;" :: "r"(dst), "l"(src))
#define CP_COMMIT() asm volatile("cp.async.commit_group;" ::: "memory")
#define CP_WAIT2()  asm volatile("cp.async.wait_group 2;" ::: "memory")
#define CP_WAIT0()  asm volatile("cp.async.wait_group 0;" ::: "memory")

#define LDSM4(r0, r1, r2, r3, addr)                                          \
    asm volatile("ldmatrix.sync.aligned.m8n8.x4.shared.b16 {%0,%1,%2,%3}, [%4];" \
                 : "=r"(r0), "=r"(r1), "=r"(r2), "=r"(r3) : "r"(addr))
#define LDSM2(r0, r1, addr)                                                  \
    asm volatile("ldmatrix.sync.aligned.m8n8.x2.shared.b16 {%0,%1}, [%2];"   \
                 : "=r"(r0), "=r"(r1) : "r"(addr))

__device__ __forceinline__ void mma16816(float* c, const uint32_t* a, const uint32_t* b) {
    asm volatile(
        "mma.sync.aligned.m16n8k16.row.col.f32.bf16.bf16.f32 "
        "{%0,%1,%2,%3}, {%4,%5,%6,%7}, {%8,%9}, {%0,%1,%2,%3};"
        : "+f"(c[0]), "+f"(c[1]), "+f"(c[2]), "+f"(c[3])
        : "r"(a[0]), "r"(a[1]), "r"(a[2]), "r"(a[3]), "r"(b[0]), "r"(b[1]));
}

__device__ __forceinline__ uint32_t pack_bf16(float a, float b) {
    __nv_bfloat162 t = __floats2bfloat162_rn(a, b);
    return *(uint32_t*)&t;
}

__device__ __forceinline__ uint32_t sw_off(int r, int c16) {
    return (uint32_t)(r * 64 + ((c16 ^ ((r >> 1) & 3)) << 4));
}
__device__ __forceinline__ uint32_t sw128(int r, int c16) {
    return (uint32_t)(r * 128 + ((c16 ^ (r & 7)) << 4));
}
__device__ __forceinline__ uint32_t sw256(int r, int c16) {
    return (uint32_t)(r * 256 + ((c16 ^ (r & 7)) << 4));
}

// ---------------------------------------------------------------------------
// GEMM v2: CTA 256x128, 8 warps (4m x 2n), warp tile 64x64, BK=32, 3 stages.
// C[M,N] = (Ahi+Alo)[M,K] @ (Bhi+Blo)[N,K]^T + bias
// stage layout: Ahi 16K | Alo 16K | Bhi 8K | Blo 8K  = 48K
// ---------------------------------------------------------------------------
#define G2_STAGE 49152
#define G2_SMEM (3 * G2_STAGE)
__global__ __launch_bounds__(256, 1)
void gemm_mma_kernel(const __nv_bfloat16* __restrict__ Ahi, const __nv_bfloat16* __restrict__ Alo,
                     const __nv_bfloat16* __restrict__ Bhi, const __nv_bfloat16* __restrict__ Blo,
                     const float* __restrict__ bias, float* __restrict__ C,
                     int M, int N, int K) {
    extern __shared__ char smraw[];
    const uint32_t sbase = smem_u32(smraw);
    const int tid = threadIdx.x;
    const int lane = tid & 31;
    const int warp = tid >> 5;
    const int wm = warp >> 1;         // 0..3 -> 64-row slab
    const int wn = warp & 1;          // 0..1 -> 64-col slab

    const int row0 = blockIdx.y * 256;
    const int col0 = blockIdx.x * 128;
    const __nv_bfloat16* pAhi = Ahi + (size_t)row0 * K;
    const __nv_bfloat16* pAlo = Alo + (size_t)row0 * K;
    const __nv_bfloat16* pBhi = Bhi + (size_t)col0 * K;
    const __nv_bfloat16* pBlo = Blo + (size_t)col0 * K;
    const int nk = K / 32;

    auto load_stage = [&](int kc, int st) {
        const int kbase = kc * 32;
        const uint32_t stg = sbase + st * G2_STAGE;
        // A: 256 rows x 4 chunks per type -> 1024 chunks -> 4 iters
#pragma unroll
        for (int it = 0; it < 4; it++) {
            int idx = tid + it * 256;
            int r = idx >> 2, c = idx & 3;
            CP_ASYNC16(stg + sw_off(r, c), pAhi + (size_t)r * K + kbase + c * 8);
            CP_ASYNC16(stg + 16384 + sw_off(r, c), pAlo + (size_t)r * K + kbase + c * 8);
        }
        // B: 128 rows x 4 chunks per type -> 512 chunks -> 2 iters
#pragma unroll
        for (int it = 0; it < 2; it++) {
            int idx = tid + it * 256;
            int r = idx >> 2, c = idx & 3;
            CP_ASYNC16(stg + 32768 + sw_off(r, c), pBhi + (size_t)r * K + kbase + c * 8);
            CP_ASYNC16(stg + 40960 + sw_off(r, c), pBlo + (size_t)r * K + kbase + c * 8);
        }
    };

    float acc[4][8][4];
#pragma unroll
    for (int i = 0; i < 4; i++)
#pragma unroll
        for (int j = 0; j < 8; j++)
#pragma unroll
            for (int k = 0; k < 4; k++) acc[i][j][k] = 0.f;

    load_stage(0, 0); CP_COMMIT();
    load_stage(1, 1); CP_COMMIT();

    for (int kc = 0; kc < nk; kc++) {
        const int ps = kc + 2;
        if (ps < nk) load_stage(ps, ps % 3);
        CP_COMMIT();
        CP_WAIT2();
        __syncthreads();

        const uint32_t stg = sbase + (kc % 3) * G2_STAGE;
        const uint32_t sAhi = stg, sAlo = stg + 16384;
        const uint32_t sBhi = stg + 32768, sBlo = stg + 40960;

#pragma unroll
        for (int ks = 0; ks < 2; ks++) {
            const int arow = wm * 64 + (lane & 15);
            const int ac = ks * 2 + (lane >> 4);
            const int brow = wn * 64 + (lane & 7);
            const int bc = ks * 2 + ((lane >> 3) & 1);

            uint32_t ah[4][4];
#pragma unroll
            for (int mt = 0; mt < 4; mt++)
                LDSM4(ah[mt][0], ah[mt][1], ah[mt][2], ah[mt][3],
                      sAhi + sw_off(arow + mt * 16, ac));

            {
                uint32_t bf[8][2];
#pragma unroll
                for (int nt = 0; nt < 8; nt++)
                    LDSM2(bf[nt][0], bf[nt][1], sBhi + sw_off(brow + nt * 8, bc));
                // hi*hi
#pragma unroll
                for (int mt = 0; mt < 4; mt++)
#pragma unroll
                    for (int nt = 0; nt < 8; nt++)
                        mma16816(acc[mt][nt], ah[mt], bf[nt]);
                // lo*hi
                uint32_t al[4][4];
#pragma unroll
                for (int mt = 0; mt < 4; mt++)
                    LDSM4(al[mt][0], al[mt][1], al[mt][2], al[mt][3],
                          sAlo + sw_off(arow + mt * 16, ac));
#pragma unroll
                for (int mt = 0; mt < 4; mt++)
#pragma unroll
                    for (int nt = 0; nt < 8; nt++)
                        mma16816(acc[mt][nt], al[mt], bf[nt]);
            }
            {
                // hi*lo
                uint32_t bf[8][2];
#pragma unroll
                for (int nt = 0; nt < 8; nt++)
                    LDSM2(bf[nt][0], bf[nt][1], sBlo + sw_off(brow + nt * 8, bc));
#pragma unroll
                for (int mt = 0; mt < 4; mt++)
#pragma unroll
                    for (int nt = 0; nt < 8; nt++)
                        mma16816(acc[mt][nt], ah[mt], bf[nt]);
            }
        }
        __syncthreads();
    }

#pragma unroll
    for (int mt = 0; mt < 4; mt++) {
        int r = row0 + wm * 64 + mt * 16 + (lane >> 2);
#pragma unroll
        for (int nt = 0; nt < 8; nt++) {
            int c = col0 + wn * 64 + nt * 8 + (lane & 3) * 2;
            float b0 = __ldg(bias + c), b1 = __ldg(bias + c + 1);
            *(float2*)(C + (size_t)r * N + c) =
                make_float2(acc[mt][nt][0] + b0, acc[mt][nt][1] + b1);
            *(float2*)(C + (size_t)(r + 8) * N + c) =
                make_float2(acc[mt][nt][2] + b0, acc[mt][nt][3] + b1);
        }
    }
}

// ---------------------------------------------------------------------------
// fp32 -> bf16 hi/lo split
// ---------------------------------------------------------------------------
__global__ __launch_bounds__(256)
void split_kernel(const float4* __restrict__ x, __nv_bfloat162* __restrict__ hi,
                  __nv_bfloat162* __restrict__ lo, int n4) {
    int i = blockIdx.x * 256 + threadIdx.x;
    if (i >= n4) return;
    float4 v = x[i];
    __nv_bfloat16 h0 = __float2bfloat16(v.x), h1 = __float2bfloat16(v.y);
    __nv_bfloat16 h2 = __float2bfloat16(v.z), h3 = __float2bfloat16(v.w);
    __nv_bfloat16 l0 = __float2bfloat16(v.x - __bfloat162float(h0));
    __nv_bfloat16 l1 = __float2bfloat16(v.y - __bfloat162float(h1));
    __nv_bfloat16 l2 = __float2bfloat16(v.z - __bfloat162float(h2));
    __nv_bfloat16 l3 = __float2bfloat16(v.w - __bfloat162float(h3));
    hi[2 * i] = __halves2bfloat162(h0, h1);
    hi[2 * i + 1] = __halves2bfloat162(h2, h3);
    lo[2 * i] = __halves2bfloat162(l0, l1);
    lo[2 * i + 1] = __halves2bfloat162(l2, l3);
}

// ---------------------------------------------------------------------------
// Q prep (unchanged)
// ---------------------------------------------------------------------------
__global__ __launch_bounds__(256)
void qprep_kernel(const float* __restrict__ q, __nv_bfloat16* __restrict__ qhi,
                  __nv_bfloat16* __restrict__ qlo) {
    __shared__ float sm[1024];
    int bid = blockIdx.x;
    int d = bid & 3;
    int bs = bid >> 2;
    int b = bs >> 9, s = bs & 511;
    const float* src = q + (size_t)bs * HID + d * 1024;
    int tid = threadIdx.x;
    *(float4*)&sm[tid * 4] = *(const float4*)(src + tid * 4);
    __syncthreads();
    int h = tid >> 4;
    int v = (tid * 4) & 63;
    size_t dst = ((size_t)(b * 16 + h) * SDUP + (s * 4 + d)) * VECD + v;
    float x0 = sm[(v + 0) * 16 + h], x1 = sm[(v + 1) * 16 + h];
    float x2 = sm[(v + 2) * 16 + h], x3 = sm[(v + 3) * 16 + h];
    __nv_bfloat16 h0 = __float2bfloat16(x0), h1 = __float2bfloat16(x1);
    __nv_bfloat16 h2 = __float2bfloat16(x2), h3 = __float2bfloat16(x3);
    *(__nv_bfloat162*)(qhi + dst) = __halves2bfloat162(h0, h1);
    *(__nv_bfloat162*)(qhi + dst + 2) = __halves2bfloat162(h2, h3);
    __nv_bfloat16 l0 = __float2bfloat16(x0 - __bfloat162float(h0));
    __nv_bfloat16 l1 = __float2bfloat16(x1 - __bfloat162float(h1));
    __nv_bfloat16 l2 = __float2bfloat16(x2 - __bfloat162float(h2));
    __nv_bfloat16 l3 = __float2bfloat16(x3 - __bfloat162float(h3));
    *(__nv_bfloat162*)(qlo + dst) = __halves2bfloat162(l0, l1);
    *(__nv_bfloat162*)(qlo + dst + 2) = __halves2bfloat162(l2, l3);
}

// ---------------------------------------------------------------------------
// KV prep v2: smem-staged, vectorized stores.
// grid (b*32 + nchunk), block 256. Each block: 16 n rows of one batch.
// smem: sk[16][1024], sv[16][1024]  (128 KB dynamic)
// ---------------------------------------------------------------------------
#define KVP_SMEM (2 * 16 * 1024 * 4)
__global__ __launch_bounds__(256)
void kvprep2_kernel(const float* __restrict__ keys, const float* __restrict__ vals,
                    __nv_bfloat16* __restrict__ khi, __nv_bfloat16* __restrict__ klo,
                    __nv_bfloat16* __restrict__ vhi, __nv_bfloat16* __restrict__ vlo) {
    extern __shared__ float smf[];
    float* sk = smf;               // [16][1024]
    float* sv = smf + 16 * 1024;
    const int bid = blockIdx.x;    // b*32 + nc
    const int b = bid >> 5, nc = bid & 31;
    const int n0 = nc * 16;
    const int tid = threadIdx.x;

    const float* ksrc = keys + ((size_t)b * NKV + n0) * 1024;
    const float* vsrc = vals + ((size_t)b * NKV + n0) * 1024;
#pragma unroll
    for (int it = 0; it < 16; it++) {
        int i = tid + it * 256;     // 0..4095 float4s
        *(float4*)&sk[i * 4] = *(const float4*)(ksrc + i * 4);
        *(float4*)&sv[i * 4] = *(const float4*)(vsrc + i * 4);
    }
    __syncthreads();

    // K writes: [bh][n][v], 16B per task. tasks: h(16) x n(16) x vg(8) = 2048 -> 8 iters
#pragma unroll
    for (int it = 0; it < 8; it++) {
        int task = tid + it * 256;
        int vg = task & 7, n = (task >> 3) & 15, h = task >> 7;
        uint32_t hhx[4], llx[4];
#pragma unroll
        for (int j = 0; j < 4; j++) {
            float x0 = sk[n * 1024 + (vg * 8 + j * 2 + 0) * 16 + h];
            float x1 = sk[n * 1024 + (vg * 8 + j * 2 + 1) * 16 + h];
            float h0 = __bfloat162float(__float2bfloat16(x0));
            float h1 = __bfloat162float(__float2bfloat16(x1));
            hhx[j] = pack_bf16(h0, h1);
            llx[j] = pack_bf16(x0 - h0, x1 - h1);
        }
        size_t dst = ((size_t)(b * 16 + h) * NKV + n0 + n) * VECD + vg * 8;
        *(uint4*)(khi + dst) = make_uint4(hhx[0], hhx[1], hhx[2], hhx[3]);
        *(uint4*)(klo + dst) = make_uint4(llx[0], llx[1], llx[2], llx[3]);
    }

    // V writes: [bh][v][n], 32B (16 n) per task. tasks: h(16) x v(64) = 1024 -> 4 iters
#pragma unroll
    for (int it = 0; it < 4; it++) {
        int task = tid + it * 256;
        int v = task & 63, h = task >> 6;
        uint32_t hhx[8], llx[8];
#pragma unroll
        for (int j = 0; j < 8; j++) {
            float x0 = sv[(j * 2 + 0) * 1024 + v * 16 + h];
            float x1 = sv[(j * 2 + 1) * 1024 + v * 16 + h];
            float h0 = __bfloat162float(__float2bfloat16(x0));
            float h1 = __bfloat162float(__float2bfloat16(x1));
            hhx[j] = pack_bf16(h0, h1);
            llx[j] = pack_bf16(x0 - h0, x1 - h1);
        }
        size_t dst = ((size_t)(b * 16 + h) * VECD + v) * NKV + n0;
        *(uint4*)(vhi + dst) = make_uint4(hhx[0], hhx[1], hhx[2], hhx[3]);
        *(uint4*)(vhi + dst + 8) = make_uint4(hhx[4], hhx[5], hhx[6], hhx[7]);
        *(uint4*)(vlo + dst) = make_uint4(llx[0], llx[1], llx[2], llx[3]);
        *(uint4*)(vlo + dst + 8) = make_uint4(llx[4], llx[5], llx[6], llx[7]);
    }
}

// ---------------------------------------------------------------------------
// Tensor-core flash attention (unchanged from R5, proven)
// ---------------------------------------------------------------------------
#define ATT_SMEM (6 * 16384)
__global__ __launch_bounds__(256)
void attn_mma_kernel(const __nv_bfloat16* __restrict__ qhi, const __nv_bfloat16* __restrict__ qlo,
                     const __nv_bfloat16* __restrict__ khi, const __nv_bfloat16* __restrict__ klo,
                     const __nv_bfloat16* __restrict__ vhi, const __nv_bfloat16* __restrict__ vlo,
                     float* __restrict__ outT) {
    extern __shared__ char smraw[];
    const uint32_t sQhi = smem_u32(smraw);
    const uint32_t sQlo = sQhi + 16384;
    const uint32_t sKhi = sQhi + 32768;
    const uint32_t sKlo = sQhi + 49152;
    const uint32_t sVhi = sQhi + 65536;
    const uint32_t sVlo = sQhi + 81920;

    const int tid = threadIdx.x;
    const int lane = tid & 31;
    const int warp = tid >> 5;
    const int g = lane >> 2;
    const int tq = lane & 3;
    const int bh = blockIdx.y;
    const int tile = blockIdx.x;
    const int wrow0 = warp * 16;

    const __nv_bfloat16* qh = qhi + ((size_t)bh * SDUP + tile * 128) * VECD;
    const __nv_bfloat16* ql = qlo + ((size_t)bh * SDUP + tile * 128) * VECD;
#pragma unroll
    for (int it = 0; it < 4; it++) {
        int idx = tid + it * 256;
        int r = idx >> 3, c = idx & 7;
        CP_ASYNC16(sQhi + sw128(r, c), qh + (size_t)r * VECD + c * 8);
        CP_ASYNC16(sQlo + sw128(r, c), ql + (size_t)r * VECD + c * 8);
    }
    CP_COMMIT();

    const __nv_bfloat16* kh = khi + (size_t)bh * NKV * VECD;
    const __nv_bfloat16* kl = klo + (size_t)bh * NKV * VECD;
    const __nv_bfloat16* vh = vhi + (size_t)bh * VECD * NKV;
    const __nv_bfloat16* vl = vlo + (size_t)bh * VECD * NKV;

    float oa[8][4];
#pragma unroll
    for (int i = 0; i < 8; i++)
#pragma unroll
        for (int j = 0; j < 4; j++) oa[i][j] = 0.f;
    float m0 = -1e30f, m1 = -1e30f, l0 = 0.f, l1 = 0.f;

    for (int ck = 0; ck < 4; ck++) {
        const int n0 = ck * 128;
        __syncthreads();
#pragma unroll
        for (int it = 0; it < 4; it++) {
            int idx = tid + it * 256;
            int r = idx >> 3, c = idx & 7;
            CP_ASYNC16(sKhi + sw128(r, c), kh + (size_t)(n0 + r) * VECD + c * 8);
            CP_ASYNC16(sKlo + sw128(r, c), kl + (size_t)(n0 + r) * VECD + c * 8);
            int v = idx >> 4, cc = idx & 15;
            CP_ASYNC16(sVhi + sw256(v, cc), vh + (size_t)v * NKV + n0 + cc * 8);
            CP_ASYNC16(sVlo + sw256(v, cc), vl + (size_t)v * NKV + n0 + cc * 8);
        }
        CP_COMMIT();
        CP_WAIT0();
        __syncthreads();

        float S[16][4];
#pragma unroll
        for (int jt = 0; jt < 16; jt++)
#pragma unroll
            for (int j = 0; j < 4; j++) S[jt][j] = 0.f;

#pragma unroll
        for (int ks = 0; ks < 4; ks++) {
            uint32_t ah[4], al[4];
            int arow = wrow0 + (lane & 15);
            int ac = ks * 2 + (lane >> 4);
            uint32_t qoff = sw128(arow, ac);
            LDSM4(ah[0], ah[1], ah[2], ah[3], sQhi + qoff);
            LDSM4(al[0], al[1], al[2], al[3], sQlo + qoff);
#pragma unroll
            for (int jt = 0; jt < 16; jt++) {
                int brow = jt * 8 + (lane & 7);
                int bc = ks * 2 + ((lane >> 3) & 1);
                uint32_t koff = sw128(brow, bc);
                uint32_t b2h[2], b2l[2];
                LDSM2(b2h[0], b2h[1], sKhi + koff);
                LDSM2(b2l[0], b2l[1], sKlo + koff);
                mma16816(S[jt], ah, b2h);
                mma16816(S[jt], al, b2h);
                mma16816(S[jt], ah, b2l);
            }
        }

        float cm0 = -1e30f, cm1 = -1e30f;
#pragma unroll
        for (int jt = 0; jt < 16; jt++) {
            S[jt][0] *= 0.125f; S[jt][1] *= 0.125f;
            S[jt][2] *= 0.125f; S[jt][3] *= 0.125f;
            cm0 = fmaxf(cm0, fmaxf(S[jt][0], S[jt][1]));
            cm1 = fmaxf(cm1, fmaxf(S[jt][2], S[jt][3]));
        }
        cm0 = fmaxf(cm0, __shfl_xor_sync(0xffffffffu, cm0, 1));
        cm0 = fmaxf(cm0, __shfl_xor_sync(0xffffffffu, cm0, 2));
        cm1 = fmaxf(cm1, __shfl_xor_sync(0xffffffffu, cm1, 1));
        cm1 = fmaxf(cm1, __shfl_xor_sync(0xffffffffu, cm1, 2));
        float mn0 = fmaxf(m0, cm0), mn1 = fmaxf(m1, cm1);
        float sc0 = __expf(m0 - mn0), sc1 = __expf(m1 - mn1);
        m0 = mn0; m1 = mn1;
        l0 *= sc0; l1 *= sc1;
#pragma unroll
        for (int vt = 0; vt < 8; vt++) {
            oa[vt][0] *= sc0; oa[vt][1] *= sc0;
            oa[vt][2] *= sc1; oa[vt][3] *= sc1;
        }

        float cs0 = 0.f, cs1 = 0.f;
#pragma unroll
        for (int ks = 0; ks < 8; ks++) {
            uint32_t pah[4], pal[4];
#pragma unroll
            for (int half = 0; half < 2; half++) {
                int jt = ks * 2 + half;
                float p0 = __expf(S[jt][0] - m0);
                float p1 = __expf(S[jt][1] - m0);
                float p2 = __expf(S[jt][2] - m1);
                float p3 = __expf(S[jt][3] - m1);
                cs0 += p0 + p1;
                cs1 += p2 + p3;
                float h0 = __bfloat162float(__float2bfloat16(p0));
                float h1 = __bfloat162float(__float2bfloat16(p1));
                float h2 = __bfloat162float(__float2bfloat16(p2));
                float h3 = __bfloat162float(__float2bfloat16(p3));
                pah[half * 2 + 0] = pack_bf16(h0, h1);
                pah[half * 2 + 1] = pack_bf16(h2, h3);
                pal[half * 2 + 0] = pack_bf16(p0 - h0, p1 - h1);
                pal[half * 2 + 1] = pack_bf16(p2 - h2, p3 - h3);
            }
#pragma unroll
            for (int vt = 0; vt < 8; vt++) {
                int brow = vt * 8 + (lane & 7);
                int bc = ks * 2 + ((lane >> 3) & 1);
                uint32_t voff = sw256(brow, bc);
                uint32_t b2h[2], b2l[2];
                LDSM2(b2h[0], b2h[1], sVhi + voff);
                LDSM2(b2l[0], b2l[1], sVlo + voff);
                mma16816(oa[vt], pah, b2h);
                mma16816(oa[vt], pal, b2h);
                mma16816(oa[vt], pah, b2l);
            }
        }
        cs0 += __shfl_xor_sync(0xffffffffu, cs0, 1);
        cs0 += __shfl_xor_sync(0xffffffffu, cs0, 2);
        cs1 += __shfl_xor_sync(0xffffffffu, cs1, 1);
        cs1 += __shfl_xor_sync(0xffffffffu, cs1, 2);
        l0 += cs0; l1 += cs1;
    }

    float inv0 = 1.f / l0, inv1 = 1.f / l1;
    float* orow0 = outT + ((size_t)bh * SDUP + tile * 128 + wrow0 + g) * VECD;
    float* orow1 = orow0 + 8 * VECD;
#pragma unroll
    for (int vt = 0; vt < 8; vt++) {
        int v = vt * 8 + tq * 2;
        *(float2*)(orow0 + v) = make_float2(oa[vt][0] * inv0, oa[vt][1] * inv0);
        *(float2*)(orow1 + v) = make_float2(oa[vt][2] * inv1, oa[vt][3] * inv1);
    }
}

// ---------------------------------------------------------------------------
// LayerNorm gather + bf16 split (unchanged)
// ---------------------------------------------------------------------------
__global__ __launch_bounds__(256)
void ln_gather_split_kernel(const float* __restrict__ attnT, const float* __restrict__ gam,
                            const float* __restrict__ bet, __nv_bfloat16* __restrict__ hi,
                            __nv_bfloat16* __restrict__ lo) {
    __shared__ float xs[HID];
    __shared__ float red[8];
    __shared__ float red2[8];
    const int row = blockIdx.x;
    const int b = row >> 9, s = row & 511;
    const int tid = threadIdx.x;
    const int lane = tid & 31, w = tid >> 5;

    float lsum = 0.f;
#pragma unroll
    for (int it = 0; it < 4; it++) {
        int i = it * 1024 + tid * 4;
        int h = i >> 8, d = (i >> 6) & 3, v = i & 63;
        const float* src = attnT + ((size_t)(b * 16 + h) * SDUP + (s * 4 + d)) * VECD + v;
        float4 x = *(const float4*)src;
        *(float4*)&xs[i] = x;
        lsum += x.x + x.y + x.z + x.w;
    }
#pragma unroll
    for (int o = 16; o > 0; o >>= 1) lsum += __shfl_xor_sync(0xffffffffu, lsum, o);
    if (lane == 0) red[w] = lsum;
    __syncthreads();
    float tot = 0.f;
#pragma unroll
    for (int j = 0; j < 8; j++) tot += red[j];
    float mu = tot * (1.f / HID);

    float lv = 0.f;
    for (int i = tid; i < HID; i += 256) {
        float d = xs[i] - mu;
        lv += d * d;
    }
#pragma unroll
    for (int o = 16; o > 0; o >>= 1) lv += __shfl_xor_sync(0xffffffffu, lv, o);
    if (lane == 0) red2[w] = lv;
    __syncthreads();
    float tv = 0.f;
#pragma unroll
    for (int j = 0; j < 8; j++) tv += red2[j];
    float inv = rsqrtf(tv * (1.f / HID) + 1e-12f);

#pragma unroll
    for (int it = 0; it < 4; it++) {
        int i = it * 1024 + tid * 4;
        float4 xv = *(const float4*)&xs[i];
        float4 gv = *(const float4*)&gam[i];
        float4 bv = *(const float4*)&bet[i];
        float y0 = (xv.x - mu) * inv * gv.x + bv.x;
        float y1 = (xv.y - mu) * inv * gv.y + bv.y;
        float y2 = (xv.z - mu) * inv * gv.z + bv.z;
        float y3 = (xv.w - mu) * inv * gv.w + bv.w;
        __nv_bfloat16 h0 = __float2bfloat16(y0), h1 = __float2bfloat16(y1);
        __nv_bfloat16 h2 = __float2bfloat16(y2), h3 = __float2bfloat16(y3);
        __nv_bfloat16 l0 = __float2bfloat16(y0 - __bfloat162float(h0));
        __nv_bfloat16 l1 = __float2bfloat16(y1 - __bfloat162float(h1));
        __nv_bfloat16 l2 = __float2bfloat16(y2 - __bfloat162float(h2));
        __nv_bfloat16 l3 = __float2bfloat16(y3 - __bfloat162float(h3));
        size_t o = (size_t)row * HID + i;
        *(__nv_bfloat162*)(hi + o) = __halves2bfloat162(h0, h1);
        *(__nv_bfloat162*)(hi + o + 2) = __halves2bfloat162(h2, h3);
        *(__nv_bfloat162*)(lo + o) = __halves2bfloat162(l0, l1);
        *(__nv_bfloat162*)(lo + o + 2) = __halves2bfloat162(l2, l3);
    }
}

// ---------------------------------------------------------------------------
extern "C" void kernel_launch(void* const* d_in, const int* in_sizes, int n_in,
                              void* d_out, int out_size) {
    const float* emb  = (const float*)d_in[0];
    const float* keys = (const float*)d_in[1];
    const float* vals = (const float*)d_in[2];
    const float* Wq   = (const float*)d_in[3];
    const float* bq   = (const float*)d_in[4];
    const float* Wre  = (const float*)d_in[5];
    const float* bre  = (const float*)d_in[6];
    const float* ln_g = (const float*)d_in[7];
    const float* ln_b = (const float*)d_in[8];
    float* out = (float*)d_out;

    float *qbuf, *aT;
    __nv_bfloat16 *ehi, *elo, *lnhi, *lnlo, *wqhi, *wqlo, *wrehi, *wrelo;
    __nv_bfloat16 *qhi, *qlo, *khi, *klo, *vhi, *vlo;
    cudaGetSymbolAddress((void**)&qbuf, g_q);
    cudaGetSymbolAddress((void**)&aT, g_attnT);
    cudaGetSymbolAddress((void**)&ehi, g_ehi);
    cudaGetSymbolAddress((void**)&elo, g_elo);
    cudaGetSymbolAddress((void**)&lnhi, g_lnhi);
    cudaGetSymbolAddress((void**)&lnlo, g_lnlo);
    cudaGetSymbolAddress((void**)&wqhi, g_wqhi);
    cudaGetSymbolAddress((void**)&wqlo, g_wqlo);
    cudaGetSymbolAddress((void**)&wrehi, g_wrehi);
    cudaGetSymbolAddress((void**)&wrelo, g_wrelo);
    cudaGetSymbolAddress((void**)&qhi, g_qhi);
    cudaGetSymbolAddress((void**)&qlo, g_qlo);
    cudaGetSymbolAddress((void**)&khi, g_khi);
    cudaGetSymbolAddress((void**)&klo, g_klo);
    cudaGetSymbolAddress((void**)&vhi, g_vhi);
    cudaGetSymbolAddress((void**)&vlo, g_vlo);

    cudaFuncSetAttribute(gemm_mma_kernel, cudaFuncAttributeMaxDynamicSharedMemorySize, G2_SMEM);
    cudaFuncSetAttribute(attn_mma_kernel, cudaFuncAttributeMaxDynamicSharedMemorySize, ATT_SMEM);
    cudaFuncSetAttribute(kvprep2_kernel, cudaFuncAttributeMaxDynamicSharedMemorySize, KVP_SMEM);

    split_kernel<<<(MROWS * HID / 4 + 255) / 256, 256>>>((const float4*)emb,
        (__nv_bfloat162*)ehi, (__nv_bfloat162*)elo, MROWS * HID / 4);
    split_kernel<<<(HID * HID / 4 + 255) / 256, 256>>>((const float4*)Wq,
        (__nv_bfloat162*)wqhi, (__nv_bfloat162*)wqlo, HID * HID / 4);
    split_kernel<<<(HID * HID / 4 + 255) / 256, 256>>>((const float4*)Wre,
        (__nv_bfloat162*)wrehi, (__nv_bfloat162*)wrelo, HID * HID / 4);
    kvprep2_kernel<<<4 * 32, 256, KVP_SMEM>>>(keys, vals, khi, klo, vhi, vlo);
    gemm_mma_kernel<<<dim3(HID / 128, MROWS / 256), 256, G2_SMEM>>>(
        ehi, elo, wqhi, wqlo, bq, qbuf, MROWS, HID, HID);
    qprep_kernel<<<MROWS * 4, 256>>>(qbuf, qhi, qlo);
    attn_mma_kernel<<<dim3(16, 64), 256, ATT_SMEM>>>(qhi, qlo, khi, klo, vhi, vlo, aT);
    ln_gather_split_kernel<<<MROWS, 256>>>(aT, ln_g, ln_b, lnhi, lnlo);
    gemm_mma_kernel<<<dim3(HID / 128, MROWS / 256), 256, G2_SMEM>>>(
        lnhi, lnlo, wrehi, wrelo, bre, out, MROWS, HID, HID);
}

// round 7
// speedup vs baseline: 1.4202x; 1.3991x over previous
#include <cuda_runtime.h>
#include <cuda_fp16.h>
#include <cstdint>

#define HID 4096
#define MROWS 2048
#define NKV 512
#define VECD 64
#define NHEAD 16
#define NBH 64
#define SDUP 2048

// ---------------- scratch ----------------
__device__ float g_q[MROWS * HID];
__device__ float g_attnT[NBH * SDUP * VECD];
__device__ __half g_qhi[NBH * SDUP * VECD], g_qlo[NBH * SDUP * VECD];
__device__ __half g_khi[NBH * NKV * VECD];
__device__ __half g_vhi[NBH * VECD * NKV];
__device__ __half g_ehi[MROWS * HID], g_elo[MROWS * HID];
__device__ __half g_lnhi[MROWS * HID], g_lnlo[MROWS * HID];
__device__ __half g_wqhi[HID * HID];
__device__ __half g_wrehi[HID * HID];

// ---------------- PTX helpers ----------------
__device__ __forceinline__ uint32_t smem_u32(const void* p) {
    uint32_t a;
    asm("{ .reg .u64 t; cvta.to.shared.u64 t, %1; cvt.u32.u64 %0, t; }" : "=r"(a) : "l"(p));
    return a;
}
#define CP_ASYNC16(dst, src) \
    asm volatile("cp.async.cg.shared.global [%0], [%1], 16;" :: "r"(dst), "l"(src))
#define CP_COMMIT() asm volatile("cp.async.commit_group;" ::: "memory")
#define CP_WAIT1()  asm volatile("cp.async.wait_group 1;" ::: "memory")
#define CP_WAIT0()  asm volatile("cp.async.wait_group 0;" ::: "memory")

#define LDSM4(r0, r1, r2, r3, addr)                                          \
    asm volatile("ldmatrix.sync.aligned.m8n8.x4.shared.b16 {%0,%1,%2,%3}, [%4];" \
                 : "=r"(r0), "=r"(r1), "=r"(r2), "=r"(r3) : "r"(addr))
#define LDSM2(r0, r1, addr)                                                  \
    asm volatile("ldmatrix.sync.aligned.m8n8.x2.shared.b16 {%0,%1}, [%2];"   \
                 : "=r"(r0), "=r"(r1) : "r"(addr))

__device__ __forceinline__ void mma16816h(float* c, const uint32_t* a, const uint32_t* b) {
    asm volatile(
        "mma.sync.aligned.m16n8k16.row.col.f32.f16.f16.f32 "
        "{%0,%1,%2,%3}, {%4,%5,%6,%7}, {%8,%9}, {%0,%1,%2,%3};"
        : "+f"(c[0]), "+f"(c[1]), "+f"(c[2]), "+f"(c[3])
        : "r"(a[0]), "r"(a[1]), "r"(a[2]), "r"(a[3]), "r"(b[0]), "r"(b[1]));
}

__device__ __forceinline__ uint32_t pack_h2(float a, float b) {
    __half2 t = __floats2half2_rn(a, b);
    return *(uint32_t*)&t;
}

__device__ __forceinline__ uint32_t sw_off(int r, int c16) {
    return (uint32_t)(r * 64 + ((c16 ^ ((r >> 1) & 3)) << 4));
}
__device__ __forceinline__ uint32_t sw128(int r, int c16) {
    return (uint32_t)(r * 128 + ((c16 ^ (r & 7)) << 4));
}
__device__ __forceinline__ uint32_t sw256(int r, int c16) {
    return (uint32_t)(r * 256 + ((c16 ^ (r & 7)) << 4));
}

// ---------------------------------------------------------------------------
// GEMM v3: fp16 2-product. C[M,N] = (Ahi+Alo)[M,K] @ Bhi[N,K]^T + bias
// CTA 256x128, 8 warps (4m x 2n), warp tile 64x64, BK=32, 3 stages.
// stage: Ahi 16K | Alo 16K | Bhi 8K = 40K; one barrier per iter.
// ---------------------------------------------------------------------------
#define G3_STAGE 40960
#define G3_SMEM (3 * G3_STAGE)
__global__ __launch_bounds__(256, 1)
void gemm_mma_kernel(const __half* __restrict__ Ahi, const __half* __restrict__ Alo,
                     const __half* __restrict__ Bhi,
                     const float* __restrict__ bias, float* __restrict__ C,
                     int M, int N, int K) {
    extern __shared__ char smraw[];
    const uint32_t sbase = smem_u32(smraw);
    const int tid = threadIdx.x;
    const int lane = tid & 31;
    const int warp = tid >> 5;
    const int wm = warp >> 1;
    const int wn = warp & 1;

    const int row0 = blockIdx.y * 256;
    const int col0 = blockIdx.x * 128;
    const __half* pAhi = Ahi + (size_t)row0 * K;
    const __half* pAlo = Alo + (size_t)row0 * K;
    const __half* pBhi = Bhi + (size_t)col0 * K;
    const int nk = K / 32;

    auto load_stage = [&](int kc, int st) {
        const int kbase = kc * 32;
        const uint32_t stg = sbase + st * G3_STAGE;
#pragma unroll
        for (int it = 0; it < 4; it++) {
            int idx = tid + it * 256;
            int r = idx >> 2, c = idx & 3;
            CP_ASYNC16(stg + sw_off(r, c), pAhi + (size_t)r * K + kbase + c * 8);
            CP_ASYNC16(stg + 16384 + sw_off(r, c), pAlo + (size_t)r * K + kbase + c * 8);
        }
#pragma unroll
        for (int it = 0; it < 2; it++) {
            int idx = tid + it * 256;
            int r = idx >> 2, c = idx & 3;
            CP_ASYNC16(stg + 32768 + sw_off(r, c), pBhi + (size_t)r * K + kbase + c * 8);
        }
    };

    float acc[4][8][4];
#pragma unroll
    for (int i = 0; i < 4; i++)
#pragma unroll
        for (int j = 0; j < 8; j++)
#pragma unroll
            for (int k = 0; k < 4; k++) acc[i][j][k] = 0.f;

    load_stage(0, 0); CP_COMMIT();
    load_stage(1, 1); CP_COMMIT();

    for (int kc = 0; kc < nk; kc++) {
        CP_WAIT1();
        __syncthreads();
        const int ps = kc + 2;
        if (ps < nk) load_stage(ps, ps % 3);
        CP_COMMIT();

        const uint32_t stg = sbase + (kc % 3) * G3_STAGE;
        const uint32_t sAhi = stg, sAlo = stg + 16384, sBhi = stg + 32768;

#pragma unroll
        for (int ks = 0; ks < 2; ks++) {
            const int arow = wm * 64 + (lane & 15);
            const int ac = ks * 2 + (lane >> 4);
            const int brow = wn * 64 + (lane & 7);
            const int bc = ks * 2 + ((lane >> 3) & 1);

            uint32_t ah[4][4], bf[8][2];
#pragma unroll
            for (int mt = 0; mt < 4; mt++)
                LDSM4(ah[mt][0], ah[mt][1], ah[mt][2], ah[mt][3],
                      sAhi + sw_off(arow + mt * 16, ac));
#pragma unroll
            for (int nt = 0; nt < 8; nt++)
                LDSM2(bf[nt][0], bf[nt][1], sBhi + sw_off(brow + nt * 8, bc));
#pragma unroll
            for (int mt = 0; mt < 4; mt++)
#pragma unroll
                for (int nt = 0; nt < 8; nt++)
                    mma16816h(acc[mt][nt], ah[mt], bf[nt]);

            uint32_t al[4][4];
#pragma unroll
            for (int mt = 0; mt < 4; mt++)
                LDSM4(al[mt][0], al[mt][1], al[mt][2], al[mt][3],
                      sAlo + sw_off(arow + mt * 16, ac));
#pragma unroll
            for (int mt = 0; mt < 4; mt++)
#pragma unroll
                for (int nt = 0; nt < 8; nt++)
                    mma16816h(acc[mt][nt], al[mt], bf[nt]);
        }
    }

#pragma unroll
    for (int mt = 0; mt < 4; mt++) {
        int r = row0 + wm * 64 + mt * 16 + (lane >> 2);
#pragma unroll
        for (int nt = 0; nt < 8; nt++) {
            int c = col0 + wn * 64 + nt * 8 + (lane & 3) * 2;
            float b0 = __ldg(bias + c), b1 = __ldg(bias + c + 1);
            *(float2*)(C + (size_t)r * N + c) =
                make_float2(acc[mt][nt][0] + b0, acc[mt][nt][1] + b1);
            *(float2*)(C + (size_t)(r + 8) * N + c) =
                make_float2(acc[mt][nt][2] + b0, acc[mt][nt][3] + b1);
        }
    }
}

// ---------------------------------------------------------------------------
// fp32 -> fp16 hi + lo split (for activations)
// ---------------------------------------------------------------------------
__global__ __launch_bounds__(256)
void split16_kernel(const float4* __restrict__ x, __half2* __restrict__ hi,
                    __half2* __restrict__ lo, int n4) {
    int i = blockIdx.x * 256 + threadIdx.x;
    if (i >= n4) return;
    float4 v = x[i];
    float h0 = __half2float(__float2half_rn(v.x));
    float h1 = __half2float(__float2half_rn(v.y));
    float h2 = __half2float(__float2half_rn(v.z));
    float h3 = __half2float(__float2half_rn(v.w));
    hi[2 * i] = __floats2half2_rn(v.x, v.y);
    hi[2 * i + 1] = __floats2half2_rn(v.z, v.w);
    lo[2 * i] = __floats2half2_rn(v.x - h0, v.y - h1);
    lo[2 * i + 1] = __floats2half2_rn(v.z - h2, v.w - h3);
}

// fp32 -> fp16 (hi only, for weights)
__global__ __launch_bounds__(256)
void conv16_kernel(const float4* __restrict__ x, __half2* __restrict__ hi, int n4) {
    int i = blockIdx.x * 256 + threadIdx.x;
    if (i >= n4) return;
    float4 v = x[i];
    hi[2 * i] = __floats2half2_rn(v.x, v.y);
    hi[2 * i + 1] = __floats2half2_rn(v.z, v.w);
}

// ---------------------------------------------------------------------------
// Q prep: fp32 (B,S,HID) -> qhi/qlo fp16 [bh][sdup][vec]
// ---------------------------------------------------------------------------
__global__ __launch_bounds__(256)
void qprep_kernel(const float* __restrict__ q, __half* __restrict__ qhi,
                  __half* __restrict__ qlo) {
    __shared__ float sm[1024];
    int bid = blockIdx.x;
    int d = bid & 3;
    int bs = bid >> 2;
    int b = bs >> 9, s = bs & 511;
    const float* src = q + (size_t)bs * HID + d * 1024;
    int tid = threadIdx.x;
    *(float4*)&sm[tid * 4] = *(const float4*)(src + tid * 4);
    __syncthreads();
    int h = tid >> 4;
    int v = (tid * 4) & 63;
    size_t dst = ((size_t)(b * 16 + h) * SDUP + (s * 4 + d)) * VECD + v;
    float x0 = sm[(v + 0) * 16 + h], x1 = sm[(v + 1) * 16 + h];
    float x2 = sm[(v + 2) * 16 + h], x3 = sm[(v + 3) * 16 + h];
    float h0 = __half2float(__float2half_rn(x0));
    float h1 = __half2float(__float2half_rn(x1));
    float h2 = __half2float(__float2half_rn(x2));
    float h3 = __half2float(__float2half_rn(x3));
    *(__half2*)(qhi + dst) = __floats2half2_rn(x0, x1);
    *(__half2*)(qhi + dst + 2) = __floats2half2_rn(x2, x3);
    *(__half2*)(qlo + dst) = __floats2half2_rn(x0 - h0, x1 - h1);
    *(__half2*)(qlo + dst + 2) = __floats2half2_rn(x2 - h2, x3 - h3);
}

// ---------------------------------------------------------------------------
// KV prep: fp16 hi only.  K -> [bh][n][v], V -> [bh][v][n]
// ---------------------------------------------------------------------------
#define KVP_SMEM (2 * 16 * 1024 * 4)
__global__ __launch_bounds__(256)
void kvprep_kernel(const float* __restrict__ keys, const float* __restrict__ vals,
                   __half* __restrict__ khi, __half* __restrict__ vhi) {
    extern __shared__ float smf[];
    float* sk = smf;
    float* sv = smf + 16 * 1024;
    const int bid = blockIdx.x;
    const int b = bid >> 5, nc = bid & 31;
    const int n0 = nc * 16;
    const int tid = threadIdx.x;

    const float* ksrc = keys + ((size_t)b * NKV + n0) * 1024;
    const float* vsrc = vals + ((size_t)b * NKV + n0) * 1024;
#pragma unroll
    for (int it = 0; it < 16; it++) {
        int i = tid + it * 256;
        *(float4*)&sk[i * 4] = *(const float4*)(ksrc + i * 4);
        *(float4*)&sv[i * 4] = *(const float4*)(vsrc + i * 4);
    }
    __syncthreads();

#pragma unroll
    for (int it = 0; it < 8; it++) {
        int task = tid + it * 256;
        int vg = task & 7, n = (task >> 3) & 15, h = task >> 7;
        uint32_t hhx[4];
#pragma unroll
        for (int j = 0; j < 4; j++) {
            float x0 = sk[n * 1024 + (vg * 8 + j * 2 + 0) * 16 + h];
            float x1 = sk[n * 1024 + (vg * 8 + j * 2 + 1) * 16 + h];
            hhx[j] = pack_h2(x0, x1);
        }
        size_t dst = ((size_t)(b * 16 + h) * NKV + n0 + n) * VECD + vg * 8;
        *(uint4*)(khi + dst) = make_uint4(hhx[0], hhx[1], hhx[2], hhx[3]);
    }

#pragma unroll
    for (int it = 0; it < 4; it++) {
        int task = tid + it * 256;
        int v = task & 63, h = task >> 6;
        uint32_t hhx[8];
#pragma unroll
        for (int j = 0; j < 8; j++) {
            float x0 = sv[(j * 2 + 0) * 1024 + v * 16 + h];
            float x1 = sv[(j * 2 + 1) * 1024 + v * 16 + h];
            hhx[j] = pack_h2(x0, x1);
        }
        size_t dst = ((size_t)(b * 16 + h) * VECD + v) * NKV + n0;
        *(uint4*)(vhi + dst) = make_uint4(hhx[0], hhx[1], hhx[2], hhx[3]);
        *(uint4*)(vhi + dst + 8) = make_uint4(hhx[4], hhx[5], hhx[6], hhx[7]);
    }
}

// ---------------------------------------------------------------------------
// Flash attention, fp16 2-product, double-buffered K/V.
// smem: Qhi 16K | Qlo 16K | buf0(K 16K, V 16K) | buf1(K 16K, V 16K) = 96K
// ---------------------------------------------------------------------------
#define ATT_SMEM (6 * 16384)
__global__ __launch_bounds__(256)
void attn_mma_kernel(const __half* __restrict__ qhi, const __half* __restrict__ qlo,
                     const __half* __restrict__ khi, const __half* __restrict__ vhi,
                     float* __restrict__ outT) {
    extern __shared__ char smraw[];
    const uint32_t sQhi = smem_u32(smraw);
    const uint32_t sQlo = sQhi + 16384;
    const uint32_t sKV = sQhi + 32768;      // + buf*32768 : K @0, V @16384

    const int tid = threadIdx.x;
    const int lane = tid & 31;
    const int warp = tid >> 5;
    const int g = lane >> 2;
    const int tq = lane & 3;
    const int bh = blockIdx.y;
    const int tile = blockIdx.x;
    const int wrow0 = warp * 16;

    const __half* qh = qhi + ((size_t)bh * SDUP + tile * 128) * VECD;
    const __half* ql = qlo + ((size_t)bh * SDUP + tile * 128) * VECD;
    const __half* kh = khi + (size_t)bh * NKV * VECD;
    const __half* vh = vhi + (size_t)bh * VECD * NKV;

    auto load_kv = [&](int ck, int buf) {
        const int n0 = ck * 128;
        const uint32_t sK = sKV + buf * 32768;
        const uint32_t sV = sK + 16384;
#pragma unroll
        for (int it = 0; it < 4; it++) {
            int idx = tid + it * 256;
            int r = idx >> 3, c = idx & 7;
            CP_ASYNC16(sK + sw128(r, c), kh + (size_t)(n0 + r) * VECD + c * 8);
            int v = idx >> 4, cc = idx & 15;
            CP_ASYNC16(sV + sw256(v, cc), vh + (size_t)v * NKV + n0 + cc * 8);
        }
    };

    // prologue: Q + KV0 as one group
#pragma unroll
    for (int it = 0; it < 4; it++) {
        int idx = tid + it * 256;
        int r = idx >> 3, c = idx & 7;
        CP_ASYNC16(sQhi + sw128(r, c), qh + (size_t)r * VECD + c * 8);
        CP_ASYNC16(sQlo + sw128(r, c), ql + (size_t)r * VECD + c * 8);
    }
    load_kv(0, 0);
    CP_COMMIT();

    float oa[8][4];
#pragma unroll
    for (int i = 0; i < 8; i++)
#pragma unroll
        for (int j = 0; j < 4; j++) oa[i][j] = 0.f;
    float m0 = -1e30f, m1 = -1e30f, l0 = 0.f, l1 = 0.f;

    for (int ck = 0; ck < 4; ck++) {
        CP_WAIT0();
        __syncthreads();
        if (ck < 3) {
            load_kv(ck + 1, (ck + 1) & 1);
            CP_COMMIT();
        }
        const uint32_t sK = sKV + (ck & 1) * 32768;
        const uint32_t sV = sK + 16384;

        // ---- S = (qhi+qlo) @ khi^T ----
        float S[16][4];
#pragma unroll
        for (int jt = 0; jt < 16; jt++)
#pragma unroll
            for (int j = 0; j < 4; j++) S[jt][j] = 0.f;

#pragma unroll
        for (int ks = 0; ks < 4; ks++) {
            uint32_t ah[4], al[4];
            int arow = wrow0 + (lane & 15);
            int ac = ks * 2 + (lane >> 4);
            uint32_t qoff = sw128(arow, ac);
            LDSM4(ah[0], ah[1], ah[2], ah[3], sQhi + qoff);
            LDSM4(al[0], al[1], al[2], al[3], sQlo + qoff);
#pragma unroll
            for (int jt = 0; jt < 16; jt++) {
                int brow = jt * 8 + (lane & 7);
                int bc = ks * 2 + ((lane >> 3) & 1);
                uint32_t b2[2];
                LDSM2(b2[0], b2[1], sK + sw128(brow, bc));
                mma16816h(S[jt], ah, b2);
                mma16816h(S[jt], al, b2);
            }
        }

        // ---- online softmax ----
        float cm0 = -1e30f, cm1 = -1e30f;
#pragma unroll
        for (int jt = 0; jt < 16; jt++) {
            S[jt][0] *= 0.125f; S[jt][1] *= 0.125f;
            S[jt][2] *= 0.125f; S[jt][3] *= 0.125f;
            cm0 = fmaxf(cm0, fmaxf(S[jt][0], S[jt][1]));
            cm1 = fmaxf(cm1, fmaxf(S[jt][2], S[jt][3]));
        }
        cm0 = fmaxf(cm0, __shfl_xor_sync(0xffffffffu, cm0, 1));
        cm0 = fmaxf(cm0, __shfl_xor_sync(0xffffffffu, cm0, 2));
        cm1 = fmaxf(cm1, __shfl_xor_sync(0xffffffffu, cm1, 1));
        cm1 = fmaxf(cm1, __shfl_xor_sync(0xffffffffu, cm1, 2));
        float mn0 = fmaxf(m0, cm0), mn1 = fmaxf(m1, cm1);
        float sc0 = __expf(m0 - mn0), sc1 = __expf(m1 - mn1);
        m0 = mn0; m1 = mn1;
        l0 *= sc0; l1 *= sc1;
#pragma unroll
        for (int vt = 0; vt < 8; vt++) {
            oa[vt][0] *= sc0; oa[vt][1] *= sc0;
            oa[vt][2] *= sc1; oa[vt][3] *= sc1;
        }

        // ---- P = exp(S-m) (hi/lo), out += P @ vhi ----
        float cs0 = 0.f, cs1 = 0.f;
#pragma unroll
        for (int ks = 0; ks < 8; ks++) {
            uint32_t pah[4], pal[4];
#pragma unroll
            for (int half = 0; half < 2; half++) {
                int jt = ks * 2 + half;
                float p0 = __expf(S[jt][0] - m0);
                float p1 = __expf(S[jt][1] - m0);
                float p2 = __expf(S[jt][2] - m1);
                float p3 = __expf(S[jt][3] - m1);
                cs0 += p0 + p1;
                cs1 += p2 + p3;
                float h0 = __half2float(__float2half_rn(p0));
                float h1 = __half2float(__float2half_rn(p1));
                float h2 = __half2float(__float2half_rn(p2));
                float h3 = __half2float(__float2half_rn(p3));
                pah[half * 2 + 0] = pack_h2(h0, h1);
                pah[half * 2 + 1] = pack_h2(h2, h3);
                pal[half * 2 + 0] = pack_h2(p0 - h0, p1 - h1);
                pal[half * 2 + 1] = pack_h2(p2 - h2, p3 - h3);
            }
#pragma unroll
            for (int vt = 0; vt < 8; vt++) {
                int brow = vt * 8 + (lane & 7);
                int bc = ks * 2 + ((lane >> 3) & 1);
                uint32_t b2[2];
                LDSM2(b2[0], b2[1], sV + sw256(brow, bc));
                mma16816h(oa[vt], pah, b2);
                mma16816h(oa[vt], pal, b2);
            }
        }
        cs0 += __shfl_xor_sync(0xffffffffu, cs0, 1);
        cs0 += __shfl_xor_sync(0xffffffffu, cs0, 2);
        cs1 += __shfl_xor_sync(0xffffffffu, cs1, 1);
        cs1 += __shfl_xor_sync(0xffffffffu, cs1, 2);
        l0 += cs0; l1 += cs1;
    }

    float inv0 = 1.f / l0, inv1 = 1.f / l1;
    float* orow0 = outT + ((size_t)bh * SDUP + tile * 128 + wrow0 + g) * VECD;
    float* orow1 = orow0 + 8 * VECD;
#pragma unroll
    for (int vt = 0; vt < 8; vt++) {
        int v = vt * 8 + tq * 2;
        *(float2*)(orow0 + v) = make_float2(oa[vt][0] * inv0, oa[vt][1] * inv0);
        *(float2*)(orow1 + v) = make_float2(oa[vt][2] * inv1, oa[vt][3] * inv1);
    }
}

// ---------------------------------------------------------------------------
// LayerNorm gather + fp16 hi/lo split
// ---------------------------------------------------------------------------
__global__ __launch_bounds__(256)
void ln_gather_split_kernel(const float* __restrict__ attnT, const float* __restrict__ gam,
                            const float* __restrict__ bet, __half* __restrict__ hi,
                            __half* __restrict__ lo) {
    __shared__ float xs[HID];
    __shared__ float red[8];
    __shared__ float red2[8];
    const int row = blockIdx.x;
    const int b = row >> 9, s = row & 511;
    const int tid = threadIdx.x;
    const int lane = tid & 31, w = tid >> 5;

    float lsum = 0.f;
#pragma unroll
    for (int it = 0; it < 4; it++) {
        int i = it * 1024 + tid * 4;
        int h = i >> 8, d = (i >> 6) & 3, v = i & 63;
        const float* src = attnT + ((size_t)(b * 16 + h) * SDUP + (s * 4 + d)) * VECD + v;
        float4 x = *(const float4*)src;
        *(float4*)&xs[i] = x;
        lsum += x.x + x.y + x.z + x.w;
    }
#pragma unroll
    for (int o = 16; o > 0; o >>= 1) lsum += __shfl_xor_sync(0xffffffffu, lsum, o);
    if (lane == 0) red[w] = lsum;
    __syncthreads();
    float tot = 0.f;
#pragma unroll
    for (int j = 0; j < 8; j++) tot += red[j];
    float mu = tot * (1.f / HID);

    float lv = 0.f;
    for (int i = tid; i < HID; i += 256) {
        float d = xs[i] - mu;
        lv += d * d;
    }
#pragma unroll
    for (int o = 16; o > 0; o >>= 1) lv += __shfl_xor_sync(0xffffffffu, lv, o);
    if (lane == 0) red2[w] = lv;
    __syncthreads();
    float tv = 0.f;
#pragma unroll
    for (int j = 0; j < 8; j++) tv += red2[j];
    float inv = rsqrtf(tv * (1.f / HID) + 1e-12f);

#pragma unroll
    for (int it = 0; it < 4; it++) {
        int i = it * 1024 + tid * 4;
        float4 xv = *(const float4*)&xs[i];
        float4 gv = *(const float4*)&gam[i];
        float4 bv = *(const float4*)&bet[i];
        float y0 = (xv.x - mu) * inv * gv.x + bv.x;
        float y1 = (xv.y - mu) * inv * gv.y + bv.y;
        float y2 = (xv.z - mu) * inv * gv.z + bv.z;
        float y3 = (xv.w - mu) * inv * gv.w + bv.w;
        float h0 = __half2float(__float2half_rn(y0));
        float h1 = __half2float(__float2half_rn(y1));
        float h2 = __half2float(__float2half_rn(y2));
        float h3 = __half2float(__float2half_rn(y3));
        size_t o = (size_t)row * HID + i;
        *(__half2*)(hi + o) = __floats2half2_rn(y0, y1);
        *(__half2*)(hi + o + 2) = __floats2half2_rn(y2, y3);
        *(__half2*)(lo + o) = __floats2half2_rn(y0 - h0, y1 - h1);
        *(__half2*)(lo + o + 2) = __floats2half2_rn(y2 - h2, y3 - h3);
    }
}

// ---------------------------------------------------------------------------
extern "C" void kernel_launch(void* const* d_in, const int* in_sizes, int n_in,
                              void* d_out, int out_size) {
    const float* emb  = (const float*)d_in[0];
    const float* keys = (const float*)d_in[1];
    const float* vals = (const float*)d_in[2];
    const float* Wq   = (const float*)d_in[3];
    const float* bq   = (const float*)d_in[4];
    const float* Wre  = (const float*)d_in[5];
    const float* bre  = (const float*)d_in[6];
    const float* ln_g = (const float*)d_in[7];
    const float* ln_b = (const float*)d_in[8];
    float* out = (float*)d_out;

    float *qbuf, *aT;
    __half *ehi, *elo, *lnhi, *lnlo, *wqhi, *wrehi;
    __half *qhi, *qlo, *khi, *vhi;
    cudaGetSymbolAddress((void**)&qbuf, g_q);
    cudaGetSymbolAddress((void**)&aT, g_attnT);
    cudaGetSymbolAddress((void**)&ehi, g_ehi);
    cudaGetSymbolAddress((void**)&elo, g_elo);
    cudaGetSymbolAddress((void**)&lnhi, g_lnhi);
    cudaGetSymbolAddress((void**)&lnlo, g_lnlo);
    cudaGetSymbolAddress((void**)&wqhi, g_wqhi);
    cudaGetSymbolAddress((void**)&wrehi, g_wrehi);
    cudaGetSymbolAddress((void**)&qhi, g_qhi);
    cudaGetSymbolAddress((void**)&qlo, g_qlo);
    cudaGetSymbolAddress((void**)&khi, g_khi);
    cudaGetSymbolAddress((void**)&vhi, g_vhi);

    cudaFuncSetAttribute(gemm_mma_kernel, cudaFuncAttributeMaxDynamicSharedMemorySize, G3_SMEM);
    cudaFuncSetAttribute(attn_mma_kernel, cudaFuncAttributeMaxDynamicSharedMemorySize, ATT_SMEM);
    cudaFuncSetAttribute(kvprep_kernel, cudaFuncAttributeMaxDynamicSharedMemorySize, KVP_SMEM);

    split16_kernel<<<(MROWS * HID / 4 + 255) / 256, 256>>>((const float4*)emb,
        (__half2*)ehi, (__half2*)elo, MROWS * HID / 4);
    conv16_kernel<<<(HID * HID / 4 + 255) / 256, 256>>>((const float4*)Wq,
        (__half2*)wqhi, HID * HID / 4);
    conv16_kernel<<<(HID * HID / 4 + 255) / 256, 256>>>((const float4*)Wre,
        (__half2*)wrehi, HID * HID / 4);
    kvprep_kernel<<<4 * 32, 256, KVP_SMEM>>>(keys, vals, khi, vhi);
    gemm_mma_kernel<<<dim3(HID / 128, MROWS / 256), 256, G3_SMEM>>>(
        ehi, elo, wqhi, bq, qbuf, MROWS, HID, HID);
    qprep_kernel<<<MROWS * 4, 256>>>(qbuf, qhi, qlo);
    attn_mma_kernel<<<dim3(16, 64), 256, ATT_SMEM>>>(qhi, qlo, khi, vhi, aT);
    ln_gather_split_kernel<<<MROWS, 256>>>(aT, ln_g, ln_b, lnhi, lnlo);
    gemm_mma_kernel<<<dim3(HID / 128, MROWS / 256), 256, G3_SMEM>>>(
        lnhi, lnlo, wrehi, bre, out, MROWS, HID, HID);
}

// round 8
// speedup vs baseline: 1.5766x; 1.1101x over previous
#include <cuda_runtime.h>
#include <cuda_fp16.h>
#include <cstdint>

#define HID 4096
#define MROWS 2048
#define NKV 512
#define VECD 64
#define NHEAD 16
#define NBH 64
#define SDUP 2048

// ---------------- scratch ----------------
__device__ float g_q[MROWS * HID];
__device__ float g_attnT[NBH * SDUP * VECD];
__device__ __half g_qhi[NBH * SDUP * VECD], g_qlo[NBH * SDUP * VECD];
__device__ __half g_khi[NBH * NKV * VECD];
__device__ __half g_vhi[NBH * VECD * NKV];
__device__ __half g_ehi[MROWS * HID], g_elo[MROWS * HID];
__device__ __half g_lnhi[MROWS * HID], g_lnlo[MROWS * HID];
__device__ __half g_wqhi[HID * HID];
__device__ __half g_wrehi[HID * HID];

// ---------------- PTX helpers ----------------
__device__ __forceinline__ uint32_t smem_u32(const void* p) {
    uint32_t a;
    asm("{ .reg .u64 t; cvta.to.shared.u64 t, %1; cvt.u32.u64 %0, t; }" : "=r"(a) : "l"(p));
    return a;
}
#define CP_ASYNC16(dst, src) \
    asm volatile("cp.async.cg.shared.global [%0], [%1], 16;" :: "r"(dst), "l"(src))
#define CP_COMMIT() asm volatile("cp.async.commit_group;" ::: "memory")
#define CP_WAIT0()  asm volatile("cp.async.wait_group 0;" ::: "memory")

#define LDSM4(r0, r1, r2, r3, addr)                                          \
    asm volatile("ldmatrix.sync.aligned.m8n8.x4.shared.b16 {%0,%1,%2,%3}, [%4];" \
                 : "=r"(r0), "=r"(r1), "=r"(r2), "=r"(r3) : "r"(addr))
#define LDSM2(r0, r1, addr)                                                  \
    asm volatile("ldmatrix.sync.aligned.m8n8.x2.shared.b16 {%0,%1}, [%2];"   \
                 : "=r"(r0), "=r"(r1) : "r"(addr))

__device__ __forceinline__ void mma16816h(float* c, const uint32_t* a, const uint32_t* b) {
    asm volatile(
        "mma.sync.aligned.m16n8k16.row.col.f32.f16.f16.f32 "
        "{%0,%1,%2,%3}, {%4,%5,%6,%7}, {%8,%9}, {%0,%1,%2,%3};"
        : "+f"(c[0]), "+f"(c[1]), "+f"(c[2]), "+f"(c[3])
        : "r"(a[0]), "r"(a[1]), "r"(a[2]), "r"(a[3]), "r"(b[0]), "r"(b[1]));
}

__device__ __forceinline__ uint32_t pack_h2(float a, float b) {
    __half2 t = __floats2half2_rn(a, b);
    return *(uint32_t*)&t;
}

__device__ __forceinline__ uint32_t sw128(int r, int c16) {
    return (uint32_t)(r * 128 + ((c16 ^ (r & 7)) << 4));
}
__device__ __forceinline__ uint32_t sw256(int r, int c16) {
    return (uint32_t)(r * 256 + ((c16 ^ (r & 7)) << 4));
}

// ---------------------------------------------------------------------------
// GEMM v4: fp16 2-product, BK=64, 2-stage cp.async, one barrier per 64-K.
// CTA 256x128 (8 warps, 64x64 warp tiles).
// stage: Ahi[256][64] 32K | Alo 32K | Bhi[128][64] 16K = 80K; 2 stages = 160K
// ---------------------------------------------------------------------------
#define G4_STAGE 81920
#define G4_SMEM (2 * G4_STAGE)
__global__ __launch_bounds__(256, 1)
void gemm_mma_kernel(const __half* __restrict__ Ahi, const __half* __restrict__ Alo,
                     const __half* __restrict__ Bhi,
                     const float* __restrict__ bias, float* __restrict__ C,
                     int M, int N, int K) {
    extern __shared__ char smraw[];
    const uint32_t sbase = smem_u32(smraw);
    const int tid = threadIdx.x;
    const int lane = tid & 31;
    const int warp = tid >> 5;
    const int wm = warp >> 1;
    const int wn = warp & 1;

    const int row0 = blockIdx.y * 256;
    const int col0 = blockIdx.x * 128;
    const __half* pAhi = Ahi + (size_t)row0 * K;
    const __half* pAlo = Alo + (size_t)row0 * K;
    const __half* pBhi = Bhi + (size_t)col0 * K;
    const int nk = K / 64;

    auto load_stage = [&](int kc, int st) {
        const int kbase = kc * 64;
        const uint32_t stg = sbase + st * G4_STAGE;
        // A: 256 rows x 8 chunks x 2 types
#pragma unroll
        for (int it = 0; it < 8; it++) {
            int idx = tid + it * 256;
            int r = idx >> 3, c = idx & 7;
            CP_ASYNC16(stg + sw128(r, c), pAhi + (size_t)r * K + kbase + c * 8);
            CP_ASYNC16(stg + 32768 + sw128(r, c), pAlo + (size_t)r * K + kbase + c * 8);
        }
        // B: 128 rows x 8 chunks
#pragma unroll
        for (int it = 0; it < 4; it++) {
            int idx = tid + it * 256;
            int r = idx >> 3, c = idx & 7;
            CP_ASYNC16(stg + 65536 + sw128(r, c), pBhi + (size_t)r * K + kbase + c * 8);
        }
    };

    float acc[4][8][4];
#pragma unroll
    for (int i = 0; i < 4; i++)
#pragma unroll
        for (int j = 0; j < 8; j++)
#pragma unroll
            for (int k = 0; k < 4; k++) acc[i][j][k] = 0.f;

    load_stage(0, 0); CP_COMMIT();

    for (int kc = 0; kc < nk; kc++) {
        CP_WAIT0();
        __syncthreads();
        if (kc + 1 < nk) {
            load_stage(kc + 1, (kc + 1) & 1);
            CP_COMMIT();
        }

        const uint32_t stg = sbase + (kc & 1) * G4_STAGE;
        const uint32_t sAhi = stg, sAlo = stg + 32768, sBhi = stg + 65536;

#pragma unroll
        for (int ks = 0; ks < 4; ks++) {
            const int arow = wm * 64 + (lane & 15);
            const int ac = ks * 2 + (lane >> 4);
            const int brow = wn * 64 + (lane & 7);
            const int bc = ks * 2 + ((lane >> 3) & 1);

            uint32_t ah[4][4], bf[8][2];
#pragma unroll
            for (int mt = 0; mt < 4; mt++)
                LDSM4(ah[mt][0], ah[mt][1], ah[mt][2], ah[mt][3],
                      sAhi + sw128(arow + mt * 16, ac));
#pragma unroll
            for (int nt = 0; nt < 8; nt++)
                LDSM2(bf[nt][0], bf[nt][1], sBhi + sw128(brow + nt * 8, bc));
#pragma unroll
            for (int mt = 0; mt < 4; mt++)
#pragma unroll
                for (int nt = 0; nt < 8; nt++)
                    mma16816h(acc[mt][nt], ah[mt], bf[nt]);

            uint32_t al[4][4];
#pragma unroll
            for (int mt = 0; mt < 4; mt++)
                LDSM4(al[mt][0], al[mt][1], al[mt][2], al[mt][3],
                      sAlo + sw128(arow + mt * 16, ac));
#pragma unroll
            for (int mt = 0; mt < 4; mt++)
#pragma unroll
                for (int nt = 0; nt < 8; nt++)
                    mma16816h(acc[mt][nt], al[mt], bf[nt]);
        }
    }

#pragma unroll
    for (int mt = 0; mt < 4; mt++) {
        int r = row0 + wm * 64 + mt * 16 + (lane >> 2);
#pragma unroll
        for (int nt = 0; nt < 8; nt++) {
            int c = col0 + wn * 64 + nt * 8 + (lane & 3) * 2;
            float b0 = __ldg(bias + c), b1 = __ldg(bias + c + 1);
            *(float2*)(C + (size_t)r * N + c) =
                make_float2(acc[mt][nt][0] + b0, acc[mt][nt][1] + b1);
            *(float2*)(C + (size_t)(r + 8) * N + c) =
                make_float2(acc[mt][nt][2] + b0, acc[mt][nt][3] + b1);
        }
    }
}

// ---------------------------------------------------------------------------
// fp32 -> fp16 hi + lo split (activations)
// ---------------------------------------------------------------------------
__global__ __launch_bounds__(256)
void split16_kernel(const float4* __restrict__ x, __half2* __restrict__ hi,
                    __half2* __restrict__ lo, int n4) {
    int i = blockIdx.x * 256 + threadIdx.x;
    if (i >= n4) return;
    float4 v = x[i];
    float h0 = __half2float(__float2half_rn(v.x));
    float h1 = __half2float(__float2half_rn(v.y));
    float h2 = __half2float(__float2half_rn(v.z));
    float h3 = __half2float(__float2half_rn(v.w));
    hi[2 * i] = __floats2half2_rn(v.x, v.y);
    hi[2 * i + 1] = __floats2half2_rn(v.z, v.w);
    lo[2 * i] = __floats2half2_rn(v.x - h0, v.y - h1);
    lo[2 * i + 1] = __floats2half2_rn(v.z - h2, v.w - h3);
}

// fp32 -> fp16 (weights)
__global__ __launch_bounds__(256)
void conv16_kernel(const float4* __restrict__ x, __half2* __restrict__ hi, int n4) {
    int i = blockIdx.x * 256 + threadIdx.x;
    if (i >= n4) return;
    float4 v = x[i];
    hi[2 * i] = __floats2half2_rn(v.x, v.y);
    hi[2 * i + 1] = __floats2half2_rn(v.z, v.w);
}

// ---------------------------------------------------------------------------
// Q prep: fp32 (B,S,HID) -> qhi/qlo fp16 [bh][sdup][vec]
// ---------------------------------------------------------------------------
__global__ __launch_bounds__(256)
void qprep_kernel(const float* __restrict__ q, __half* __restrict__ qhi,
                  __half* __restrict__ qlo) {
    __shared__ float sm[1024];
    int bid = blockIdx.x;
    int d = bid & 3;
    int bs = bid >> 2;
    int b = bs >> 9, s = bs & 511;
    const float* src = q + (size_t)bs * HID + d * 1024;
    int tid = threadIdx.x;
    *(float4*)&sm[tid * 4] = *(const float4*)(src + tid * 4);
    __syncthreads();
    int h = tid >> 4;
    int v = (tid * 4) & 63;
    size_t dst = ((size_t)(b * 16 + h) * SDUP + (s * 4 + d)) * VECD + v;
    float x0 = sm[(v + 0) * 16 + h], x1 = sm[(v + 1) * 16 + h];
    float x2 = sm[(v + 2) * 16 + h], x3 = sm[(v + 3) * 16 + h];
    float h0 = __half2float(__float2half_rn(x0));
    float h1 = __half2float(__float2half_rn(x1));
    float h2 = __half2float(__float2half_rn(x2));
    float h3 = __half2float(__float2half_rn(x3));
    *(__half2*)(qhi + dst) = __floats2half2_rn(x0, x1);
    *(__half2*)(qhi + dst + 2) = __floats2half2_rn(x2, x3);
    *(__half2*)(qlo + dst) = __floats2half2_rn(x0 - h0, x1 - h1);
    *(__half2*)(qlo + dst + 2) = __floats2half2_rn(x2 - h2, x3 - h3);
}

// ---------------------------------------------------------------------------
// KV prep: fp16.  K -> [bh][n][v], V -> [bh][v][n]
// ---------------------------------------------------------------------------
#define KVP_SMEM (2 * 16 * 1024 * 4)
__global__ __launch_bounds__(256)
void kvprep_kernel(const float* __restrict__ keys, const float* __restrict__ vals,
                   __half* __restrict__ khi, __half* __restrict__ vhi) {
    extern __shared__ float smf[];
    float* sk = smf;
    float* sv = smf + 16 * 1024;
    const int bid = blockIdx.x;
    const int b = bid >> 5, nc = bid & 31;
    const int n0 = nc * 16;
    const int tid = threadIdx.x;

    const float* ksrc = keys + ((size_t)b * NKV + n0) * 1024;
    const float* vsrc = vals + ((size_t)b * NKV + n0) * 1024;
#pragma unroll
    for (int it = 0; it < 16; it++) {
        int i = tid + it * 256;
        *(float4*)&sk[i * 4] = *(const float4*)(ksrc + i * 4);
        *(float4*)&sv[i * 4] = *(const float4*)(vsrc + i * 4);
    }
    __syncthreads();

#pragma unroll
    for (int it = 0; it < 8; it++) {
        int task = tid + it * 256;
        int vg = task & 7, n = (task >> 3) & 15, h = task >> 7;
        uint32_t hhx[4];
#pragma unroll
        for (int j = 0; j < 4; j++) {
            float x0 = sk[n * 1024 + (vg * 8 + j * 2 + 0) * 16 + h];
            float x1 = sk[n * 1024 + (vg * 8 + j * 2 + 1) * 16 + h];
            hhx[j] = pack_h2(x0, x1);
        }
        size_t dst = ((size_t)(b * 16 + h) * NKV + n0 + n) * VECD + vg * 8;
        *(uint4*)(khi + dst) = make_uint4(hhx[0], hhx[1], hhx[2], hhx[3]);
    }

#pragma unroll
    for (int it = 0; it < 4; it++) {
        int task = tid + it * 256;
        int v = task & 63, h = task >> 6;
        uint32_t hhx[8];
#pragma unroll
        for (int j = 0; j < 8; j++) {
            float x0 = sv[(j * 2 + 0) * 1024 + v * 16 + h];
            float x1 = sv[(j * 2 + 1) * 1024 + v * 16 + h];
            hhx[j] = pack_h2(x0, x1);
        }
        size_t dst = ((size_t)(b * 16 + h) * VECD + v) * NKV + n0;
        *(uint4*)(vhi + dst) = make_uint4(hhx[0], hhx[1], hhx[2], hhx[3]);
        *(uint4*)(vhi + dst + 8) = make_uint4(hhx[4], hhx[5], hhx[6], hhx[7]);
    }
}

// ---------------------------------------------------------------------------
// Flash attention, fp16 2-product, double-buffered K/V (unchanged from R7)
// ---------------------------------------------------------------------------
#define ATT_SMEM (6 * 16384)
__global__ __launch_bounds__(256)
void attn_mma_kernel(const __half* __restrict__ qhi, const __half* __restrict__ qlo,
                     const __half* __restrict__ khi, const __half* __restrict__ vhi,
                     float* __restrict__ outT) {
    extern __shared__ char smraw[];
    const uint32_t sQhi = smem_u32(smraw);
    const uint32_t sQlo = sQhi + 16384;
    const uint32_t sKV = sQhi + 32768;

    const int tid = threadIdx.x;
    const int lane = tid & 31;
    const int warp = tid >> 5;
    const int g = lane >> 2;
    const int tq = lane & 3;
    const int bh = blockIdx.y;
    const int tile = blockIdx.x;
    const int wrow0 = warp * 16;

    const __half* qh = qhi + ((size_t)bh * SDUP + tile * 128) * VECD;
    const __half* ql = qlo + ((size_t)bh * SDUP + tile * 128) * VECD;
    const __half* kh = khi + (size_t)bh * NKV * VECD;
    const __half* vh = vhi + (size_t)bh * VECD * NKV;

    auto load_kv = [&](int ck, int buf) {
        const int n0 = ck * 128;
        const uint32_t sK = sKV + buf * 32768;
        const uint32_t sV = sK + 16384;
#pragma unroll
        for (int it = 0; it < 4; it++) {
            int idx = tid + it * 256;
            int r = idx >> 3, c = idx & 7;
            CP_ASYNC16(sK + sw128(r, c), kh + (size_t)(n0 + r) * VECD + c * 8);
            int v = idx >> 4, cc = idx & 15;
            CP_ASYNC16(sV + sw256(v, cc), vh + (size_t)v * NKV + n0 + cc * 8);
        }
    };

#pragma unroll
    for (int it = 0; it < 4; it++) {
        int idx = tid + it * 256;
        int r = idx >> 3, c = idx & 7;
        CP_ASYNC16(sQhi + sw128(r, c), qh + (size_t)r * VECD + c * 8);
        CP_ASYNC16(sQlo + sw128(r, c), ql + (size_t)r * VECD + c * 8);
    }
    load_kv(0, 0);
    CP_COMMIT();

    float oa[8][4];
#pragma unroll
    for (int i = 0; i < 8; i++)
#pragma unroll
        for (int j = 0; j < 4; j++) oa[i][j] = 0.f;
    float m0 = -1e30f, m1 = -1e30f, l0 = 0.f, l1 = 0.f;

    for (int ck = 0; ck < 4; ck++) {
        CP_WAIT0();
        __syncthreads();
        if (ck < 3) {
            load_kv(ck + 1, (ck + 1) & 1);
            CP_COMMIT();
        }
        const uint32_t sK = sKV + (ck & 1) * 32768;
        const uint32_t sV = sK + 16384;

        float S[16][4];
#pragma unroll
        for (int jt = 0; jt < 16; jt++)
#pragma unroll
            for (int j = 0; j < 4; j++) S[jt][j] = 0.f;

#pragma unroll
        for (int ks = 0; ks < 4; ks++) {
            uint32_t ah[4], al[4];
            int arow = wrow0 + (lane & 15);
            int ac = ks * 2 + (lane >> 4);
            uint32_t qoff = sw128(arow, ac);
            LDSM4(ah[0], ah[1], ah[2], ah[3], sQhi + qoff);
            LDSM4(al[0], al[1], al[2], al[3], sQlo + qoff);
#pragma unroll
            for (int jt = 0; jt < 16; jt++) {
                int brow = jt * 8 + (lane & 7);
                int bc = ks * 2 + ((lane >> 3) & 1);
                uint32_t b2[2];
                LDSM2(b2[0], b2[1], sK + sw128(brow, bc));
                mma16816h(S[jt], ah, b2);
                mma16816h(S[jt], al, b2);
            }
        }

        float cm0 = -1e30f, cm1 = -1e30f;
#pragma unroll
        for (int jt = 0; jt < 16; jt++) {
            S[jt][0] *= 0.125f; S[jt][1] *= 0.125f;
            S[jt][2] *= 0.125f; S[jt][3] *= 0.125f;
            cm0 = fmaxf(cm0, fmaxf(S[jt][0], S[jt][1]));
            cm1 = fmaxf(cm1, fmaxf(S[jt][2], S[jt][3]));
        }
        cm0 = fmaxf(cm0, __shfl_xor_sync(0xffffffffu, cm0, 1));
        cm0 = fmaxf(cm0, __shfl_xor_sync(0xffffffffu, cm0, 2));
        cm1 = fmaxf(cm1, __shfl_xor_sync(0xffffffffu, cm1, 1));
        cm1 = fmaxf(cm1, __shfl_xor_sync(0xffffffffu, cm1, 2));
        float mn0 = fmaxf(m0, cm0), mn1 = fmaxf(m1, cm1);
        float sc0 = __expf(m0 - mn0), sc1 = __expf(m1 - mn1);
        m0 = mn0; m1 = mn1;
        l0 *= sc0; l1 *= sc1;
#pragma unroll
        for (int vt = 0; vt < 8; vt++) {
            oa[vt][0] *= sc0; oa[vt][1] *= sc0;
            oa[vt][2] *= sc1; oa[vt][3] *= sc1;
        }

        float cs0 = 0.f, cs1 = 0.f;
#pragma unroll
        for (int ks = 0; ks < 8; ks++) {
            uint32_t pah[4], pal[4];
#pragma unroll
            for (int half = 0; half < 2; half++) {
                int jt = ks * 2 + half;
                float p0 = __expf(S[jt][0] - m0);
                float p1 = __expf(S[jt][1] - m0);
                float p2 = __expf(S[jt][2] - m1);
                float p3 = __expf(S[jt][3] - m1);
                cs0 += p0 + p1;
                cs1 += p2 + p3;
                float h0 = __half2float(__float2half_rn(p0));
                float h1 = __half2float(__float2half_rn(p1));
                float h2 = __half2float(__float2half_rn(p2));
                float h3 = __half2float(__float2half_rn(p3));
                pah[half * 2 + 0] = pack_h2(h0, h1);
                pah[half * 2 + 1] = pack_h2(h2, h3);
                pal[half * 2 + 0] = pack_h2(p0 - h0, p1 - h1);
                pal[half * 2 + 1] = pack_h2(p2 - h2, p3 - h3);
            }
#pragma unroll
            for (int vt = 0; vt < 8; vt++) {
                int brow = vt * 8 + (lane & 7);
                int bc = ks * 2 + ((lane >> 3) & 1);
                uint32_t b2[2];
                LDSM2(b2[0], b2[1], sV + sw256(brow, bc));
                mma16816h(oa[vt], pah, b2);
                mma16816h(oa[vt], pal, b2);
            }
        }
        cs0 += __shfl_xor_sync(0xffffffffu, cs0, 1);
        cs0 += __shfl_xor_sync(0xffffffffu, cs0, 2);
        cs1 += __shfl_xor_sync(0xffffffffu, cs1, 1);
        cs1 += __shfl_xor_sync(0xffffffffu, cs1, 2);
        l0 += cs0; l1 += cs1;
    }

    float inv0 = 1.f / l0, inv1 = 1.f / l1;
    float* orow0 = outT + ((size_t)bh * SDUP + tile * 128 + wrow0 + g) * VECD;
    float* orow1 = orow0 + 8 * VECD;
#pragma unroll
    for (int vt = 0; vt < 8; vt++) {
        int v = vt * 8 + tq * 2;
        *(float2*)(orow0 + v) = make_float2(oa[vt][0] * inv0, oa[vt][1] * inv0);
        *(float2*)(orow1 + v) = make_float2(oa[vt][2] * inv1, oa[vt][3] * inv1);
    }
}

// ---------------------------------------------------------------------------
// LayerNorm gather + fp16 hi/lo split (unchanged)
// ---------------------------------------------------------------------------
__global__ __launch_bounds__(256)
void ln_gather_split_kernel(const float* __restrict__ attnT, const float* __restrict__ gam,
                            const float* __restrict__ bet, __half* __restrict__ hi,
                            __half* __restrict__ lo) {
    __shared__ float xs[HID];
    __shared__ float red[8];
    __shared__ float red2[8];
    const int row = blockIdx.x;
    const int b = row >> 9, s = row & 511;
    const int tid = threadIdx.x;
    const int lane = tid & 31, w = tid >> 5;

    float lsum = 0.f;
#pragma unroll
    for (int it = 0; it < 4; it++) {
        int i = it * 1024 + tid * 4;
        int h = i >> 8, d = (i >> 6) & 3, v = i & 63;
        const float* src = attnT + ((size_t)(b * 16 + h) * SDUP + (s * 4 + d)) * VECD + v;
        float4 x = *(const float4*)src;
        *(float4*)&xs[i] = x;
        lsum += x.x + x.y + x.z + x.w;
    }
#pragma unroll
    for (int o = 16; o > 0; o >>= 1) lsum += __shfl_xor_sync(0xffffffffu, lsum, o);
    if (lane == 0) red[w] = lsum;
    __syncthreads();
    float tot = 0.f;
#pragma unroll
    for (int j = 0; j < 8; j++) tot += red[j];
    float mu = tot * (1.f / HID);

    float lv = 0.f;
    for (int i = tid; i < HID; i += 256) {
        float d = xs[i] - mu;
        lv += d * d;
    }
#pragma unroll
    for (int o = 16; o > 0; o >>= 1) lv += __shfl_xor_sync(0xffffffffu, lv, o);
    if (lane == 0) red2[w] = lv;
    __syncthreads();
    float tv = 0.f;
#pragma unroll
    for (int j = 0; j < 8; j++) tv += red2[j];
    float inv = rsqrtf(tv * (1.f / HID) + 1e-12f);

#pragma unroll
    for (int it = 0; it < 4; it++) {
        int i = it * 1024 + tid * 4;
        float4 xv = *(const float4*)&xs[i];
        float4 gv = *(const float4*)&gam[i];
        float4 bv = *(const float4*)&bet[i];
        float y0 = (xv.x - mu) * inv * gv.x + bv.x;
        float y1 = (xv.y - mu) * inv * gv.y + bv.y;
        float y2 = (xv.z - mu) * inv * gv.z + bv.z;
        float y3 = (xv.w - mu) * inv * gv.w + bv.w;
        float h0 = __half2float(__float2half_rn(y0));
        float h1 = __half2float(__float2half_rn(y1));
        float h2 = __half2float(__float2half_rn(y2));
        float h3 = __half2float(__float2half_rn(y3));
        size_t o = (size_t)row * HID + i;
        *(__half2*)(hi + o) = __floats2half2_rn(y0, y1);
        *(__half2*)(hi + o + 2) = __floats2half2_rn(y2, y3);
        *(__half2*)(lo + o) = __floats2half2_rn(y0 - h0, y1 - h1);
        *(__half2*)(lo + o + 2) = __floats2half2_rn(y2 - h2, y3 - h3);
    }
}

// ---------------------------------------------------------------------------
extern "C" void kernel_launch(void* const* d_in, const int* in_sizes, int n_in,
                              void* d_out, int out_size) {
    const float* emb  = (const float*)d_in[0];
    const float* keys = (const float*)d_in[1];
    const float* vals = (const float*)d_in[2];
    const float* Wq   = (const float*)d_in[3];
    const float* bq   = (const float*)d_in[4];
    const float* Wre  = (const float*)d_in[5];
    const float* bre  = (const float*)d_in[6];
    const float* ln_g = (const float*)d_in[7];
    const float* ln_b = (const float*)d_in[8];
    float* out = (float*)d_out;

    float *qbuf, *aT;
    __half *ehi, *elo, *lnhi, *lnlo, *wqhi, *wrehi;
    __half *qhi, *qlo, *khi, *vhi;
    cudaGetSymbolAddress((void**)&qbuf, g_q);
    cudaGetSymbolAddress((void**)&aT, g_attnT);
    cudaGetSymbolAddress((void**)&ehi, g_ehi);
    cudaGetSymbolAddress((void**)&elo, g_elo);
    cudaGetSymbolAddress((void**)&lnhi, g_lnhi);
    cudaGetSymbolAddress((void**)&lnlo, g_lnlo);
    cudaGetSymbolAddress((void**)&wqhi, g_wqhi);
    cudaGetSymbolAddress((void**)&wrehi, g_wrehi);
    cudaGetSymbolAddress((void**)&qhi, g_qhi);
    cudaGetSymbolAddress((void**)&qlo, g_qlo);
    cudaGetSymbolAddress((void**)&khi, g_khi);
    cudaGetSymbolAddress((void**)&vhi, g_vhi);

    cudaFuncSetAttribute(gemm_mma_kernel, cudaFuncAttributeMaxDynamicSharedMemorySize, G4_SMEM);
    cudaFuncSetAttribute(attn_mma_kernel, cudaFuncAttributeMaxDynamicSharedMemorySize, ATT_SMEM);
    cudaFuncSetAttribute(kvprep_kernel, cudaFuncAttributeMaxDynamicSharedMemorySize, KVP_SMEM);

    split16_kernel<<<(MROWS * HID / 4 + 255) / 256, 256>>>((const float4*)emb,
        (__half2*)ehi, (__half2*)elo, MROWS * HID / 4);
    conv16_kernel<<<(HID * HID / 4 + 255) / 256, 256>>>((const float4*)Wq,
        (__half2*)wqhi, HID * HID / 4);
    conv16_kernel<<<(HID * HID / 4 + 255) / 256, 256>>>((const float4*)Wre,
        (__half2*)wrehi, HID * HID / 4);
    kvprep_kernel<<<4 * 32, 256, KVP_SMEM>>>(keys, vals, khi, vhi);
    gemm_mma_kernel<<<dim3(HID / 128, MROWS / 256), 256, G4_SMEM>>>(
        ehi, elo, wqhi, bq, qbuf, MROWS, HID, HID);
    qprep_kernel<<<MROWS * 4, 256>>>(qbuf, qhi, qlo);
    attn_mma_kernel<<<dim3(16, 64), 256, ATT_SMEM>>>(qhi, qlo, khi, vhi, aT);
    ln_gather_split_kernel<<<MROWS, 256>>>(aT, ln_g, ln_b, lnhi, lnlo);
    gemm_mma_kernel<<<dim3(HID / 128, MROWS / 256), 256, G4_SMEM>>>(
        lnhi, lnlo, wrehi, bre, out, MROWS, HID, HID);
}

// round 9
// speedup vs baseline: 1.5882x; 1.0074x over previous
#include <cuda_runtime.h>
#include <cuda_fp16.h>
#include <cstdint>

#define HID 4096
#define MROWS 2048
#define NKV 512
#define VECD 64
#define NHEAD 16
#define NBH 64
#define SDUP 2048

// ---------------- scratch ----------------
__device__ float g_q[MROWS * HID];
__device__ float g_attnT[NBH * SDUP * VECD];
__device__ __half g_qhi[NBH * SDUP * VECD], g_qlo[NBH * SDUP * VECD];
__device__ __half g_khi[NBH * NKV * VECD];
__device__ __half g_vhi[NBH * VECD * NKV];
__device__ __half g_ehi[MROWS * HID], g_elo[MROWS * HID];
__device__ __half g_lnhi[MROWS * HID], g_lnlo[MROWS * HID];
__device__ __half g_wqhi[HID * HID];
__device__ __half g_wrehi[HID * HID];

// ---------------- PTX helpers ----------------
__device__ __forceinline__ uint32_t smem_u32(const void* p) {
    uint32_t a;
    asm("{ .reg .u64 t; cvta.to.shared.u64 t, %1; cvt.u32.u64 %0, t; }" : "=r"(a) : "l"(p));
    return a;
}
#define CP_ASYNC16(dst, src) \
    asm volatile("cp.async.cg.shared.global [%0], [%1], 16;" :: "r"(dst), "l"(src))
#define CP_COMMIT() asm volatile("cp.async.commit_group;" ::: "memory")
#define CP_WAIT0()  asm volatile("cp.async.wait_group 0;" ::: "memory")

#define LDSM4(r0, r1, r2, r3, addr)                                          \
    asm volatile("ldmatrix.sync.aligned.m8n8.x4.shared.b16 {%0,%1,%2,%3}, [%4];" \
                 : "=r"(r0), "=r"(r1), "=r"(r2), "=r"(r3) : "r"(addr))
#define LDSM2(r0, r1, addr)                                                  \
    asm volatile("ldmatrix.sync.aligned.m8n8.x2.shared.b16 {%0,%1}, [%2];"   \
                 : "=r"(r0), "=r"(r1) : "r"(addr))

__device__ __forceinline__ void mma16816h(float* c, const uint32_t* a, const uint32_t* b) {
    asm volatile(
        "mma.sync.aligned.m16n8k16.row.col.f32.f16.f16.f32 "
        "{%0,%1,%2,%3}, {%4,%5,%6,%7}, {%8,%9}, {%0,%1,%2,%3};"
        : "+f"(c[0]), "+f"(c[1]), "+f"(c[2]), "+f"(c[3])
        : "r"(a[0]), "r"(a[1]), "r"(a[2]), "r"(a[3]), "r"(b[0]), "r"(b[1]));
}

__device__ __forceinline__ uint32_t pack_h2(float a, float b) {
    __half2 t = __floats2half2_rn(a, b);
    return *(uint32_t*)&t;
}

__device__ __forceinline__ uint32_t sw128(int r, int c16) {
    return (uint32_t)(r * 128 + ((c16 ^ (r & 7)) << 4));
}
__device__ __forceinline__ uint32_t sw256(int r, int c16) {
    return (uint32_t)(r * 256 + ((c16 ^ (r & 7)) << 4));
}

// ---------------------------------------------------------------------------
// GEMM v4 (unchanged from R8): fp16 2-product, BK=64, 2-stage, 256x128 CTA.
// ---------------------------------------------------------------------------
#define G4_STAGE 81920
#define G4_SMEM (2 * G4_STAGE)
__global__ __launch_bounds__(256, 1)
void gemm_mma_kernel(const __half* __restrict__ Ahi, const __half* __restrict__ Alo,
                     const __half* __restrict__ Bhi,
                     const float* __restrict__ bias, float* __restrict__ C,
                     int M, int N, int K) {
    extern __shared__ char smraw[];
    const uint32_t sbase = smem_u32(smraw);
    const int tid = threadIdx.x;
    const int lane = tid & 31;
    const int warp = tid >> 5;
    const int wm = warp >> 1;
    const int wn = warp & 1;

    const int row0 = blockIdx.y * 256;
    const int col0 = blockIdx.x * 128;
    const __half* pAhi = Ahi + (size_t)row0 * K;
    const __half* pAlo = Alo + (size_t)row0 * K;
    const __half* pBhi = Bhi + (size_t)col0 * K;
    const int nk = K / 64;

    auto load_stage = [&](int kc, int st) {
        const int kbase = kc * 64;
        const uint32_t stg = sbase + st * G4_STAGE;
#pragma unroll
        for (int it = 0; it < 8; it++) {
            int idx = tid + it * 256;
            int r = idx >> 3, c = idx & 7;
            CP_ASYNC16(stg + sw128(r, c), pAhi + (size_t)r * K + kbase + c * 8);
            CP_ASYNC16(stg + 32768 + sw128(r, c), pAlo + (size_t)r * K + kbase + c * 8);
        }
#pragma unroll
        for (int it = 0; it < 4; it++) {
            int idx = tid + it * 256;
            int r = idx >> 3, c = idx & 7;
            CP_ASYNC16(stg + 65536 + sw128(r, c), pBhi + (size_t)r * K + kbase + c * 8);
        }
    };

    float acc[4][8][4];
#pragma unroll
    for (int i = 0; i < 4; i++)
#pragma unroll
        for (int j = 0; j < 8; j++)
#pragma unroll
            for (int k = 0; k < 4; k++) acc[i][j][k] = 0.f;

    load_stage(0, 0); CP_COMMIT();

    for (int kc = 0; kc < nk; kc++) {
        CP_WAIT0();
        __syncthreads();
        if (kc + 1 < nk) {
            load_stage(kc + 1, (kc + 1) & 1);
            CP_COMMIT();
        }

        const uint32_t stg = sbase + (kc & 1) * G4_STAGE;
        const uint32_t sAhi = stg, sAlo = stg + 32768, sBhi = stg + 65536;

#pragma unroll
        for (int ks = 0; ks < 4; ks++) {
            const int arow = wm * 64 + (lane & 15);
            const int ac = ks * 2 + (lane >> 4);
            const int brow = wn * 64 + (lane & 7);
            const int bc = ks * 2 + ((lane >> 3) & 1);

            uint32_t ah[4][4], bf[8][2];
#pragma unroll
            for (int mt = 0; mt < 4; mt++)
                LDSM4(ah[mt][0], ah[mt][1], ah[mt][2], ah[mt][3],
                      sAhi + sw128(arow + mt * 16, ac));
#pragma unroll
            for (int nt = 0; nt < 8; nt++)
                LDSM2(bf[nt][0], bf[nt][1], sBhi + sw128(brow + nt * 8, bc));
#pragma unroll
            for (int mt = 0; mt < 4; mt++)
#pragma unroll
                for (int nt = 0; nt < 8; nt++)
                    mma16816h(acc[mt][nt], ah[mt], bf[nt]);

            uint32_t al[4][4];
#pragma unroll
            for (int mt = 0; mt < 4; mt++)
                LDSM4(al[mt][0], al[mt][1], al[mt][2], al[mt][3],
                      sAlo + sw128(arow + mt * 16, ac));
#pragma unroll
            for (int mt = 0; mt < 4; mt++)
#pragma unroll
                for (int nt = 0; nt < 8; nt++)
                    mma16816h(acc[mt][nt], al[mt], bf[nt]);
        }
    }

#pragma unroll
    for (int mt = 0; mt < 4; mt++) {
        int r = row0 + wm * 64 + mt * 16 + (lane >> 2);
#pragma unroll
        for (int nt = 0; nt < 8; nt++) {
            int c = col0 + wn * 64 + nt * 8 + (lane & 3) * 2;
            float b0 = __ldg(bias + c), b1 = __ldg(bias + c + 1);
            *(float2*)(C + (size_t)r * N + c) =
                make_float2(acc[mt][nt][0] + b0, acc[mt][nt][1] + b1);
            *(float2*)(C + (size_t)(r + 8) * N + c) =
                make_float2(acc[mt][nt][2] + b0, acc[mt][nt][3] + b1);
        }
    }
}

// ---------------------------------------------------------------------------
// fp32 -> fp16 hi + lo split (activations)
// ---------------------------------------------------------------------------
__global__ __launch_bounds__(256)
void split16_kernel(const float4* __restrict__ x, __half2* __restrict__ hi,
                    __half2* __restrict__ lo, int n4) {
    int i = blockIdx.x * 256 + threadIdx.x;
    if (i >= n4) return;
    float4 v = x[i];
    float h0 = __half2float(__float2half_rn(v.x));
    float h1 = __half2float(__float2half_rn(v.y));
    float h2 = __half2float(__float2half_rn(v.z));
    float h3 = __half2float(__float2half_rn(v.w));
    hi[2 * i] = __floats2half2_rn(v.x, v.y);
    hi[2 * i + 1] = __floats2half2_rn(v.z, v.w);
    lo[2 * i] = __floats2half2_rn(v.x - h0, v.y - h1);
    lo[2 * i + 1] = __floats2half2_rn(v.z - h2, v.w - h3);
}

// fp32 -> fp16 (weights)
__global__ __launch_bounds__(256)
void conv16_kernel(const float4* __restrict__ x, __half2* __restrict__ hi, int n4) {
    int i = blockIdx.x * 256 + threadIdx.x;
    if (i >= n4) return;
    float4 v = x[i];
    hi[2 * i] = __floats2half2_rn(v.x, v.y);
    hi[2 * i + 1] = __floats2half2_rn(v.z, v.w);
}

// ---------------------------------------------------------------------------
// Q prep: fp32 (B,S,HID) -> qhi/qlo fp16 [bh][sdup][vec]
// ---------------------------------------------------------------------------
__global__ __launch_bounds__(256)
void qprep_kernel(const float* __restrict__ q, __half* __restrict__ qhi,
                  __half* __restrict__ qlo) {
    __shared__ float sm[1024];
    int bid = blockIdx.x;
    int d = bid & 3;
    int bs = bid >> 2;
    int b = bs >> 9, s = bs & 511;
    const float* src = q + (size_t)bs * HID + d * 1024;
    int tid = threadIdx.x;
    *(float4*)&sm[tid * 4] = *(const float4*)(src + tid * 4);
    __syncthreads();
    int h = tid >> 4;
    int v = (tid * 4) & 63;
    size_t dst = ((size_t)(b * 16 + h) * SDUP + (s * 4 + d)) * VECD + v;
    float x0 = sm[(v + 0) * 16 + h], x1 = sm[(v + 1) * 16 + h];
    float x2 = sm[(v + 2) * 16 + h], x3 = sm[(v + 3) * 16 + h];
    float h0 = __half2float(__float2half_rn(x0));
    float h1 = __half2float(__float2half_rn(x1));
    float h2 = __half2float(__float2half_rn(x2));
    float h3 = __half2float(__float2half_rn(x3));
    *(__half2*)(qhi + dst) = __floats2half2_rn(x0, x1);
    *(__half2*)(qhi + dst + 2) = __floats2half2_rn(x2, x3);
    *(__half2*)(qlo + dst) = __floats2half2_rn(x0 - h0, x1 - h1);
    *(__half2*)(qlo + dst + 2) = __floats2half2_rn(x2 - h2, x3 - h3);
}

// ---------------------------------------------------------------------------
// KV prep v3: 4 n-rows per CTA (512 CTAs), 32KB smem, vectorized stores.
// ---------------------------------------------------------------------------
#define KVP_SMEM (2 * 4 * 1024 * 4)
__global__ __launch_bounds__(256)
void kvprep_kernel(const float* __restrict__ keys, const float* __restrict__ vals,
                   __half* __restrict__ khi, __half* __restrict__ vhi) {
    extern __shared__ float smf[];
    float* sk = smf;               // [4][1024]
    float* sv = smf + 4 * 1024;
    const int bid = blockIdx.x;    // b*128 + nc
    const int b = bid >> 7, nc = bid & 127;
    const int n0 = nc * 4;
    const int tid = threadIdx.x;

    const float* ksrc = keys + ((size_t)b * NKV + n0) * 1024;
    const float* vsrc = vals + ((size_t)b * NKV + n0) * 1024;
#pragma unroll
    for (int it = 0; it < 4; it++) {
        int i = tid + it * 256;     // 0..1023 float4s
        *(float4*)&sk[i * 4] = *(const float4*)(ksrc + i * 4);
        *(float4*)&sv[i * 4] = *(const float4*)(vsrc + i * 4);
    }
    __syncthreads();

    // K writes: [bh][n][v], 16B per task. tasks: h(16) x n(4) x vg(8) = 512
#pragma unroll
    for (int it = 0; it < 2; it++) {
        int task = tid + it * 256;
        int vg = task & 7, n = (task >> 3) & 3, h = task >> 5;
        uint32_t hhx[4];
#pragma unroll
        for (int j = 0; j < 4; j++) {
            float x0 = sk[n * 1024 + (vg * 8 + j * 2 + 0) * 16 + h];
            float x1 = sk[n * 1024 + (vg * 8 + j * 2 + 1) * 16 + h];
            hhx[j] = pack_h2(x0, x1);
        }
        size_t dst = ((size_t)(b * 16 + h) * NKV + n0 + n) * VECD + vg * 8;
        *(uint4*)(khi + dst) = make_uint4(hhx[0], hhx[1], hhx[2], hhx[3]);
    }

    // V writes: [bh][v][n], 8B (4 n) per task. tasks: h(16) x v(64) = 1024
#pragma unroll
    for (int it = 0; it < 4; it++) {
        int task = tid + it * 256;
        int v = task & 63, h = task >> 6;
        uint32_t p0 = pack_h2(sv[0 * 1024 + v * 16 + h], sv[1 * 1024 + v * 16 + h]);
        uint32_t p1 = pack_h2(sv[2 * 1024 + v * 16 + h], sv[3 * 1024 + v * 16 + h]);
        size_t dst = ((size_t)(b * 16 + h) * VECD + v) * NKV + n0;
        *(uint2*)(vhi + dst) = make_uint2(p0, p1);
    }
}

// ---------------------------------------------------------------------------
// Flash attention (unchanged from R8)
// ---------------------------------------------------------------------------
#define ATT_SMEM (6 * 16384)
__global__ __launch_bounds__(256)
void attn_mma_kernel(const __half* __restrict__ qhi, const __half* __restrict__ qlo,
                     const __half* __restrict__ khi, const __half* __restrict__ vhi,
                     float* __restrict__ outT) {
    extern __shared__ char smraw[];
    const uint32_t sQhi = smem_u32(smraw);
    const uint32_t sQlo = sQhi + 16384;
    const uint32_t sKV = sQhi + 32768;

    const int tid = threadIdx.x;
    const int lane = tid & 31;
    const int warp = tid >> 5;
    const int g = lane >> 2;
    const int tq = lane & 3;
    const int bh = blockIdx.y;
    const int tile = blockIdx.x;
    const int wrow0 = warp * 16;

    const __half* qh = qhi + ((size_t)bh * SDUP + tile * 128) * VECD;
    const __half* ql = qlo + ((size_t)bh * SDUP + tile * 128) * VECD;
    const __half* kh = khi + (size_t)bh * NKV * VECD;
    const __half* vh = vhi + (size_t)bh * VECD * NKV;

    auto load_kv = [&](int ck, int buf) {
        const int n0 = ck * 128;
        const uint32_t sK = sKV + buf * 32768;
        const uint32_t sV = sK + 16384;
#pragma unroll
        for (int it = 0; it < 4; it++) {
            int idx = tid + it * 256;
            int r = idx >> 3, c = idx & 7;
            CP_ASYNC16(sK + sw128(r, c), kh + (size_t)(n0 + r) * VECD + c * 8);
            int v = idx >> 4, cc = idx & 15;
            CP_ASYNC16(sV + sw256(v, cc), vh + (size_t)v * NKV + n0 + cc * 8);
        }
    };

#pragma unroll
    for (int it = 0; it < 4; it++) {
        int idx = tid + it * 256;
        int r = idx >> 3, c = idx & 7;
        CP_ASYNC16(sQhi + sw128(r, c), qh + (size_t)r * VECD + c * 8);
        CP_ASYNC16(sQlo + sw128(r, c), ql + (size_t)r * VECD + c * 8);
    }
    load_kv(0, 0);
    CP_COMMIT();

    float oa[8][4];
#pragma unroll
    for (int i = 0; i < 8; i++)
#pragma unroll
        for (int j = 0; j < 4; j++) oa[i][j] = 0.f;
    float m0 = -1e30f, m1 = -1e30f, l0 = 0.f, l1 = 0.f;

    for (int ck = 0; ck < 4; ck++) {
        CP_WAIT0();
        __syncthreads();
        if (ck < 3) {
            load_kv(ck + 1, (ck + 1) & 1);
            CP_COMMIT();
        }
        const uint32_t sK = sKV + (ck & 1) * 32768;
        const uint32_t sV = sK + 16384;

        float S[16][4];
#pragma unroll
        for (int jt = 0; jt < 16; jt++)
#pragma unroll
            for (int j = 0; j < 4; j++) S[jt][j] = 0.f;

#pragma unroll
        for (int ks = 0; ks < 4; ks++) {
            uint32_t ah[4], al[4];
            int arow = wrow0 + (lane & 15);
            int ac = ks * 2 + (lane >> 4);
            uint32_t qoff = sw128(arow, ac);
            LDSM4(ah[0], ah[1], ah[2], ah[3], sQhi + qoff);
            LDSM4(al[0], al[1], al[2], al[3], sQlo + qoff);
#pragma unroll
            for (int jt = 0; jt < 16; jt++) {
                int brow = jt * 8 + (lane & 7);
                int bc = ks * 2 + ((lane >> 3) & 1);
                uint32_t b2[2];
                LDSM2(b2[0], b2[1], sK + sw128(brow, bc));
                mma16816h(S[jt], ah, b2);
                mma16816h(S[jt], al, b2);
            }
        }

        float cm0 = -1e30f, cm1 = -1e30f;
#pragma unroll
        for (int jt = 0; jt < 16; jt++) {
            S[jt][0] *= 0.125f; S[jt][1] *= 0.125f;
            S[jt][2] *= 0.125f; S[jt][3] *= 0.125f;
            cm0 = fmaxf(cm0, fmaxf(S[jt][0], S[jt][1]));
            cm1 = fmaxf(cm1, fmaxf(S[jt][2], S[jt][3]));
        }
        cm0 = fmaxf(cm0, __shfl_xor_sync(0xffffffffu, cm0, 1));
        cm0 = fmaxf(cm0, __shfl_xor_sync(0xffffffffu, cm0, 2));
        cm1 = fmaxf(cm1, __shfl_xor_sync(0xffffffffu, cm1, 1));
        cm1 = fmaxf(cm1, __shfl_xor_sync(0xffffffffu, cm1, 2));
        float mn0 = fmaxf(m0, cm0), mn1 = fmaxf(m1, cm1);
        float sc0 = __expf(m0 - mn0), sc1 = __expf(m1 - mn1);
        m0 = mn0; m1 = mn1;
        l0 *= sc0; l1 *= sc1;
#pragma unroll
        for (int vt = 0; vt < 8; vt++) {
            oa[vt][0] *= sc0; oa[vt][1] *= sc0;
            oa[vt][2] *= sc1; oa[vt][3] *= sc1;
        }

        float cs0 = 0.f, cs1 = 0.f;
#pragma unroll
        for (int ks = 0; ks < 8; ks++) {
            uint32_t pah[4], pal[4];
#pragma unroll
            for (int half = 0; half < 2; half++) {
                int jt = ks * 2 + half;
                float p0 = __expf(S[jt][0] - m0);
                float p1 = __expf(S[jt][1] - m0);
                float p2 = __expf(S[jt][2] - m1);
                float p3 = __expf(S[jt][3] - m1);
                cs0 += p0 + p1;
                cs1 += p2 + p3;
                float h0 = __half2float(__float2half_rn(p0));
                float h1 = __half2float(__float2half_rn(p1));
                float h2 = __half2float(__float2half_rn(p2));
                float h3 = __half2float(__float2half_rn(p3));
                pah[half * 2 + 0] = pack_h2(h0, h1);
                pah[half * 2 + 1] = pack_h2(h2, h3);
                pal[half * 2 + 0] = pack_h2(p0 - h0, p1 - h1);
                pal[half * 2 + 1] = pack_h2(p2 - h2, p3 - h3);
            }
#pragma unroll
            for (int vt = 0; vt < 8; vt++) {
                int brow = vt * 8 + (lane & 7);
                int bc = ks * 2 + ((lane >> 3) & 1);
                uint32_t b2[2];
                LDSM2(b2[0], b2[1], sV + sw256(brow, bc));
                mma16816h(oa[vt], pah, b2);
                mma16816h(oa[vt], pal, b2);
            }
        }
        cs0 += __shfl_xor_sync(0xffffffffu, cs0, 1);
        cs0 += __shfl_xor_sync(0xffffffffu, cs0, 2);
        cs1 += __shfl_xor_sync(0xffffffffu, cs1, 1);
        cs1 += __shfl_xor_sync(0xffffffffu, cs1, 2);
        l0 += cs0; l1 += cs1;
    }

    float inv0 = 1.f / l0, inv1 = 1.f / l1;
    float* orow0 = outT + ((size_t)bh * SDUP + tile * 128 + wrow0 + g) * VECD;
    float* orow1 = orow0 + 8 * VECD;
#pragma unroll
    for (int vt = 0; vt < 8; vt++) {
        int v = vt * 8 + tq * 2;
        *(float2*)(orow0 + v) = make_float2(oa[vt][0] * inv0, oa[vt][1] * inv0);
        *(float2*)(orow1 + v) = make_float2(oa[vt][2] * inv1, oa[vt][3] * inv1);
    }
}

// ---------------------------------------------------------------------------
// LayerNorm gather + fp16 hi/lo split (unchanged)
// ---------------------------------------------------------------------------
__global__ __launch_bounds__(256)
void ln_gather_split_kernel(const float* __restrict__ attnT, const float* __restrict__ gam,
                            const float* __restrict__ bet, __half* __restrict__ hi,
                            __half* __restrict__ lo) {
    __shared__ float xs[HID];
    __shared__ float red[8];
    __shared__ float red2[8];
    const int row = blockIdx.x;
    const int b = row >> 9, s = row & 511;
    const int tid = threadIdx.x;
    const int lane = tid & 31, w = tid >> 5;

    float lsum = 0.f;
#pragma unroll
    for (int it = 0; it < 4; it++) {
        int i = it * 1024 + tid * 4;
        int h = i >> 8, d = (i >> 6) & 3, v = i & 63;
        const float* src = attnT + ((size_t)(b * 16 + h) * SDUP + (s * 4 + d)) * VECD + v;
        float4 x = *(const float4*)src;
        *(float4*)&xs[i] = x;
        lsum += x.x + x.y + x.z + x.w;
    }
#pragma unroll
    for (int o = 16; o > 0; o >>= 1) lsum += __shfl_xor_sync(0xffffffffu, lsum, o);
    if (lane == 0) red[w] = lsum;
    __syncthreads();
    float tot = 0.f;
#pragma unroll
    for (int j = 0; j < 8; j++) tot += red[j];
    float mu = tot * (1.f / HID);

    float lv = 0.f;
    for (int i = tid; i < HID; i += 256) {
        float d = xs[i] - mu;
        lv += d * d;
    }
#pragma unroll
    for (int o = 16; o > 0; o >>= 1) lv += __shfl_xor_sync(0xffffffffu, lv, o);
    if (lane == 0) red2[w] = lv;
    __syncthreads();
    float tv = 0.f;
#pragma unroll
    for (int j = 0; j < 8; j++) tv += red2[j];
    float inv = rsqrtf(tv * (1.f / HID) + 1e-12f);

#pragma unroll
    for (int it = 0; it < 4; it++) {
        int i = it * 1024 + tid * 4;
        float4 xv = *(const float4*)&xs[i];
        float4 gv = *(const float4*)&gam[i];
        float4 bv = *(const float4*)&bet[i];
        float y0 = (xv.x - mu) * inv * gv.x + bv.x;
        float y1 = (xv.y - mu) * inv * gv.y + bv.y;
        float y2 = (xv.z - mu) * inv * gv.z + bv.z;
        float y3 = (xv.w - mu) * inv * gv.w + bv.w;
        float h0 = __half2float(__float2half_rn(y0));
        float h1 = __half2float(__float2half_rn(y1));
        float h2 = __half2float(__float2half_rn(y2));
        float h3 = __half2float(__float2half_rn(y3));
        size_t o = (size_t)row * HID + i;
        *(__half2*)(hi + o) = __floats2half2_rn(y0, y1);
        *(__half2*)(hi + o + 2) = __floats2half2_rn(y2, y3);
        *(__half2*)(lo + o) = __floats2half2_rn(y0 - h0, y1 - h1);
        *(__half2*)(lo + o + 2) = __floats2half2_rn(y2 - h2, y3 - h3);
    }
}

// ---------------------------------------------------------------------------
extern "C" void kernel_launch(void* const* d_in, const int* in_sizes, int n_in,
                              void* d_out, int out_size) {
    const float* emb  = (const float*)d_in[0];
    const float* keys = (const float*)d_in[1];
    const float* vals = (const float*)d_in[2];
    const float* Wq   = (const float*)d_in[3];
    const float* bq   = (const float*)d_in[4];
    const float* Wre  = (const float*)d_in[5];
    const float* bre  = (const float*)d_in[6];
    const float* ln_g = (const float*)d_in[7];
    const float* ln_b = (const float*)d_in[8];
    float* out = (float*)d_out;

    float *qbuf, *aT;
    __half *ehi, *elo, *lnhi, *lnlo, *wqhi, *wrehi;
    __half *qhi, *qlo, *khi, *vhi;
    cudaGetSymbolAddress((void**)&qbuf, g_q);
    cudaGetSymbolAddress((void**)&aT, g_attnT);
    cudaGetSymbolAddress((void**)&ehi, g_ehi);
    cudaGetSymbolAddress((void**)&elo, g_elo);
    cudaGetSymbolAddress((void**)&lnhi, g_lnhi);
    cudaGetSymbolAddress((void**)&lnlo, g_lnlo);
    cudaGetSymbolAddress((void**)&wqhi, g_wqhi);
    cudaGetSymbolAddress((void**)&wrehi, g_wrehi);
    cudaGetSymbolAddress((void**)&qhi, g_qhi);
    cudaGetSymbolAddress((void**)&qlo, g_qlo);
    cudaGetSymbolAddress((void**)&khi, g_khi);
    cudaGetSymbolAddress((void**)&vhi, g_vhi);

    cudaFuncSetAttribute(gemm_mma_kernel, cudaFuncAttributeMaxDynamicSharedMemorySize, G4_SMEM);
    cudaFuncSetAttribute(attn_mma_kernel, cudaFuncAttributeMaxDynamicSharedMemorySize, ATT_SMEM);
    cudaFuncSetAttribute(kvprep_kernel, cudaFuncAttributeMaxDynamicSharedMemorySize, KVP_SMEM);

    // One-time host-side stream/event setup (no device allocations; launch
    // sequence below is identical on every call).
    static cudaStream_t sA = nullptr, sB = nullptr;
    static cudaEvent_t evRoot = nullptr, evKV = nullptr, evWq = nullptr, evWre = nullptr;
    if (sA == nullptr) {
        cudaStreamCreateWithFlags(&sA, cudaStreamNonBlocking);
        cudaStreamCreateWithFlags(&sB, cudaStreamNonBlocking);
        cudaEventCreateWithFlags(&evRoot, cudaEventDisableTiming);
        cudaEventCreateWithFlags(&evKV, cudaEventDisableTiming);
        cudaEventCreateWithFlags(&evWq, cudaEventDisableTiming);
        cudaEventCreateWithFlags(&evWre, cudaEventDisableTiming);
    }

    // Fork side streams off the main (default) stream.
    cudaEventRecord(evRoot, 0);
    cudaStreamWaitEvent(sA, evRoot, 0);
    cudaStreamWaitEvent(sB, evRoot, 0);

    // sA: K/V relayout (needed only by attention)
    kvprep_kernel<<<4 * 128, 256, KVP_SMEM, sA>>>(keys, vals, khi, vhi);
    cudaEventRecord(evKV, sA);

    // sB: weight conversions (Wq needed by GEMM1, Wre by GEMM2)
    conv16_kernel<<<(HID * HID / 4 + 255) / 256, 256, 0, sB>>>(
        (const float4*)Wq, (__half2*)wqhi, HID * HID / 4);
    cudaEventRecord(evWq, sB);
    conv16_kernel<<<(HID * HID / 4 + 255) / 256, 256, 0, sB>>>(
        (const float4*)Wre, (__half2*)wrehi, HID * HID / 4);
    cudaEventRecord(evWre, sB);

    // main: activation split (concurrent with conv16(Wq))
    split16_kernel<<<(MROWS * HID / 4 + 255) / 256, 256>>>((const float4*)emb,
        (__half2*)ehi, (__half2*)elo, MROWS * HID / 4);

    cudaStreamWaitEvent(0, evWq, 0);
    gemm_mma_kernel<<<dim3(HID / 128, MROWS / 256), 256, G4_SMEM>>>(
        ehi, elo, wqhi, bq, qbuf, MROWS, HID, HID);
    qprep_kernel<<<MROWS * 4, 256>>>(qbuf, qhi, qlo);

    cudaStreamWaitEvent(0, evKV, 0);
    attn_mma_kernel<<<dim3(16, 64), 256, ATT_SMEM>>>(qhi, qlo, khi, vhi, aT);
    ln_gather_split_kernel<<<MROWS, 256>>>(aT, ln_g, ln_b, lnhi, lnlo);

    cudaStreamWaitEvent(0, evWre, 0);
    gemm_mma_kernel<<<dim3(HID / 128, MROWS / 256), 256, G4_SMEM>>>(
        lnhi, lnlo, wrehi, bre, out, MROWS, HID, HID);
}

// round 10
// speedup vs baseline: 1.8957x; 1.1936x over previous
#include <cuda_runtime.h>
#include <cuda_fp16.h>
#include <cstdint>

#define HID 4096
#define MROWS 2048
#define NKV 512
#define VECD 64
#define NHEAD 16
#define NBH 64
#define SDUP 2048

// ---------------- scratch ----------------
__device__ float g_q[MROWS * HID];
__device__ float g_attnT[NBH * SDUP * VECD];
__device__ __half g_qhi[NBH * SDUP * VECD], g_qlo[NBH * SDUP * VECD];
__device__ __half g_khi[NBH * NKV * VECD];
__device__ __half g_vhi[NBH * VECD * NKV];
__device__ __half g_ehi[MROWS * HID], g_elo[MROWS * HID];
__device__ __half g_lnhi[MROWS * HID];
__device__ __half g_wqhi[HID * HID];
__device__ __half g_wrehi[HID * HID];

// ---------------- PTX helpers ----------------
__device__ __forceinline__ uint32_t smem_u32(const void* p) {
    uint32_t a;
    asm("{ .reg .u64 t; cvta.to.shared.u64 t, %1; cvt.u32.u64 %0, t; }" : "=r"(a) : "l"(p));
    return a;
}
#define CP_ASYNC16(dst, src) \
    asm volatile("cp.async.cg.shared.global [%0], [%1], 16;" :: "r"(dst), "l"(src))
#define CP_COMMIT() asm volatile("cp.async.commit_group;" ::: "memory")
#define CP_WAIT0()  asm volatile("cp.async.wait_group 0;" ::: "memory")

#define LDSM4(r0, r1, r2, r3, addr)                                          \
    asm volatile("ldmatrix.sync.aligned.m8n8.x4.shared.b16 {%0,%1,%2,%3}, [%4];" \
                 : "=r"(r0), "=r"(r1), "=r"(r2), "=r"(r3) : "r"(addr))
#define LDSM2(r0, r1, addr)                                                  \
    asm volatile("ldmatrix.sync.aligned.m8n8.x2.shared.b16 {%0,%1}, [%2];"   \
                 : "=r"(r0), "=r"(r1) : "r"(addr))

__device__ __forceinline__ void mma16816h(float* c, const uint32_t* a, const uint32_t* b) {
    asm volatile(
        "mma.sync.aligned.m16n8k16.row.col.f32.f16.f16.f32 "
        "{%0,%1,%2,%3}, {%4,%5,%6,%7}, {%8,%9}, {%0,%1,%2,%3};"
        : "+f"(c[0]), "+f"(c[1]), "+f"(c[2]), "+f"(c[3])
        : "r"(a[0]), "r"(a[1]), "r"(a[2]), "r"(a[3]), "r"(b[0]), "r"(b[1]));
}

__device__ __forceinline__ uint32_t pack_h2(float a, float b) {
    __half2 t = __floats2half2_rn(a, b);
    return *(uint32_t*)&t;
}

__device__ __forceinline__ uint32_t sw128(int r, int c16) {
    return (uint32_t)(r * 128 + ((c16 ^ (r & 7)) << 4));
}
__device__ __forceinline__ uint32_t sw256(int r, int c16) {
    return (uint32_t)(r * 256 + ((c16 ^ (r & 7)) << 4));
}

// ---------------------------------------------------------------------------
// GEMM: fp16, NPROD products on the A side (2 = hi+lo, 1 = hi only).
// CTA 256x128 (8 warps, 64x64 warp tiles), BK=64, 2-stage cp.async.
// stage (NPROD=2): Ahi 32K | Alo 32K | B 16K = 80K
// stage (NPROD=1): Ahi 32K | B 16K          = 48K
// ---------------------------------------------------------------------------
template <int NPROD>
__global__ __launch_bounds__(256, 1)
void gemm_mma_kernel(const __half* __restrict__ Ahi, const __half* __restrict__ Alo,
                     const __half* __restrict__ Bhi,
                     const float* __restrict__ bias, float* __restrict__ C,
                     int M, int N, int K) {
    constexpr uint32_t B_OFF = (NPROD == 2) ? 65536u : 32768u;
    constexpr uint32_t STAGE = B_OFF + 16384u;
    extern __shared__ char smraw[];
    const uint32_t sbase = smem_u32(smraw);
    const int tid = threadIdx.x;
    const int lane = tid & 31;
    const int warp = tid >> 5;
    const int wm = warp >> 1;
    const int wn = warp & 1;

    const int row0 = blockIdx.y * 256;
    const int col0 = blockIdx.x * 128;
    const __half* pAhi = Ahi + (size_t)row0 * K;
    const __half* pAlo = (NPROD == 2) ? (Alo + (size_t)row0 * K) : nullptr;
    const __half* pBhi = Bhi + (size_t)col0 * K;
    const int nk = K / 64;

    auto load_stage = [&](int kc, int st) {
        const int kbase = kc * 64;
        const uint32_t stg = sbase + st * STAGE;
#pragma unroll
        for (int it = 0; it < 8; it++) {
            int idx = tid + it * 256;
            int r = idx >> 3, c = idx & 7;
            CP_ASYNC16(stg + sw128(r, c), pAhi + (size_t)r * K + kbase + c * 8);
            if (NPROD == 2)
                CP_ASYNC16(stg + 32768 + sw128(r, c), pAlo + (size_t)r * K + kbase + c * 8);
        }
#pragma unroll
        for (int it = 0; it < 4; it++) {
            int idx = tid + it * 256;
            int r = idx >> 3, c = idx & 7;
            CP_ASYNC16(stg + B_OFF + sw128(r, c), pBhi + (size_t)r * K + kbase + c * 8);
        }
    };

    float acc[4][8][4];
#pragma unroll
    for (int i = 0; i < 4; i++)
#pragma unroll
        for (int j = 0; j < 8; j++)
#pragma unroll
            for (int k = 0; k < 4; k++) acc[i][j][k] = 0.f;

    load_stage(0, 0); CP_COMMIT();

    for (int kc = 0; kc < nk; kc++) {
        CP_WAIT0();
        __syncthreads();
        if (kc + 1 < nk) {
            load_stage(kc + 1, (kc + 1) & 1);
            CP_COMMIT();
        }

        const uint32_t stg = sbase + (kc & 1) * STAGE;
        const uint32_t sAhi = stg, sAlo = stg + 32768, sBhi = stg + B_OFF;

#pragma unroll
        for (int ks = 0; ks < 4; ks++) {
            const int arow = wm * 64 + (lane & 15);
            const int ac = ks * 2 + (lane >> 4);
            const int brow = wn * 64 + (lane & 7);
            const int bc = ks * 2 + ((lane >> 3) & 1);

            uint32_t ah[4][4], bf[8][2];
#pragma unroll
            for (int mt = 0; mt < 4; mt++)
                LDSM4(ah[mt][0], ah[mt][1], ah[mt][2], ah[mt][3],
                      sAhi + sw128(arow + mt * 16, ac));
#pragma unroll
            for (int nt = 0; nt < 8; nt++)
                LDSM2(bf[nt][0], bf[nt][1], sBhi + sw128(brow + nt * 8, bc));
#pragma unroll
            for (int mt = 0; mt < 4; mt++)
#pragma unroll
                for (int nt = 0; nt < 8; nt++)
                    mma16816h(acc[mt][nt], ah[mt], bf[nt]);

            if (NPROD == 2) {
                uint32_t al[4][4];
#pragma unroll
                for (int mt = 0; mt < 4; mt++)
                    LDSM4(al[mt][0], al[mt][1], al[mt][2], al[mt][3],
                          sAlo + sw128(arow + mt * 16, ac));
#pragma unroll
                for (int mt = 0; mt < 4; mt++)
#pragma unroll
                    for (int nt = 0; nt < 8; nt++)
                        mma16816h(acc[mt][nt], al[mt], bf[nt]);
            }
        }
    }

#pragma unroll
    for (int mt = 0; mt < 4; mt++) {
        int r = row0 + wm * 64 + mt * 16 + (lane >> 2);
#pragma unroll
        for (int nt = 0; nt < 8; nt++) {
            int c = col0 + wn * 64 + nt * 8 + (lane & 3) * 2;
            float b0 = __ldg(bias + c), b1 = __ldg(bias + c + 1);
            *(float2*)(C + (size_t)r * N + c) =
                make_float2(acc[mt][nt][0] + b0, acc[mt][nt][1] + b1);
            *(float2*)(C + (size_t)(r + 8) * N + c) =
                make_float2(acc[mt][nt][2] + b0, acc[mt][nt][3] + b1);
        }
    }
}

#define G2P_SMEM (2 * 81920)
#define G1P_SMEM (2 * 49152)

// ---------------------------------------------------------------------------
// fp32 -> fp16 hi + lo split (activations)
// ---------------------------------------------------------------------------
__global__ __launch_bounds__(256)
void split16_kernel(const float4* __restrict__ x, __half2* __restrict__ hi,
                    __half2* __restrict__ lo, int n4) {
    int i = blockIdx.x * 256 + threadIdx.x;
    if (i >= n4) return;
    float4 v = x[i];
    float h0 = __half2float(__float2half_rn(v.x));
    float h1 = __half2float(__float2half_rn(v.y));
    float h2 = __half2float(__float2half_rn(v.z));
    float h3 = __half2float(__float2half_rn(v.w));
    hi[2 * i] = __floats2half2_rn(v.x, v.y);
    hi[2 * i + 1] = __floats2half2_rn(v.z, v.w);
    lo[2 * i] = __floats2half2_rn(v.x - h0, v.y - h1);
    lo[2 * i + 1] = __floats2half2_rn(v.z - h2, v.w - h3);
}

// fp32 -> fp16 (weights)
__global__ __launch_bounds__(256)
void conv16_kernel(const float4* __restrict__ x, __half2* __restrict__ hi, int n4) {
    int i = blockIdx.x * 256 + threadIdx.x;
    if (i >= n4) return;
    float4 v = x[i];
    hi[2 * i] = __floats2half2_rn(v.x, v.y);
    hi[2 * i + 1] = __floats2half2_rn(v.z, v.w);
}

// ---------------------------------------------------------------------------
// Q prep: fp32 (B,S,HID) -> qhi/qlo fp16 [bh][sdup][vec]
// ---------------------------------------------------------------------------
__global__ __launch_bounds__(256)
void qprep_kernel(const float* __restrict__ q, __half* __restrict__ qhi,
                  __half* __restrict__ qlo) {
    __shared__ float sm[1024];
    int bid = blockIdx.x;
    int d = bid & 3;
    int bs = bid >> 2;
    int b = bs >> 9, s = bs & 511;
    const float* src = q + (size_t)bs * HID + d * 1024;
    int tid = threadIdx.x;
    *(float4*)&sm[tid * 4] = *(const float4*)(src + tid * 4);
    __syncthreads();
    int h = tid >> 4;
    int v = (tid * 4) & 63;
    size_t dst = ((size_t)(b * 16 + h) * SDUP + (s * 4 + d)) * VECD + v;
    float x0 = sm[(v + 0) * 16 + h], x1 = sm[(v + 1) * 16 + h];
    float x2 = sm[(v + 2) * 16 + h], x3 = sm[(v + 3) * 16 + h];
    float h0 = __half2float(__float2half_rn(x0));
    float h1 = __half2float(__float2half_rn(x1));
    float h2 = __half2float(__float2half_rn(x2));
    float h3 = __half2float(__float2half_rn(x3));
    *(__half2*)(qhi + dst) = __floats2half2_rn(x0, x1);
    *(__half2*)(qhi + dst + 2) = __floats2half2_rn(x2, x3);
    *(__half2*)(qlo + dst) = __floats2half2_rn(x0 - h0, x1 - h1);
    *(__half2*)(qlo + dst + 2) = __floats2half2_rn(x2 - h2, x3 - h3);
}

// ---------------------------------------------------------------------------
// KV prep: 4 n-rows per CTA (512 CTAs), 32KB smem
// ---------------------------------------------------------------------------
#define KVP_SMEM (2 * 4 * 1024 * 4)
__global__ __launch_bounds__(256)
void kvprep_kernel(const float* __restrict__ keys, const float* __restrict__ vals,
                   __half* __restrict__ khi, __half* __restrict__ vhi) {
    extern __shared__ float smf[];
    float* sk = smf;
    float* sv = smf + 4 * 1024;
    const int bid = blockIdx.x;
    const int b = bid >> 7, nc = bid & 127;
    const int n0 = nc * 4;
    const int tid = threadIdx.x;

    const float* ksrc = keys + ((size_t)b * NKV + n0) * 1024;
    const float* vsrc = vals + ((size_t)b * NKV + n0) * 1024;
#pragma unroll
    for (int it = 0; it < 4; it++) {
        int i = tid + it * 256;
        *(float4*)&sk[i * 4] = *(const float4*)(ksrc + i * 4);
        *(float4*)&sv[i * 4] = *(const float4*)(vsrc + i * 4);
    }
    __syncthreads();

#pragma unroll
    for (int it = 0; it < 2; it++) {
        int task = tid + it * 256;
        int vg = task & 7, n = (task >> 3) & 3, h = task >> 5;
        uint32_t hhx[4];
#pragma unroll
        for (int j = 0; j < 4; j++) {
            float x0 = sk[n * 1024 + (vg * 8 + j * 2 + 0) * 16 + h];
            float x1 = sk[n * 1024 + (vg * 8 + j * 2 + 1) * 16 + h];
            hhx[j] = pack_h2(x0, x1);
        }
        size_t dst = ((size_t)(b * 16 + h) * NKV + n0 + n) * VECD + vg * 8;
        *(uint4*)(khi + dst) = make_uint4(hhx[0], hhx[1], hhx[2], hhx[3]);
    }

#pragma unroll
    for (int it = 0; it < 4; it++) {
        int task = tid + it * 256;
        int v = task & 63, h = task >> 6;
        uint32_t p0 = pack_h2(sv[0 * 1024 + v * 16 + h], sv[1 * 1024 + v * 16 + h]);
        uint32_t p1 = pack_h2(sv[2 * 1024 + v * 16 + h], sv[3 * 1024 + v * 16 + h]);
        size_t dst = ((size_t)(b * 16 + h) * VECD + v) * NKV + n0;
        *(uint2*)(vhi + dst) = make_uint2(p0, p1);
    }
}

// ---------------------------------------------------------------------------
// Flash attention (unchanged)
// ---------------------------------------------------------------------------
#define ATT_SMEM (6 * 16384)
__global__ __launch_bounds__(256)
void attn_mma_kernel(const __half* __restrict__ qhi, const __half* __restrict__ qlo,
                     const __half* __restrict__ khi, const __half* __restrict__ vhi,
                     float* __restrict__ outT) {
    extern __shared__ char smraw[];
    const uint32_t sQhi = smem_u32(smraw);
    const uint32_t sQlo = sQhi + 16384;
    const uint32_t sKV = sQhi + 32768;

    const int tid = threadIdx.x;
    const int lane = tid & 31;
    const int warp = tid >> 5;
    const int g = lane >> 2;
    const int tq = lane & 3;
    const int bh = blockIdx.y;
    const int tile = blockIdx.x;
    const int wrow0 = warp * 16;

    const __half* qh = qhi + ((size_t)bh * SDUP + tile * 128) * VECD;
    const __half* ql = qlo + ((size_t)bh * SDUP + tile * 128) * VECD;
    const __half* kh = khi + (size_t)bh * NKV * VECD;
    const __half* vh = vhi + (size_t)bh * VECD * NKV;

    auto load_kv = [&](int ck, int buf) {
        const int n0 = ck * 128;
        const uint32_t sK = sKV + buf * 32768;
        const uint32_t sV = sK + 16384;
#pragma unroll
        for (int it = 0; it < 4; it++) {
            int idx = tid + it * 256;
            int r = idx >> 3, c = idx & 7;
            CP_ASYNC16(sK + sw128(r, c), kh + (size_t)(n0 + r) * VECD + c * 8);
            int v = idx >> 4, cc = idx & 15;
            CP_ASYNC16(sV + sw256(v, cc), vh + (size_t)v * NKV + n0 + cc * 8);
        }
    };

#pragma unroll
    for (int it = 0; it < 4; it++) {
        int idx = tid + it * 256;
        int r = idx >> 3, c = idx & 7;
        CP_ASYNC16(sQhi + sw128(r, c), qh + (size_t)r * VECD + c * 8);
        CP_ASYNC16(sQlo + sw128(r, c), ql + (size_t)r * VECD + c * 8);
    }
    load_kv(0, 0);
    CP_COMMIT();

    float oa[8][4];
#pragma unroll
    for (int i = 0; i < 8; i++)
#pragma unroll
        for (int j = 0; j < 4; j++) oa[i][j] = 0.f;
    float m0 = -1e30f, m1 = -1e30f, l0 = 0.f, l1 = 0.f;

    for (int ck = 0; ck < 4; ck++) {
        CP_WAIT0();
        __syncthreads();
        if (ck < 3) {
            load_kv(ck + 1, (ck + 1) & 1);
            CP_COMMIT();
        }
        const uint32_t sK = sKV + (ck & 1) * 32768;
        const uint32_t sV = sK + 16384;

        float S[16][4];
#pragma unroll
        for (int jt = 0; jt < 16; jt++)
#pragma unroll
            for (int j = 0; j < 4; j++) S[jt][j] = 0.f;

#pragma unroll
        for (int ks = 0; ks < 4; ks++) {
            uint32_t ah[4], al[4];
            int arow = wrow0 + (lane & 15);
            int ac = ks * 2 + (lane >> 4);
            uint32_t qoff = sw128(arow, ac);
            LDSM4(ah[0], ah[1], ah[2], ah[3], sQhi + qoff);
            LDSM4(al[0], al[1], al[2], al[3], sQlo + qoff);
#pragma unroll
            for (int jt = 0; jt < 16; jt++) {
                int brow = jt * 8 + (lane & 7);
                int bc = ks * 2 + ((lane >> 3) & 1);
                uint32_t b2[2];
                LDSM2(b2[0], b2[1], sK + sw128(brow, bc));
                mma16816h(S[jt], ah, b2);
                mma16816h(S[jt], al, b2);
            }
        }

        float cm0 = -1e30f, cm1 = -1e30f;
#pragma unroll
        for (int jt = 0; jt < 16; jt++) {
            S[jt][0] *= 0.125f; S[jt][1] *= 0.125f;
            S[jt][2] *= 0.125f; S[jt][3] *= 0.125f;
            cm0 = fmaxf(cm0, fmaxf(S[jt][0], S[jt][1]));
            cm1 = fmaxf(cm1, fmaxf(S[jt][2], S[jt][3]));
        }
        cm0 = fmaxf(cm0, __shfl_xor_sync(0xffffffffu, cm0, 1));
        cm0 = fmaxf(cm0, __shfl_xor_sync(0xffffffffu, cm0, 2));
        cm1 = fmaxf(cm1, __shfl_xor_sync(0xffffffffu, cm1, 1));
        cm1 = fmaxf(cm1, __shfl_xor_sync(0xffffffffu, cm1, 2));
        float mn0 = fmaxf(m0, cm0), mn1 = fmaxf(m1, cm1);
        float sc0 = __expf(m0 - mn0), sc1 = __expf(m1 - mn1);
        m0 = mn0; m1 = mn1;
        l0 *= sc0; l1 *= sc1;
#pragma unroll
        for (int vt = 0; vt < 8; vt++) {
            oa[vt][0] *= sc0; oa[vt][1] *= sc0;
            oa[vt][2] *= sc1; oa[vt][3] *= sc1;
        }

        float cs0 = 0.f, cs1 = 0.f;
#pragma unroll
        for (int ks = 0; ks < 8; ks++) {
            uint32_t pah[4], pal[4];
#pragma unroll
            for (int half = 0; half < 2; half++) {
                int jt = ks * 2 + half;
                float p0 = __expf(S[jt][0] - m0);
                float p1 = __expf(S[jt][1] - m0);
                float p2 = __expf(S[jt][2] - m1);
                float p3 = __expf(S[jt][3] - m1);
                cs0 += p0 + p1;
                cs1 += p2 + p3;
                float h0 = __half2float(__float2half_rn(p0));
                float h1 = __half2float(__float2half_rn(p1));
                float h2 = __half2float(__float2half_rn(p2));
                float h3 = __half2float(__float2half_rn(p3));
                pah[half * 2 + 0] = pack_h2(h0, h1);
                pah[half * 2 + 1] = pack_h2(h2, h3);
                pal[half * 2 + 0] = pack_h2(p0 - h0, p1 - h1);
                pal[half * 2 + 1] = pack_h2(p2 - h2, p3 - h3);
            }
#pragma unroll
            for (int vt = 0; vt < 8; vt++) {
                int brow = vt * 8 + (lane & 7);
                int bc = ks * 2 + ((lane >> 3) & 1);
                uint32_t b2[2];
                LDSM2(b2[0], b2[1], sV + sw256(brow, bc));
                mma16816h(oa[vt], pah, b2);
                mma16816h(oa[vt], pal, b2);
            }
        }
        cs0 += __shfl_xor_sync(0xffffffffu, cs0, 1);
        cs0 += __shfl_xor_sync(0xffffffffu, cs0, 2);
        cs1 += __shfl_xor_sync(0xffffffffu, cs1, 1);
        cs1 += __shfl_xor_sync(0xffffffffu, cs1, 2);
        l0 += cs0; l1 += cs1;
    }

    float inv0 = 1.f / l0, inv1 = 1.f / l1;
    float* orow0 = outT + ((size_t)bh * SDUP + tile * 128 + wrow0 + g) * VECD;
    float* orow1 = orow0 + 8 * VECD;
#pragma unroll
    for (int vt = 0; vt < 8; vt++) {
        int v = vt * 8 + tq * 2;
        *(float2*)(orow0 + v) = make_float2(oa[vt][0] * inv0, oa[vt][1] * inv0);
        *(float2*)(orow1 + v) = make_float2(oa[vt][2] * inv1, oa[vt][3] * inv1);
    }
}

// ---------------------------------------------------------------------------
// LayerNorm gather -> fp16 (hi only; GEMM2 is 1-product)
// ---------------------------------------------------------------------------
__global__ __launch_bounds__(256)
void ln_gather_kernel(const float* __restrict__ attnT, const float* __restrict__ gam,
                      const float* __restrict__ bet, __half* __restrict__ hi) {
    __shared__ float xs[HID];
    __shared__ float red[8];
    __shared__ float red2[8];
    const int row = blockIdx.x;
    const int b = row >> 9, s = row & 511;
    const int tid = threadIdx.x;
    const int lane = tid & 31, w = tid >> 5;

    float lsum = 0.f;
#pragma unroll
    for (int it = 0; it < 4; it++) {
        int i = it * 1024 + tid * 4;
        int h = i >> 8, d = (i >> 6) & 3, v = i & 63;
        const float* src = attnT + ((size_t)(b * 16 + h) * SDUP + (s * 4 + d)) * VECD + v;
        float4 x = *(const float4*)src;
        *(float4*)&xs[i] = x;
        lsum += x.x + x.y + x.z + x.w;
    }
#pragma unroll
    for (int o = 16; o > 0; o >>= 1) lsum += __shfl_xor_sync(0xffffffffu, lsum, o);
    if (lane == 0) red[w] = lsum;
    __syncthreads();
    float tot = 0.f;
#pragma unroll
    for (int j = 0; j < 8; j++) tot += red[j];
    float mu = tot * (1.f / HID);

    float lv = 0.f;
    for (int i = tid; i < HID; i += 256) {
        float d = xs[i] - mu;
        lv += d * d;
    }
#pragma unroll
    for (int o = 16; o > 0; o >>= 1) lv += __shfl_xor_sync(0xffffffffu, lv, o);
    if (lane == 0) red2[w] = lv;
    __syncthreads();
    float tv = 0.f;
#pragma unroll
    for (int j = 0; j < 8; j++) tv += red2[j];
    float inv = rsqrtf(tv * (1.f / HID) + 1e-12f);

#pragma unroll
    for (int it = 0; it < 4; it++) {
        int i = it * 1024 + tid * 4;
        float4 xv = *(const float4*)&xs[i];
        float4 gv = *(const float4*)&gam[i];
        float4 bv = *(const float4*)&bet[i];
        float y0 = (xv.x - mu) * inv * gv.x + bv.x;
        float y1 = (xv.y - mu) * inv * gv.y + bv.y;
        float y2 = (xv.z - mu) * inv * gv.z + bv.z;
        float y3 = (xv.w - mu) * inv * gv.w + bv.w;
        size_t o = (size_t)row * HID + i;
        *(__half2*)(hi + o) = __floats2half2_rn(y0, y1);
        *(__half2*)(hi + o + 2) = __floats2half2_rn(y2, y3);
    }
}

// ---------------------------------------------------------------------------
extern "C" void kernel_launch(void* const* d_in, const int* in_sizes, int n_in,
                              void* d_out, int out_size) {
    const float* emb  = (const float*)d_in[0];
    const float* keys = (const float*)d_in[1];
    const float* vals = (const float*)d_in[2];
    const float* Wq   = (const float*)d_in[3];
    const float* bq   = (const float*)d_in[4];
    const float* Wre  = (const float*)d_in[5];
    const float* bre  = (const float*)d_in[6];
    const float* ln_g = (const float*)d_in[7];
    const float* ln_b = (const float*)d_in[8];
    float* out = (float*)d_out;

    float *qbuf, *aT;
    __half *ehi, *elo, *lnhi, *wqhi, *wrehi;
    __half *qhi, *qlo, *khi, *vhi;
    cudaGetSymbolAddress((void**)&qbuf, g_q);
    cudaGetSymbolAddress((void**)&aT, g_attnT);
    cudaGetSymbolAddress((void**)&ehi, g_ehi);
    cudaGetSymbolAddress((void**)&elo, g_elo);
    cudaGetSymbolAddress((void**)&lnhi, g_lnhi);
    cudaGetSymbolAddress((void**)&wqhi, g_wqhi);
    cudaGetSymbolAddress((void**)&wrehi, g_wrehi);
    cudaGetSymbolAddress((void**)&qhi, g_qhi);
    cudaGetSymbolAddress((void**)&qlo, g_qlo);
    cudaGetSymbolAddress((void**)&khi, g_khi);
    cudaGetSymbolAddress((void**)&vhi, g_vhi);

    cudaFuncSetAttribute(gemm_mma_kernel<2>, cudaFuncAttributeMaxDynamicSharedMemorySize, G2P_SMEM);
    cudaFuncSetAttribute(gemm_mma_kernel<1>, cudaFuncAttributeMaxDynamicSharedMemorySize, G1P_SMEM);
    cudaFuncSetAttribute(attn_mma_kernel, cudaFuncAttributeMaxDynamicSharedMemorySize, ATT_SMEM);
    cudaFuncSetAttribute(kvprep_kernel, cudaFuncAttributeMaxDynamicSharedMemorySize, KVP_SMEM);

    static cudaStream_t sA = nullptr, sB = nullptr;
    static cudaEvent_t evRoot = nullptr, evKV = nullptr, evWq = nullptr, evWre = nullptr;
    if (sA == nullptr) {
        cudaStreamCreateWithFlags(&sA, cudaStreamNonBlocking);
        cudaStreamCreateWithFlags(&sB, cudaStreamNonBlocking);
        cudaEventCreateWithFlags(&evRoot, cudaEventDisableTiming);
        cudaEventCreateWithFlags(&evKV, cudaEventDisableTiming);
        cudaEventCreateWithFlags(&evWq, cudaEventDisableTiming);
        cudaEventCreateWithFlags(&evWre, cudaEventDisableTiming);
    }

    cudaEventRecord(evRoot, 0);
    cudaStreamWaitEvent(sA, evRoot, 0);
    cudaStreamWaitEvent(sB, evRoot, 0);

    kvprep_kernel<<<4 * 128, 256, KVP_SMEM, sA>>>(keys, vals, khi, vhi);
    cudaEventRecord(evKV, sA);

    conv16_kernel<<<(HID * HID / 4 + 255) / 256, 256, 0, sB>>>(
        (const float4*)Wq, (__half2*)wqhi, HID * HID / 4);
    cudaEventRecord(evWq, sB);
    conv16_kernel<<<(HID * HID / 4 + 255) / 256, 256, 0, sB>>>(
        (const float4*)Wre, (__half2*)wrehi, HID * HID / 4);
    cudaEventRecord(evWre, sB);

    split16_kernel<<<(MROWS * HID / 4 + 255) / 256, 256>>>((const float4*)emb,
        (__half2*)ehi, (__half2*)elo, MROWS * HID / 4);

    cudaStreamWaitEvent(0, evWq, 0);
    gemm_mma_kernel<2><<<dim3(HID / 128, MROWS / 256), 256, G2P_SMEM>>>(
        ehi, elo, wqhi, bq, qbuf, MROWS, HID, HID);
    qprep_kernel<<<MROWS * 4, 256>>>(qbuf, qhi, qlo);

    cudaStreamWaitEvent(0, evKV, 0);
    attn_mma_kernel<<<dim3(16, 64), 256, ATT_SMEM>>>(qhi, qlo, khi, vhi, aT);
    ln_gather_kernel<<<MROWS, 256>>>(aT, ln_g, ln_b, lnhi);

    cudaStreamWaitEvent(0, evWre, 0);
    gemm_mma_kernel<1><<<dim3(HID / 128, MROWS / 256), 256, G1P_SMEM>>>(
        lnhi, nullptr, wrehi, bre, out, MROWS, HID, HID);
}

// round 11
// speedup vs baseline: 2.3758x; 1.2533x over previous
#include <cuda_runtime.h>
#include <cuda_fp16.h>
#include <cstdint>

#define HID 4096
#define MROWS 2048
#define NKV 512
#define VECD 64
#define NHEAD 16
#define NBH 64
#define SDUP 2048

// ---------------- scratch ----------------
__device__ float g_q[MROWS * HID];
__device__ float g_attnT[NBH * SDUP * VECD];
__device__ __half g_qhi[NBH * SDUP * VECD], g_qlo[NBH * SDUP * VECD];
__device__ __half g_khi[NBH * NKV * VECD];
__device__ __half g_vhi[NBH * VECD * NKV];
__device__ __half g_ehi[MROWS * HID];
__device__ __half g_lnhi[MROWS * HID];
__device__ __half g_wqhi[HID * HID];
__device__ __half g_wrehi[HID * HID];

// ---------------- PTX helpers ----------------
__device__ __forceinline__ uint32_t smem_u32(const void* p) {
    uint32_t a;
    asm("{ .reg .u64 t; cvta.to.shared.u64 t, %1; cvt.u32.u64 %0, t; }" : "=r"(a) : "l"(p));
    return a;
}
#define CP_ASYNC16(dst, src) \
    asm volatile("cp.async.cg.shared.global [%0], [%1], 16;" :: "r"(dst), "l"(src))
#define CP_COMMIT() asm volatile("cp.async.commit_group;" ::: "memory")
#define CP_WAIT0()  asm volatile("cp.async.wait_group 0;" ::: "memory")

#define LDSM4(r0, r1, r2, r3, addr)                                          \
    asm volatile("ldmatrix.sync.aligned.m8n8.x4.shared.b16 {%0,%1,%2,%3}, [%4];" \
                 : "=r"(r0), "=r"(r1), "=r"(r2), "=r"(r3) : "r"(addr))
#define LDSM2(r0, r1, addr)                                                  \
    asm volatile("ldmatrix.sync.aligned.m8n8.x2.shared.b16 {%0,%1}, [%2];"   \
                 : "=r"(r0), "=r"(r1) : "r"(addr))

__device__ __forceinline__ void mma16816h(float* c, const uint32_t* a, const uint32_t* b) {
    asm volatile(
        "mma.sync.aligned.m16n8k16.row.col.f32.f16.f16.f32 "
        "{%0,%1,%2,%3}, {%4,%5,%6,%7}, {%8,%9}, {%0,%1,%2,%3};"
        : "+f"(c[0]), "+f"(c[1]), "+f"(c[2]), "+f"(c[3])
        : "r"(a[0]), "r"(a[1]), "r"(a[2]), "r"(a[3]), "r"(b[0]), "r"(b[1]));
}

__device__ __forceinline__ uint32_t pack_h2(float a, float b) {
    __half2 t = __floats2half2_rn(a, b);
    return *(uint32_t*)&t;
}

__device__ __forceinline__ uint32_t sw128(int r, int c16) {
    return (uint32_t)(r * 128 + ((c16 ^ (r & 7)) << 4));
}
__device__ __forceinline__ uint32_t sw256(int r, int c16) {
    return (uint32_t)(r * 256 + ((c16 ^ (r & 7)) << 4));
}

// ---------------------------------------------------------------------------
// GEMM: fp16 1-product. C[M,N] = Ahi[M,K] @ Bhi[N,K]^T + bias
// CTA 256x128 (8 warps, 64x64 warp tiles), BK=64, 2-stage cp.async.
// stage: Ahi 32K | B 16K = 48K; 2 stages = 96K
// ---------------------------------------------------------------------------
#define G1P_STAGE 49152
#define G1P_SMEM (2 * G1P_STAGE)
__global__ __launch_bounds__(256, 1)
void gemm_mma_kernel(const __half* __restrict__ Ahi, const __half* __restrict__ Bhi,
                     const float* __restrict__ bias, float* __restrict__ C,
                     int M, int N, int K) {
    extern __shared__ char smraw[];
    const uint32_t sbase = smem_u32(smraw);
    const int tid = threadIdx.x;
    const int lane = tid & 31;
    const int warp = tid >> 5;
    const int wm = warp >> 1;
    const int wn = warp & 1;

    const int row0 = blockIdx.y * 256;
    const int col0 = blockIdx.x * 128;
    const __half* pAhi = Ahi + (size_t)row0 * K;
    const __half* pBhi = Bhi + (size_t)col0 * K;
    const int nk = K / 64;

    auto load_stage = [&](int kc, int st) {
        const int kbase = kc * 64;
        const uint32_t stg = sbase + st * G1P_STAGE;
#pragma unroll
        for (int it = 0; it < 8; it++) {
            int idx = tid + it * 256;
            int r = idx >> 3, c = idx & 7;
            CP_ASYNC16(stg + sw128(r, c), pAhi + (size_t)r * K + kbase + c * 8);
        }
#pragma unroll
        for (int it = 0; it < 4; it++) {
            int idx = tid + it * 256;
            int r = idx >> 3, c = idx & 7;
            CP_ASYNC16(stg + 32768 + sw128(r, c), pBhi + (size_t)r * K + kbase + c * 8);
        }
    };

    float acc[4][8][4];
#pragma unroll
    for (int i = 0; i < 4; i++)
#pragma unroll
        for (int j = 0; j < 8; j++)
#pragma unroll
            for (int k = 0; k < 4; k++) acc[i][j][k] = 0.f;

    load_stage(0, 0); CP_COMMIT();

    for (int kc = 0; kc < nk; kc++) {
        CP_WAIT0();
        __syncthreads();
        if (kc + 1 < nk) {
            load_stage(kc + 1, (kc + 1) & 1);
            CP_COMMIT();
        }

        const uint32_t stg = sbase + (kc & 1) * G1P_STAGE;
        const uint32_t sAhi = stg, sBhi = stg + 32768;

#pragma unroll
        for (int ks = 0; ks < 4; ks++) {
            const int arow = wm * 64 + (lane & 15);
            const int ac = ks * 2 + (lane >> 4);
            const int brow = wn * 64 + (lane & 7);
            const int bc = ks * 2 + ((lane >> 3) & 1);

            uint32_t ah[4][4], bf[8][2];
#pragma unroll
            for (int mt = 0; mt < 4; mt++)
                LDSM4(ah[mt][0], ah[mt][1], ah[mt][2], ah[mt][3],
                      sAhi + sw128(arow + mt * 16, ac));
#pragma unroll
            for (int nt = 0; nt < 8; nt++)
                LDSM2(bf[nt][0], bf[nt][1], sBhi + sw128(brow + nt * 8, bc));
#pragma unroll
            for (int mt = 0; mt < 4; mt++)
#pragma unroll
                for (int nt = 0; nt < 8; nt++)
                    mma16816h(acc[mt][nt], ah[mt], bf[nt]);
        }
    }

#pragma unroll
    for (int mt = 0; mt < 4; mt++) {
        int r = row0 + wm * 64 + mt * 16 + (lane >> 2);
#pragma unroll
        for (int nt = 0; nt < 8; nt++) {
            int c = col0 + wn * 64 + nt * 8 + (lane & 3) * 2;
            float b0 = __ldg(bias + c), b1 = __ldg(bias + c + 1);
            *(float2*)(C + (size_t)r * N + c) =
                make_float2(acc[mt][nt][0] + b0, acc[mt][nt][1] + b1);
            *(float2*)(C + (size_t)(r + 8) * N + c) =
                make_float2(acc[mt][nt][2] + b0, acc[mt][nt][3] + b1);
        }
    }
}

// ---------------------------------------------------------------------------
// fp32 -> fp16 convert
// ---------------------------------------------------------------------------
__global__ __launch_bounds__(256)
void conv16_kernel(const float4* __restrict__ x, __half2* __restrict__ hi, int n4) {
    int i = blockIdx.x * 256 + threadIdx.x;
    if (i >= n4) return;
    float4 v = x[i];
    hi[2 * i] = __floats2half2_rn(v.x, v.y);
    hi[2 * i + 1] = __floats2half2_rn(v.z, v.w);
}

// ---------------------------------------------------------------------------
// Q prep: fp32 (B,S,HID) -> qhi/qlo fp16 [bh][sdup][vec]
// ---------------------------------------------------------------------------
__global__ __launch_bounds__(256)
void qprep_kernel(const float* __restrict__ q, __half* __restrict__ qhi,
                  __half* __restrict__ qlo) {
    __shared__ float sm[1024];
    int bid = blockIdx.x;
    int d = bid & 3;
    int bs = bid >> 2;
    int b = bs >> 9, s = bs & 511;
    const float* src = q + (size_t)bs * HID + d * 1024;
    int tid = threadIdx.x;
    *(float4*)&sm[tid * 4] = *(const float4*)(src + tid * 4);
    __syncthreads();
    int h = tid >> 4;
    int v = (tid * 4) & 63;
    size_t dst = ((size_t)(b * 16 + h) * SDUP + (s * 4 + d)) * VECD + v;
    float x0 = sm[(v + 0) * 16 + h], x1 = sm[(v + 1) * 16 + h];
    float x2 = sm[(v + 2) * 16 + h], x3 = sm[(v + 3) * 16 + h];
    float h0 = __half2float(__float2half_rn(x0));
    float h1 = __half2float(__float2half_rn(x1));
    float h2 = __half2float(__float2half_rn(x2));
    float h3 = __half2float(__float2half_rn(x3));
    *(__half2*)(qhi + dst) = __floats2half2_rn(x0, x1);
    *(__half2*)(qhi + dst + 2) = __floats2half2_rn(x2, x3);
    *(__half2*)(qlo + dst) = __floats2half2_rn(x0 - h0, x1 - h1);
    *(__half2*)(qlo + dst + 2) = __floats2half2_rn(x2 - h2, x3 - h3);
}

// ---------------------------------------------------------------------------
// KV prep: 4 n-rows per CTA (512 CTAs), 32KB smem
// ---------------------------------------------------------------------------
#define KVP_SMEM (2 * 4 * 1024 * 4)
__global__ __launch_bounds__(256)
void kvprep_kernel(const float* __restrict__ keys, const float* __restrict__ vals,
                   __half* __restrict__ khi, __half* __restrict__ vhi) {
    extern __shared__ float smf[];
    float* sk = smf;
    float* sv = smf + 4 * 1024;
    const int bid = blockIdx.x;
    const int b = bid >> 7, nc = bid & 127;
    const int n0 = nc * 4;
    const int tid = threadIdx.x;

    const float* ksrc = keys + ((size_t)b * NKV + n0) * 1024;
    const float* vsrc = vals + ((size_t)b * NKV + n0) * 1024;
#pragma unroll
    for (int it = 0; it < 4; it++) {
        int i = tid + it * 256;
        *(float4*)&sk[i * 4] = *(const float4*)(ksrc + i * 4);
        *(float4*)&sv[i * 4] = *(const float4*)(vsrc + i * 4);
    }
    __syncthreads();

#pragma unroll
    for (int it = 0; it < 2; it++) {
        int task = tid + it * 256;
        int vg = task & 7, n = (task >> 3) & 3, h = task >> 5;
        uint32_t hhx[4];
#pragma unroll
        for (int j = 0; j < 4; j++) {
            float x0 = sk[n * 1024 + (vg * 8 + j * 2 + 0) * 16 + h];
            float x1 = sk[n * 1024 + (vg * 8 + j * 2 + 1) * 16 + h];
            hhx[j] = pack_h2(x0, x1);
        }
        size_t dst = ((size_t)(b * 16 + h) * NKV + n0 + n) * VECD + vg * 8;
        *(uint4*)(khi + dst) = make_uint4(hhx[0], hhx[1], hhx[2], hhx[3]);
    }

#pragma unroll
    for (int it = 0; it < 4; it++) {
        int task = tid + it * 256;
        int v = task & 63, h = task >> 6;
        uint32_t p0 = pack_h2(sv[0 * 1024 + v * 16 + h], sv[1 * 1024 + v * 16 + h]);
        uint32_t p1 = pack_h2(sv[2 * 1024 + v * 16 + h], sv[3 * 1024 + v * 16 + h]);
        size_t dst = ((size_t)(b * 16 + h) * VECD + v) * NKV + n0;
        *(uint2*)(vhi + dst) = make_uint2(p0, p1);
    }
}

// ---------------------------------------------------------------------------
// Flash attention (unchanged)
// ---------------------------------------------------------------------------
#define ATT_SMEM (6 * 16384)
__global__ __launch_bounds__(256)
void attn_mma_kernel(const __half* __restrict__ qhi, const __half* __restrict__ qlo,
                     const __half* __restrict__ khi, const __half* __restrict__ vhi,
                     float* __restrict__ outT) {
    extern __shared__ char smraw[];
    const uint32_t sQhi = smem_u32(smraw);
    const uint32_t sQlo = sQhi + 16384;
    const uint32_t sKV = sQhi + 32768;

    const int tid = threadIdx.x;
    const int lane = tid & 31;
    const int warp = tid >> 5;
    const int g = lane >> 2;
    const int tq = lane & 3;
    const int bh = blockIdx.y;
    const int tile = blockIdx.x;
    const int wrow0 = warp * 16;

    const __half* qh = qhi + ((size_t)bh * SDUP + tile * 128) * VECD;
    const __half* ql = qlo + ((size_t)bh * SDUP + tile * 128) * VECD;
    const __half* kh = khi + (size_t)bh * NKV * VECD;
    const __half* vh = vhi + (size_t)bh * VECD * NKV;

    auto load_kv = [&](int ck, int buf) {
        const int n0 = ck * 128;
        const uint32_t sK = sKV + buf * 32768;
        const uint32_t sV = sK + 16384;
#pragma unroll
        for (int it = 0; it < 4; it++) {
            int idx = tid + it * 256;
            int r = idx >> 3, c = idx & 7;
            CP_ASYNC16(sK + sw128(r, c), kh + (size_t)(n0 + r) * VECD + c * 8);
            int v = idx >> 4, cc = idx & 15;
            CP_ASYNC16(sV + sw256(v, cc), vh + (size_t)v * NKV + n0 + cc * 8);
        }
    };

#pragma unroll
    for (int it = 0; it < 4; it++) {
        int idx = tid + it * 256;
        int r = idx >> 3, c = idx & 7;
        CP_ASYNC16(sQhi + sw128(r, c), qh + (size_t)r * VECD + c * 8);
        CP_ASYNC16(sQlo + sw128(r, c), ql + (size_t)r * VECD + c * 8);
    }
    load_kv(0, 0);
    CP_COMMIT();

    float oa[8][4];
#pragma unroll
    for (int i = 0; i < 8; i++)
#pragma unroll
        for (int j = 0; j < 4; j++) oa[i][j] = 0.f;
    float m0 = -1e30f, m1 = -1e30f, l0 = 0.f, l1 = 0.f;

    for (int ck = 0; ck < 4; ck++) {
        CP_WAIT0();
        __syncthreads();
        if (ck < 3) {
            load_kv(ck + 1, (ck + 1) & 1);
            CP_COMMIT();
        }
        const uint32_t sK = sKV + (ck & 1) * 32768;
        const uint32_t sV = sK + 16384;

        float S[16][4];
#pragma unroll
        for (int jt = 0; jt < 16; jt++)
#pragma unroll
            for (int j = 0; j < 4; j++) S[jt][j] = 0.f;

#pragma unroll
        for (int ks = 0; ks < 4; ks++) {
            uint32_t ah[4], al[4];
            int arow = wrow0 + (lane & 15);
            int ac = ks * 2 + (lane >> 4);
            uint32_t qoff = sw128(arow, ac);
            LDSM4(ah[0], ah[1], ah[2], ah[3], sQhi + qoff);
            LDSM4(al[0], al[1], al[2], al[3], sQlo + qoff);
#pragma unroll
            for (int jt = 0; jt < 16; jt++) {
                int brow = jt * 8 + (lane & 7);
                int bc = ks * 2 + ((lane >> 3) & 1);
                uint32_t b2[2];
                LDSM2(b2[0], b2[1], sK + sw128(brow, bc));
                mma16816h(S[jt], ah, b2);
                mma16816h(S[jt], al, b2);
            }
        }

        float cm0 = -1e30f, cm1 = -1e30f;
#pragma unroll
        for (int jt = 0; jt < 16; jt++) {
            S[jt][0] *= 0.125f; S[jt][1] *= 0.125f;
            S[jt][2] *= 0.125f; S[jt][3] *= 0.125f;
            cm0 = fmaxf(cm0, fmaxf(S[jt][0], S[jt][1]));
            cm1 = fmaxf(cm1, fmaxf(S[jt][2], S[jt][3]));
        }
        cm0 = fmaxf(cm0, __shfl_xor_sync(0xffffffffu, cm0, 1));
        cm0 = fmaxf(cm0, __shfl_xor_sync(0xffffffffu, cm0, 2));
        cm1 = fmaxf(cm1, __shfl_xor_sync(0xffffffffu, cm1, 1));
        cm1 = fmaxf(cm1, __shfl_xor_sync(0xffffffffu, cm1, 2));
        float mn0 = fmaxf(m0, cm0), mn1 = fmaxf(m1, cm1);
        float sc0 = __expf(m0 - mn0), sc1 = __expf(m1 - mn1);
        m0 = mn0; m1 = mn1;
        l0 *= sc0; l1 *= sc1;
#pragma unroll
        for (int vt = 0; vt < 8; vt++) {
            oa[vt][0] *= sc0; oa[vt][1] *= sc0;
            oa[vt][2] *= sc1; oa[vt][3] *= sc1;
        }

        float cs0 = 0.f, cs1 = 0.f;
#pragma unroll
        for (int ks = 0; ks < 8; ks++) {
            uint32_t pah[4], pal[4];
#pragma unroll
            for (int half = 0; half < 2; half++) {
                int jt = ks * 2 + half;
                float p0 = __expf(S[jt][0] - m0);
                float p1 = __expf(S[jt][1] - m0);
                float p2 = __expf(S[jt][2] - m1);
                float p3 = __expf(S[jt][3] - m1);
                cs0 += p0 + p1;
                cs1 += p2 + p3;
                float h0 = __half2float(__float2half_rn(p0));
                float h1 = __half2float(__float2half_rn(p1));
                float h2 = __half2float(__float2half_rn(p2));
                float h3 = __half2float(__float2half_rn(p3));
                pah[half * 2 + 0] = pack_h2(h0, h1);
                pah[half * 2 + 1] = pack_h2(h2, h3);
                pal[half * 2 + 0] = pack_h2(p0 - h0, p1 - h1);
                pal[half * 2 + 1] = pack_h2(p2 - h2, p3 - h3);
            }
#pragma unroll
            for (int vt = 0; vt < 8; vt++) {
                int brow = vt * 8 + (lane & 7);
                int bc = ks * 2 + ((lane >> 3) & 1);
                uint32_t b2[2];
                LDSM2(b2[0], b2[1], sV + sw256(brow, bc));
                mma16816h(oa[vt], pah, b2);
                mma16816h(oa[vt], pal, b2);
            }
        }
        cs0 += __shfl_xor_sync(0xffffffffu, cs0, 1);
        cs0 += __shfl_xor_sync(0xffffffffu, cs0, 2);
        cs1 += __shfl_xor_sync(0xffffffffu, cs1, 1);
        cs1 += __shfl_xor_sync(0xffffffffu, cs1, 2);
        l0 += cs0; l1 += cs1;
    }

    float inv0 = 1.f / l0, inv1 = 1.f / l1;
    float* orow0 = outT + ((size_t)bh * SDUP + tile * 128 + wrow0 + g) * VECD;
    float* orow1 = orow0 + 8 * VECD;
#pragma unroll
    for (int vt = 0; vt < 8; vt++) {
        int v = vt * 8 + tq * 2;
        *(float2*)(orow0 + v) = make_float2(oa[vt][0] * inv0, oa[vt][1] * inv0);
        *(float2*)(orow1 + v) = make_float2(oa[vt][2] * inv1, oa[vt][3] * inv1);
    }
}

// ---------------------------------------------------------------------------
// LayerNorm gather -> fp16 (hi only)
// ---------------------------------------------------------------------------
__global__ __launch_bounds__(256)
void ln_gather_kernel(const float* __restrict__ attnT, const float* __restrict__ gam,
                      const float* __restrict__ bet, __half* __restrict__ hi) {
    __shared__ float xs[HID];
    __shared__ float red[8];
    __shared__ float red2[8];
    const int row = blockIdx.x;
    const int b = row >> 9, s = row & 511;
    const int tid = threadIdx.x;
    const int lane = tid & 31, w = tid >> 5;

    float lsum = 0.f;
#pragma unroll
    for (int it = 0; it < 4; it++) {
        int i = it * 1024 + tid * 4;
        int h = i >> 8, d = (i >> 6) & 3, v = i & 63;
        const float* src = attnT + ((size_t)(b * 16 + h) * SDUP + (s * 4 + d)) * VECD + v;
        float4 x = *(const float4*)src;
        *(float4*)&xs[i] = x;
        lsum += x.x + x.y + x.z + x.w;
    }
#pragma unroll
    for (int o = 16; o > 0; o >>= 1) lsum += __shfl_xor_sync(0xffffffffu, lsum, o);
    if (lane == 0) red[w] = lsum;
    __syncthreads();
    float tot = 0.f;
#pragma unroll
    for (int j = 0; j < 8; j++) tot += red[j];
    float mu = tot * (1.f / HID);

    float lv = 0.f;
    for (int i = tid; i < HID; i += 256) {
        float d = xs[i] - mu;
        lv += d * d;
    }
#pragma unroll
    for (int o = 16; o > 0; o >>= 1) lv += __shfl_xor_sync(0xffffffffu, lv, o);
    if (lane == 0) red2[w] = lv;
    __syncthreads();
    float tv = 0.f;
#pragma unroll
    for (int j = 0; j < 8; j++) tv += red2[j];
    float inv = rsqrtf(tv * (1.f / HID) + 1e-12f);

#pragma unroll
    for (int it = 0; it < 4; it++) {
        int i = it * 1024 + tid * 4;
        float4 xv = *(const float4*)&xs[i];
        float4 gv = *(const float4*)&gam[i];
        float4 bv = *(const float4*)&bet[i];
        float y0 = (xv.x - mu) * inv * gv.x + bv.x;
        float y1 = (xv.y - mu) * inv * gv.y + bv.y;
        float y2 = (xv.z - mu) * inv * gv.z + bv.z;
        float y3 = (xv.w - mu) * inv * gv.w + bv.w;
        size_t o = (size_t)row * HID + i;
        *(__half2*)(hi + o) = __floats2half2_rn(y0, y1);
        *(__half2*)(hi + o + 2) = __floats2half2_rn(y2, y3);
    }
}

// ---------------------------------------------------------------------------
extern "C" void kernel_launch(void* const* d_in, const int* in_sizes, int n_in,
                              void* d_out, int out_size) {
    const float* emb  = (const float*)d_in[0];
    const float* keys = (const float*)d_in[1];
    const float* vals = (const float*)d_in[2];
    const float* Wq   = (const float*)d_in[3];
    const float* bq   = (const float*)d_in[4];
    const float* Wre  = (const float*)d_in[5];
    const float* bre  = (const float*)d_in[6];
    const float* ln_g = (const float*)d_in[7];
    const float* ln_b = (const float*)d_in[8];
    float* out = (float*)d_out;

    float *qbuf, *aT;
    __half *ehi, *lnhi, *wqhi, *wrehi;
    __half *qhi, *qlo, *khi, *vhi;
    cudaGetSymbolAddress((void**)&qbuf, g_q);
    cudaGetSymbolAddress((void**)&aT, g_attnT);
    cudaGetSymbolAddress((void**)&ehi, g_ehi);
    cudaGetSymbolAddress((void**)&lnhi, g_lnhi);
    cudaGetSymbolAddress((void**)&wqhi, g_wqhi);
    cudaGetSymbolAddress((void**)&wrehi, g_wrehi);
    cudaGetSymbolAddress((void**)&qhi, g_qhi);
    cudaGetSymbolAddress((void**)&qlo, g_qlo);
    cudaGetSymbolAddress((void**)&khi, g_khi);
    cudaGetSymbolAddress((void**)&vhi, g_vhi);

    cudaFuncSetAttribute(gemm_mma_kernel, cudaFuncAttributeMaxDynamicSharedMemorySize, G1P_SMEM);
    cudaFuncSetAttribute(attn_mma_kernel, cudaFuncAttributeMaxDynamicSharedMemorySize, ATT_SMEM);
    cudaFuncSetAttribute(kvprep_kernel, cudaFuncAttributeMaxDynamicSharedMemorySize, KVP_SMEM);

    static cudaStream_t sA = nullptr, sB = nullptr;
    static cudaEvent_t evRoot = nullptr, evKV = nullptr, evWq = nullptr, evWre = nullptr;
    if (sA == nullptr) {
        cudaStreamCreateWithFlags(&sA, cudaStreamNonBlocking);
        cudaStreamCreateWithFlags(&sB, cudaStreamNonBlocking);
        cudaEventCreateWithFlags(&evRoot, cudaEventDisableTiming);
        cudaEventCreateWithFlags(&evKV, cudaEventDisableTiming);
        cudaEventCreateWithFlags(&evWq, cudaEventDisableTiming);
        cudaEventCreateWithFlags(&evWre, cudaEventDisableTiming);
    }

    cudaEventRecord(evRoot, 0);
    cudaStreamWaitEvent(sA, evRoot, 0);
    cudaStreamWaitEvent(sB, evRoot, 0);

    kvprep_kernel<<<4 * 128, 256, KVP_SMEM, sA>>>(keys, vals, khi, vhi);
    cudaEventRecord(evKV, sA);

    conv16_kernel<<<(HID * HID / 4 + 255) / 256, 256, 0, sB>>>(
        (const float4*)Wq, (__half2*)wqhi, HID * HID / 4);
    cudaEventRecord(evWq, sB);
    conv16_kernel<<<(HID * HID / 4 + 255) / 256, 256, 0, sB>>>(
        (const float4*)Wre, (__half2*)wrehi, HID * HID / 4);
    cudaEventRecord(evWre, sB);

    conv16_kernel<<<(MROWS * HID / 4 + 255) / 256, 256>>>(
        (const float4*)emb, (__half2*)ehi, MROWS * HID / 4);

    cudaStreamWaitEvent(0, evWq, 0);
    gemm_mma_kernel<<<dim3(HID / 128, MROWS / 256), 256, G1P_SMEM>>>(
        ehi, wqhi, bq, qbuf, MROWS, HID, HID);
    qprep_kernel<<<MROWS * 4, 256>>>(qbuf, qhi, qlo);

    cudaStreamWaitEvent(0, evKV, 0);
    attn_mma_kernel<<<dim3(16, 64), 256, ATT_SMEM>>>(qhi, qlo, khi, vhi, aT);
    ln_gather_kernel<<<MROWS, 256>>>(aT, ln_g, ln_b, lnhi);

    cudaStreamWaitEvent(0, evWre, 0);
    gemm_mma_kernel<<<dim3(HID / 128, MROWS / 256), 256, G1P_SMEM>>>(
        lnhi, wrehi, bre, out, MROWS, HID, HID);
}

// round 12
// speedup vs baseline: 2.5412x; 1.0696x over previous
#include <cuda_runtime.h>
#include <cuda_fp16.h>
#include <cstdint>

#define HID 4096
#define MROWS 2048
#define NKV 512
#define VECD 64
#define NHEAD 16
#define NBH 64
#define SDUP 2048

// ---------------- scratch ----------------
__device__ float g_attnT[NBH * SDUP * VECD];
__device__ __half g_q16[MROWS * HID];              // GEMM1 output (fp16)
__device__ __half g_qhi[NBH * SDUP * VECD];        // q in attention layout
__device__ __half g_khi[NBH * NKV * VECD];
__device__ __half g_vhi[NBH * VECD * NKV];
__device__ __half g_ehi[MROWS * HID];
__device__ __half g_lnhi[MROWS * HID];
__device__ __half g_wqhi[HID * HID];
__device__ __half g_wrehi[HID * HID];

// ---------------- PTX helpers ----------------
__device__ __forceinline__ uint32_t smem_u32(const void* p) {
    uint32_t a;
    asm("{ .reg .u64 t; cvta.to.shared.u64 t, %1; cvt.u32.u64 %0, t; }" : "=r"(a) : "l"(p));
    return a;
}
#define CP_ASYNC16(dst, src) \
    asm volatile("cp.async.cg.shared.global [%0], [%1], 16;" :: "r"(dst), "l"(src))
#define CP_COMMIT() asm volatile("cp.async.commit_group;" ::: "memory")
#define CP_WAIT0()  asm volatile("cp.async.wait_group 0;" ::: "memory")

#define LDSM4(r0, r1, r2, r3, addr)                                          \
    asm volatile("ldmatrix.sync.aligned.m8n8.x4.shared.b16 {%0,%1,%2,%3}, [%4];" \
                 : "=r"(r0), "=r"(r1), "=r"(r2), "=r"(r3) : "r"(addr))
#define LDSM2(r0, r1, addr)                                                  \
    asm volatile("ldmatrix.sync.aligned.m8n8.x2.shared.b16 {%0,%1}, [%2];"   \
                 : "=r"(r0), "=r"(r1) : "r"(addr))

__device__ __forceinline__ void mma16816h(float* c, const uint32_t* a, const uint32_t* b) {
    asm volatile(
        "mma.sync.aligned.m16n8k16.row.col.f32.f16.f16.f32 "
        "{%0,%1,%2,%3}, {%4,%5,%6,%7}, {%8,%9}, {%0,%1,%2,%3};"
        : "+f"(c[0]), "+f"(c[1]), "+f"(c[2]), "+f"(c[3])
        : "r"(a[0]), "r"(a[1]), "r"(a[2]), "r"(a[3]), "r"(b[0]), "r"(b[1]));
}

__device__ __forceinline__ uint32_t pack_h2(float a, float b) {
    __half2 t = __floats2half2_rn(a, b);
    return *(uint32_t*)&t;
}

__device__ __forceinline__ uint32_t sw128(int r, int c16) {
    return (uint32_t)(r * 128 + ((c16 ^ (r & 7)) << 4));
}
__device__ __forceinline__ uint32_t sw256(int r, int c16) {
    return (uint32_t)(r * 256 + ((c16 ^ (r & 7)) << 4));
}

// ---------------------------------------------------------------------------
// GEMM: fp16 1-product, templated output type.
// C[M,N] = Ahi[M,K] @ Bhi[N,K]^T + bias
// CTA 256x128 (8 warps, 64x64 warp tiles), BK=64, 2-stage cp.async.
// ---------------------------------------------------------------------------
#define G1P_STAGE 49152
#define G1P_SMEM (2 * G1P_STAGE)
template <typename OutT>
__global__ __launch_bounds__(256, 1)
void gemm_mma_kernel(const __half* __restrict__ Ahi, const __half* __restrict__ Bhi,
                     const float* __restrict__ bias, OutT* __restrict__ C,
                     int M, int N, int K) {
    extern __shared__ char smraw[];
    const uint32_t sbase = smem_u32(smraw);
    const int tid = threadIdx.x;
    const int lane = tid & 31;
    const int warp = tid >> 5;
    const int wm = warp >> 1;
    const int wn = warp & 1;

    const int row0 = blockIdx.y * 256;
    const int col0 = blockIdx.x * 128;
    const __half* pAhi = Ahi + (size_t)row0 * K;
    const __half* pBhi = Bhi + (size_t)col0 * K;
    const int nk = K / 64;

    auto load_stage = [&](int kc, int st) {
        const int kbase = kc * 64;
        const uint32_t stg = sbase + st * G1P_STAGE;
#pragma unroll
        for (int it = 0; it < 8; it++) {
            int idx = tid + it * 256;
            int r = idx >> 3, c = idx & 7;
            CP_ASYNC16(stg + sw128(r, c), pAhi + (size_t)r * K + kbase + c * 8);
        }
#pragma unroll
        for (int it = 0; it < 4; it++) {
            int idx = tid + it * 256;
            int r = idx >> 3, c = idx & 7;
            CP_ASYNC16(stg + 32768 + sw128(r, c), pBhi + (size_t)r * K + kbase + c * 8);
        }
    };

    float acc[4][8][4];
#pragma unroll
    for (int i = 0; i < 4; i++)
#pragma unroll
        for (int j = 0; j < 8; j++)
#pragma unroll
            for (int k = 0; k < 4; k++) acc[i][j][k] = 0.f;

    load_stage(0, 0); CP_COMMIT();

    for (int kc = 0; kc < nk; kc++) {
        CP_WAIT0();
        __syncthreads();
        if (kc + 1 < nk) {
            load_stage(kc + 1, (kc + 1) & 1);
            CP_COMMIT();
        }

        const uint32_t stg = sbase + (kc & 1) * G1P_STAGE;
        const uint32_t sAhi = stg, sBhi = stg + 32768;

#pragma unroll
        for (int ks = 0; ks < 4; ks++) {
            const int arow = wm * 64 + (lane & 15);
            const int ac = ks * 2 + (lane >> 4);
            const int brow = wn * 64 + (lane & 7);
            const int bc = ks * 2 + ((lane >> 3) & 1);

            uint32_t ah[4][4], bf[8][2];
#pragma unroll
            for (int mt = 0; mt < 4; mt++)
                LDSM4(ah[mt][0], ah[mt][1], ah[mt][2], ah[mt][3],
                      sAhi + sw128(arow + mt * 16, ac));
#pragma unroll
            for (int nt = 0; nt < 8; nt++)
                LDSM2(bf[nt][0], bf[nt][1], sBhi + sw128(brow + nt * 8, bc));
#pragma unroll
            for (int mt = 0; mt < 4; mt++)
#pragma unroll
                for (int nt = 0; nt < 8; nt++)
                    mma16816h(acc[mt][nt], ah[mt], bf[nt]);
        }
    }

#pragma unroll
    for (int mt = 0; mt < 4; mt++) {
        int r = row0 + wm * 64 + mt * 16 + (lane >> 2);
#pragma unroll
        for (int nt = 0; nt < 8; nt++) {
            int c = col0 + wn * 64 + nt * 8 + (lane & 3) * 2;
            float b0 = __ldg(bias + c), b1 = __ldg(bias + c + 1);
            if constexpr (sizeof(OutT) == 4) {
                *(float2*)((float*)C + (size_t)r * N + c) =
                    make_float2(acc[mt][nt][0] + b0, acc[mt][nt][1] + b1);
                *(float2*)((float*)C + (size_t)(r + 8) * N + c) =
                    make_float2(acc[mt][nt][2] + b0, acc[mt][nt][3] + b1);
            } else {
                *(__half2*)((__half*)C + (size_t)r * N + c) =
                    __floats2half2_rn(acc[mt][nt][0] + b0, acc[mt][nt][1] + b1);
                *(__half2*)((__half*)C + (size_t)(r + 8) * N + c) =
                    __floats2half2_rn(acc[mt][nt][2] + b0, acc[mt][nt][3] + b1);
            }
        }
    }
}

// ---------------------------------------------------------------------------
// fp32 -> fp16 convert
// ---------------------------------------------------------------------------
__global__ __launch_bounds__(256)
void conv16_kernel(const float4* __restrict__ x, __half2* __restrict__ hi, int n4) {
    int i = blockIdx.x * 256 + threadIdx.x;
    if (i >= n4) return;
    float4 v = x[i];
    hi[2 * i] = __floats2half2_rn(v.x, v.y);
    hi[2 * i + 1] = __floats2half2_rn(v.z, v.w);
}

// ---------------------------------------------------------------------------
// Q prep: fp16 (B,S,HID) -> qhi fp16 [bh][sdup][vec]  (pure transpose)
// ---------------------------------------------------------------------------
__global__ __launch_bounds__(256)
void qprep16_kernel(const __half* __restrict__ q16, __half* __restrict__ qhi) {
    __shared__ __half sm[1024];
    int bid = blockIdx.x;              // (b*512+s)*4 + d
    int d = bid & 3;
    int bs = bid >> 2;
    int b = bs >> 9, s = bs & 511;
    const __half* src = q16 + (size_t)bs * HID + d * 1024;
    int tid = threadIdx.x;
    *(uint2*)&sm[tid * 4] = *(const uint2*)(src + tid * 4);
    __syncthreads();
    int h = tid >> 4;
    int v = (tid * 4) & 63;
    size_t dst = ((size_t)(b * 16 + h) * SDUP + (s * 4 + d)) * VECD + v;
    __half2 p0 = __halves2half2(sm[(v + 0) * 16 + h], sm[(v + 1) * 16 + h]);
    __half2 p1 = __halves2half2(sm[(v + 2) * 16 + h], sm[(v + 3) * 16 + h]);
    *(__half2*)(qhi + dst) = p0;
    *(__half2*)(qhi + dst + 2) = p1;
}

// ---------------------------------------------------------------------------
// KV prep: 4 n-rows per CTA (512 CTAs), 32KB smem
// ---------------------------------------------------------------------------
#define KVP_SMEM (2 * 4 * 1024 * 4)
__global__ __launch_bounds__(256)
void kvprep_kernel(const float* __restrict__ keys, const float* __restrict__ vals,
                   __half* __restrict__ khi, __half* __restrict__ vhi) {
    extern __shared__ float smf[];
    float* sk = smf;
    float* sv = smf + 4 * 1024;
    const int bid = blockIdx.x;
    const int b = bid >> 7, nc = bid & 127;
    const int n0 = nc * 4;
    const int tid = threadIdx.x;

    const float* ksrc = keys + ((size_t)b * NKV + n0) * 1024;
    const float* vsrc = vals + ((size_t)b * NKV + n0) * 1024;
#pragma unroll
    for (int it = 0; it < 4; it++) {
        int i = tid + it * 256;
        *(float4*)&sk[i * 4] = *(const float4*)(ksrc + i * 4);
        *(float4*)&sv[i * 4] = *(const float4*)(vsrc + i * 4);
    }
    __syncthreads();

#pragma unroll
    for (int it = 0; it < 2; it++) {
        int task = tid + it * 256;
        int vg = task & 7, n = (task >> 3) & 3, h = task >> 5;
        uint32_t hhx[4];
#pragma unroll
        for (int j = 0; j < 4; j++) {
            float x0 = sk[n * 1024 + (vg * 8 + j * 2 + 0) * 16 + h];
            float x1 = sk[n * 1024 + (vg * 8 + j * 2 + 1) * 16 + h];
            hhx[j] = pack_h2(x0, x1);
        }
        size_t dst = ((size_t)(b * 16 + h) * NKV + n0 + n) * VECD + vg * 8;
        *(uint4*)(khi + dst) = make_uint4(hhx[0], hhx[1], hhx[2], hhx[3]);
    }

#pragma unroll
    for (int it = 0; it < 4; it++) {
        int task = tid + it * 256;
        int v = task & 63, h = task >> 6;
        uint32_t p0 = pack_h2(sv[0 * 1024 + v * 16 + h], sv[1 * 1024 + v * 16 + h]);
        uint32_t p1 = pack_h2(sv[2 * 1024 + v * 16 + h], sv[3 * 1024 + v * 16 + h]);
        size_t dst = ((size_t)(b * 16 + h) * VECD + v) * NKV + n0;
        *(uint2*)(vhi + dst) = make_uint2(p0, p1);
    }
}

// ---------------------------------------------------------------------------
// Flash attention, fp16 single-product (q and P both hi-only).
// smem: Q 16K | buf0(K 16K, V 16K) | buf1(K 16K, V 16K) = 80K
// ---------------------------------------------------------------------------
#define ATT_SMEM (16384 + 2 * 32768)
__global__ __launch_bounds__(256)
void attn_mma_kernel(const __half* __restrict__ qhi,
                     const __half* __restrict__ khi, const __half* __restrict__ vhi,
                     float* __restrict__ outT) {
    extern __shared__ char smraw[];
    const uint32_t sQ = smem_u32(smraw);
    const uint32_t sKV = sQ + 16384;

    const int tid = threadIdx.x;
    const int lane = tid & 31;
    const int warp = tid >> 5;
    const int g = lane >> 2;
    const int tq = lane & 3;
    const int bh = blockIdx.y;
    const int tile = blockIdx.x;
    const int wrow0 = warp * 16;

    const __half* qh = qhi + ((size_t)bh * SDUP + tile * 128) * VECD;
    const __half* kh = khi + (size_t)bh * NKV * VECD;
    const __half* vh = vhi + (size_t)bh * VECD * NKV;

    auto load_kv = [&](int ck, int buf) {
        const int n0 = ck * 128;
        const uint32_t sK = sKV + buf * 32768;
        const uint32_t sV = sK + 16384;
#pragma unroll
        for (int it = 0; it < 4; it++) {
            int idx = tid + it * 256;
            int r = idx >> 3, c = idx & 7;
            CP_ASYNC16(sK + sw128(r, c), kh + (size_t)(n0 + r) * VECD + c * 8);
            int v = idx >> 4, cc = idx & 15;
            CP_ASYNC16(sV + sw256(v, cc), vh + (size_t)v * NKV + n0 + cc * 8);
        }
    };

#pragma unroll
    for (int it = 0; it < 4; it++) {
        int idx = tid + it * 256;
        int r = idx >> 3, c = idx & 7;
        CP_ASYNC16(sQ + sw128(r, c), qh + (size_t)r * VECD + c * 8);
    }
    load_kv(0, 0);
    CP_COMMIT();

    float oa[8][4];
#pragma unroll
    for (int i = 0; i < 8; i++)
#pragma unroll
        for (int j = 0; j < 4; j++) oa[i][j] = 0.f;
    float m0 = -1e30f, m1 = -1e30f, l0 = 0.f, l1 = 0.f;

    for (int ck = 0; ck < 4; ck++) {
        CP_WAIT0();
        __syncthreads();
        if (ck < 3) {
            load_kv(ck + 1, (ck + 1) & 1);
            CP_COMMIT();
        }
        const uint32_t sK = sKV + (ck & 1) * 32768;
        const uint32_t sV = sK + 16384;

        float S[16][4];
#pragma unroll
        for (int jt = 0; jt < 16; jt++)
#pragma unroll
            for (int j = 0; j < 4; j++) S[jt][j] = 0.f;

#pragma unroll
        for (int ks = 0; ks < 4; ks++) {
            uint32_t ah[4];
            int arow = wrow0 + (lane & 15);
            int ac = ks * 2 + (lane >> 4);
            LDSM4(ah[0], ah[1], ah[2], ah[3], sQ + sw128(arow, ac));
#pragma unroll
            for (int jt = 0; jt < 16; jt++) {
                int brow = jt * 8 + (lane & 7);
                int bc = ks * 2 + ((lane >> 3) & 1);
                uint32_t b2[2];
                LDSM2(b2[0], b2[1], sK + sw128(brow, bc));
                mma16816h(S[jt], ah, b2);
            }
        }

        float cm0 = -1e30f, cm1 = -1e30f;
#pragma unroll
        for (int jt = 0; jt < 16; jt++) {
            S[jt][0] *= 0.125f; S[jt][1] *= 0.125f;
            S[jt][2] *= 0.125f; S[jt][3] *= 0.125f;
            cm0 = fmaxf(cm0, fmaxf(S[jt][0], S[jt][1]));
            cm1 = fmaxf(cm1, fmaxf(S[jt][2], S[jt][3]));
        }
        cm0 = fmaxf(cm0, __shfl_xor_sync(0xffffffffu, cm0, 1));
        cm0 = fmaxf(cm0, __shfl_xor_sync(0xffffffffu, cm0, 2));
        cm1 = fmaxf(cm1, __shfl_xor_sync(0xffffffffu, cm1, 1));
        cm1 = fmaxf(cm1, __shfl_xor_sync(0xffffffffu, cm1, 2));
        float mn0 = fmaxf(m0, cm0), mn1 = fmaxf(m1, cm1);
        float sc0 = __expf(m0 - mn0), sc1 = __expf(m1 - mn1);
        m0 = mn0; m1 = mn1;
        l0 *= sc0; l1 *= sc1;
#pragma unroll
        for (int vt = 0; vt < 8; vt++) {
            oa[vt][0] *= sc0; oa[vt][1] *= sc0;
            oa[vt][2] *= sc1; oa[vt][3] *= sc1;
        }

        float cs0 = 0.f, cs1 = 0.f;
#pragma unroll
        for (int ks = 0; ks < 8; ks++) {
            uint32_t pah[4];
#pragma unroll
            for (int half = 0; half < 2; half++) {
                int jt = ks * 2 + half;
                float p0 = __expf(S[jt][0] - m0);
                float p1 = __expf(S[jt][1] - m0);
                float p2 = __expf(S[jt][2] - m1);
                float p3 = __expf(S[jt][3] - m1);
                cs0 += p0 + p1;
                cs1 += p2 + p3;
                pah[half * 2 + 0] = pack_h2(p0, p1);
                pah[half * 2 + 1] = pack_h2(p2, p3);
            }
#pragma unroll
            for (int vt = 0; vt < 8; vt++) {
                int brow = vt * 8 + (lane & 7);
                int bc = ks * 2 + ((lane >> 3) & 1);
                uint32_t b2[2];
                LDSM2(b2[0], b2[1], sV + sw256(brow, bc));
                mma16816h(oa[vt], pah, b2);
            }
        }
        cs0 += __shfl_xor_sync(0xffffffffu, cs0, 1);
        cs0 += __shfl_xor_sync(0xffffffffu, cs0, 2);
        cs1 += __shfl_xor_sync(0xffffffffu, cs1, 1);
        cs1 += __shfl_xor_sync(0xffffffffu, cs1, 2);
        l0 += cs0; l1 += cs1;
    }

    float inv0 = 1.f / l0, inv1 = 1.f / l1;
    float* orow0 = outT + ((size_t)bh * SDUP + tile * 128 + wrow0 + g) * VECD;
    float* orow1 = orow0 + 8 * VECD;
#pragma unroll
    for (int vt = 0; vt < 8; vt++) {
        int v = vt * 8 + tq * 2;
        *(float2*)(orow0 + v) = make_float2(oa[vt][0] * inv0, oa[vt][1] * inv0);
        *(float2*)(orow1 + v) = make_float2(oa[vt][2] * inv1, oa[vt][3] * inv1);
    }
}

// ---------------------------------------------------------------------------
// LayerNorm gather -> fp16 (hi only)
// ---------------------------------------------------------------------------
__global__ __launch_bounds__(256)
void ln_gather_kernel(const float* __restrict__ attnT, const float* __restrict__ gam,
                      const float* __restrict__ bet, __half* __restrict__ hi) {
    __shared__ float xs[HID];
    __shared__ float red[8];
    __shared__ float red2[8];
    const int row = blockIdx.x;
    const int b = row >> 9, s = row & 511;
    const int tid = threadIdx.x;
    const int lane = tid & 31, w = tid >> 5;

    float lsum = 0.f;
#pragma unroll
    for (int it = 0; it < 4; it++) {
        int i = it * 1024 + tid * 4;
        int h = i >> 8, d = (i >> 6) & 3, v = i & 63;
        const float* src = attnT + ((size_t)(b * 16 + h) * SDUP + (s * 4 + d)) * VECD + v;
        float4 x = *(const float4*)src;
        *(float4*)&xs[i] = x;
        lsum += x.x + x.y + x.z + x.w;
    }
#pragma unroll
    for (int o = 16; o > 0; o >>= 1) lsum += __shfl_xor_sync(0xffffffffu, lsum, o);
    if (lane == 0) red[w] = lsum;
    __syncthreads();
    float tot = 0.f;
#pragma unroll
    for (int j = 0; j < 8; j++) tot += red[j];
    float mu = tot * (1.f / HID);

    float lv = 0.f;
    for (int i = tid; i < HID; i += 256) {
        float d = xs[i] - mu;
        lv += d * d;
    }
#pragma unroll
    for (int o = 16; o > 0; o >>= 1) lv += __shfl_xor_sync(0xffffffffu, lv, o);
    if (lane == 0) red2[w] = lv;
    __syncthreads();
    float tv = 0.f;
#pragma unroll
    for (int j = 0; j < 8; j++) tv += red2[j];
    float inv = rsqrtf(tv * (1.f / HID) + 1e-12f);

#pragma unroll
    for (int it = 0; it < 4; it++) {
        int i = it * 1024 + tid * 4;
        float4 xv = *(const float4*)&xs[i];
        float4 gv = *(const float4*)&gam[i];
        float4 bv = *(const float4*)&bet[i];
        float y0 = (xv.x - mu) * inv * gv.x + bv.x;
        float y1 = (xv.y - mu) * inv * gv.y + bv.y;
        float y2 = (xv.z - mu) * inv * gv.z + bv.z;
        float y3 = (xv.w - mu) * inv * gv.w + bv.w;
        size_t o = (size_t)row * HID + i;
        *(__half2*)(hi + o) = __floats2half2_rn(y0, y1);
        *(__half2*)(hi + o + 2) = __floats2half2_rn(y2, y3);
    }
}

// ---------------------------------------------------------------------------
extern "C" void kernel_launch(void* const* d_in, const int* in_sizes, int n_in,
                              void* d_out, int out_size) {
    const float* emb  = (const float*)d_in[0];
    const float* keys = (const float*)d_in[1];
    const float* vals = (const float*)d_in[2];
    const float* Wq   = (const float*)d_in[3];
    const float* bq   = (const float*)d_in[4];
    const float* Wre  = (const float*)d_in[5];
    const float* bre  = (const float*)d_in[6];
    const float* ln_g = (const float*)d_in[7];
    const float* ln_b = (const float*)d_in[8];
    float* out = (float*)d_out;

    float* aT;
    __half *q16, *ehi, *lnhi, *wqhi, *wrehi, *qhi, *khi, *vhi;
    cudaGetSymbolAddress((void**)&aT, g_attnT);
    cudaGetSymbolAddress((void**)&q16, g_q16);
    cudaGetSymbolAddress((void**)&ehi, g_ehi);
    cudaGetSymbolAddress((void**)&lnhi, g_lnhi);
    cudaGetSymbolAddress((void**)&wqhi, g_wqhi);
    cudaGetSymbolAddress((void**)&wrehi, g_wrehi);
    cudaGetSymbolAddress((void**)&qhi, g_qhi);
    cudaGetSymbolAddress((void**)&khi, g_khi);
    cudaGetSymbolAddress((void**)&vhi, g_vhi);

    cudaFuncSetAttribute(gemm_mma_kernel<__half>, cudaFuncAttributeMaxDynamicSharedMemorySize, G1P_SMEM);
    cudaFuncSetAttribute(gemm_mma_kernel<float>, cudaFuncAttributeMaxDynamicSharedMemorySize, G1P_SMEM);
    cudaFuncSetAttribute(attn_mma_kernel, cudaFuncAttributeMaxDynamicSharedMemorySize, ATT_SMEM);
    cudaFuncSetAttribute(kvprep_kernel, cudaFuncAttributeMaxDynamicSharedMemorySize, KVP_SMEM);

    static cudaStream_t sA = nullptr, sB = nullptr;
    static cudaEvent_t evRoot = nullptr, evKV = nullptr, evWq = nullptr, evWre = nullptr;
    if (sA == nullptr) {
        cudaStreamCreateWithFlags(&sA, cudaStreamNonBlocking);
        cudaStreamCreateWithFlags(&sB, cudaStreamNonBlocking);
        cudaEventCreateWithFlags(&evRoot, cudaEventDisableTiming);
        cudaEventCreateWithFlags(&evKV, cudaEventDisableTiming);
        cudaEventCreateWithFlags(&evWq, cudaEventDisableTiming);
        cudaEventCreateWithFlags(&evWre, cudaEventDisableTiming);
    }

    cudaEventRecord(evRoot, 0);
    cudaStreamWaitEvent(sA, evRoot, 0);
    cudaStreamWaitEvent(sB, evRoot, 0);

    kvprep_kernel<<<4 * 128, 256, KVP_SMEM, sA>>>(keys, vals, khi, vhi);
    cudaEventRecord(evKV, sA);

    conv16_kernel<<<(HID * HID / 4 + 255) / 256, 256, 0, sB>>>(
        (const float4*)Wq, (__half2*)wqhi, HID * HID / 4);
    cudaEventRecord(evWq, sB);
    conv16_kernel<<<(HID * HID / 4 + 255) / 256, 256, 0, sB>>>(
        (const float4*)Wre, (__half2*)wrehi, HID * HID / 4);
    cudaEventRecord(evWre, sB);

    conv16_kernel<<<(MROWS * HID / 4 + 255) / 256, 256>>>(
        (const float4*)emb, (__half2*)ehi, MROWS * HID / 4);

    cudaStreamWaitEvent(0, evWq, 0);
    gemm_mma_kernel<__half><<<dim3(HID / 128, MROWS / 256), 256, G1P_SMEM>>>(
        ehi, wqhi, bq, q16, MROWS, HID, HID);
    qprep16_kernel<<<MROWS * 4, 256>>>(q16, qhi);

    cudaStreamWaitEvent(0, evKV, 0);
    attn_mma_kernel<<<dim3(16, 64), 256, ATT_SMEM>>>(qhi, khi, vhi, aT);
    ln_gather_kernel<<<MROWS, 256>>>(aT, ln_g, ln_b, lnhi);

    cudaStreamWaitEvent(0, evWre, 0);
    gemm_mma_kernel<float><<<dim3(HID / 128, MROWS / 256), 256, G1P_SMEM>>>(
        lnhi, wrehi, bre, out, MROWS, HID, HID);
}

// round 13
// speedup vs baseline: 2.6198x; 1.0309x over previous
#include <cuda_runtime.h>
#include <cuda_fp16.h>
#include <cstdint>

#define HID 4096
#define MROWS 2048
#define NKV 512
#define VECD 64
#define NHEAD 16
#define NBH 64
#define SDUP 2048

// ---------------- scratch ----------------
__device__ float g_attnT[NBH * SDUP * VECD];
__device__ __half g_qhi[NBH * SDUP * VECD];        // q in attention layout
__device__ __half g_khi[NBH * NKV * VECD];
__device__ __half g_vhi[NBH * VECD * NKV];
__device__ __half g_ehi[MROWS * HID];
__device__ __half g_lnhi[MROWS * HID];
__device__ __half g_wqp[HID * HID];                // Wq, rows permuted to (h,d,v)
__device__ __half g_wrehi[HID * HID];

// ---------------- PTX helpers ----------------
__device__ __forceinline__ uint32_t smem_u32(const void* p) {
    uint32_t a;
    asm("{ .reg .u64 t; cvta.to.shared.u64 t, %1; cvt.u32.u64 %0, t; }" : "=r"(a) : "l"(p));
    return a;
}
#define CP_ASYNC16(dst, src) \
    asm volatile("cp.async.cg.shared.global [%0], [%1], 16;" :: "r"(dst), "l"(src))
#define CP_COMMIT() asm volatile("cp.async.commit_group;" ::: "memory")
#define CP_WAIT0()  asm volatile("cp.async.wait_group 0;" ::: "memory")
#define CP_WAIT1()  asm volatile("cp.async.wait_group 1;" ::: "memory")

#define LDSM4(r0, r1, r2, r3, addr)                                          \
    asm volatile("ldmatrix.sync.aligned.m8n8.x4.shared.b16 {%0,%1,%2,%3}, [%4];" \
                 : "=r"(r0), "=r"(r1), "=r"(r2), "=r"(r3) : "r"(addr))
#define LDSM2(r0, r1, addr)                                                  \
    asm volatile("ldmatrix.sync.aligned.m8n8.x2.shared.b16 {%0,%1}, [%2];"   \
                 : "=r"(r0), "=r"(r1) : "r"(addr))

__device__ __forceinline__ void mma16816h(float* c, const uint32_t* a, const uint32_t* b) {
    asm volatile(
        "mma.sync.aligned.m16n8k16.row.col.f32.f16.f16.f32 "
        "{%0,%1,%2,%3}, {%4,%5,%6,%7}, {%8,%9}, {%0,%1,%2,%3};"
        : "+f"(c[0]), "+f"(c[1]), "+f"(c[2]), "+f"(c[3])
        : "r"(a[0]), "r"(a[1]), "r"(a[2]), "r"(a[3]), "r"(b[0]), "r"(b[1]));
}

__device__ __forceinline__ uint32_t pack_h2(float a, float b) {
    __half2 t = __floats2half2_rn(a, b);
    return *(uint32_t*)&t;
}

__device__ __forceinline__ uint32_t sw128(int r, int c16) {
    return (uint32_t)(r * 128 + ((c16 ^ (r & 7)) << 4));
}
__device__ __forceinline__ uint32_t sw256(int r, int c16) {
    return (uint32_t)(r * 256 + ((c16 ^ (r & 7)) << 4));
}

// ---------------------------------------------------------------------------
// GEMM: fp16 1-product, 3-stage cp.async (wait_group 1 slack).
// C[M,N] = Ahi[M,K] @ Bhi[N,K]^T + bias
// CTA 256x128 (8 warps, 64x64 warp tiles), BK=64.
// QPERM=true: B rows are permuted Wq (n' = h*256+d*64+v); epilogue stores
// fp16 directly into attention layout qhi[bh][sdup][v], bias gathered by
// original index j = d*1024 + v*16 + h.
// ---------------------------------------------------------------------------
#define G1P_STAGE 49152
#define G1P_SMEM (3 * G1P_STAGE)
template <typename OutT, bool QPERM>
__global__ __launch_bounds__(256, 1)
void gemm_mma_kernel(const __half* __restrict__ Ahi, const __half* __restrict__ Bhi,
                     const float* __restrict__ bias, OutT* __restrict__ C,
                     int M, int N, int K) {
    extern __shared__ char smraw[];
    const uint32_t sbase = smem_u32(smraw);
    const int tid = threadIdx.x;
    const int lane = tid & 31;
    const int warp = tid >> 5;
    const int wm = warp >> 1;
    const int wn = warp & 1;

    const int row0 = blockIdx.y * 256;
    const int col0 = blockIdx.x * 128;
    const __half* pAhi = Ahi + (size_t)row0 * K;
    const __half* pBhi = Bhi + (size_t)col0 * K;
    const int nk = K / 64;

    auto load_stage = [&](int kc, int st) {
        const int kbase = kc * 64;
        const uint32_t stg = sbase + st * G1P_STAGE;
#pragma unroll
        for (int it = 0; it < 8; it++) {
            int idx = tid + it * 256;
            int r = idx >> 3, c = idx & 7;
            CP_ASYNC16(stg + sw128(r, c), pAhi + (size_t)r * K + kbase + c * 8);
        }
#pragma unroll
        for (int it = 0; it < 4; it++) {
            int idx = tid + it * 256;
            int r = idx >> 3, c = idx & 7;
            CP_ASYNC16(stg + 32768 + sw128(r, c), pBhi + (size_t)r * K + kbase + c * 8);
        }
    };

    float acc[4][8][4];
#pragma unroll
    for (int i = 0; i < 4; i++)
#pragma unroll
        for (int j = 0; j < 8; j++)
#pragma unroll
            for (int k = 0; k < 4; k++) acc[i][j][k] = 0.f;

    load_stage(0, 0); CP_COMMIT();
    load_stage(1, 1); CP_COMMIT();

    for (int kc = 0; kc < nk; kc++) {
        if (kc == nk - 1) { CP_WAIT0(); } else { CP_WAIT1(); }
        __syncthreads();
        if (kc + 2 < nk) {
            load_stage(kc + 2, (kc + 2) % 3);
            CP_COMMIT();
        }

        const uint32_t stg = sbase + (kc % 3) * G1P_STAGE;
        const uint32_t sAhi = stg, sBhi = stg + 32768;

#pragma unroll
        for (int ks = 0; ks < 4; ks++) {
            const int arow = wm * 64 + (lane & 15);
            const int ac = ks * 2 + (lane >> 4);
            const int brow = wn * 64 + (lane & 7);
            const int bc = ks * 2 + ((lane >> 3) & 1);

            uint32_t ah[4][4], bf[8][2];
#pragma unroll
            for (int mt = 0; mt < 4; mt++)
                LDSM4(ah[mt][0], ah[mt][1], ah[mt][2], ah[mt][3],
                      sAhi + sw128(arow + mt * 16, ac));
#pragma unroll
            for (int nt = 0; nt < 8; nt++)
                LDSM2(bf[nt][0], bf[nt][1], sBhi + sw128(brow + nt * 8, bc));
#pragma unroll
            for (int mt = 0; mt < 4; mt++)
#pragma unroll
                for (int nt = 0; nt < 8; nt++)
                    mma16816h(acc[mt][nt], ah[mt], bf[nt]);
        }
    }

#pragma unroll
    for (int mt = 0; mt < 4; mt++) {
        int r = row0 + wm * 64 + mt * 16 + (lane >> 2);
#pragma unroll
        for (int nt = 0; nt < 8; nt++) {
            int c = col0 + wn * 64 + nt * 8 + (lane & 3) * 2;
            if constexpr (QPERM) {
                // c = n' = h*256 + dd*64 + v ; rows r, r+8 share b (256-blocks)
                int h = c >> 8, dd = (c >> 6) & 3, v = c & 63;
                int b = r >> 9, s = r & 511;
                float b0 = __ldg(bias + dd * 1024 + v * 16 + h);
                float b1 = __ldg(bias + dd * 1024 + (v + 1) * 16 + h);
                size_t dst0 = ((size_t)(b * 16 + h) * SDUP + (s * 4 + dd)) * VECD + v;
                size_t dst1 = ((size_t)(b * 16 + h) * SDUP + ((s + 8) * 4 + dd)) * VECD + v;
                *(__half2*)((__half*)C + dst0) =
                    __floats2half2_rn(acc[mt][nt][0] + b0, acc[mt][nt][1] + b1);
                *(__half2*)((__half*)C + dst1) =
                    __floats2half2_rn(acc[mt][nt][2] + b0, acc[mt][nt][3] + b1);
            } else {
                float b0 = __ldg(bias + c), b1 = __ldg(bias + c + 1);
                *(float2*)((float*)C + (size_t)r * N + c) =
                    make_float2(acc[mt][nt][0] + b0, acc[mt][nt][1] + b1);
                *(float2*)((float*)C + (size_t)(r + 8) * N + c) =
                    make_float2(acc[mt][nt][2] + b0, acc[mt][nt][3] + b1);
            }
        }
    }
}

// ---------------------------------------------------------------------------
// fp32 -> fp16 convert (plain)
// ---------------------------------------------------------------------------
__global__ __launch_bounds__(256)
void conv16_kernel(const float4* __restrict__ x, __half2* __restrict__ hi, int n4) {
    int i = blockIdx.x * 256 + threadIdx.x;
    if (i >= n4) return;
    float4 v = x[i];
    hi[2 * i] = __floats2half2_rn(v.x, v.y);
    hi[2 * i + 1] = __floats2half2_rn(v.z, v.w);
}

// fp32 -> fp16 Wq with row permutation: row n'=h*256+d*64+v  <-  row j=d*1024+v*16+h
__global__ __launch_bounds__(256)
void convq_kernel(const float* __restrict__ Wq, __half* __restrict__ wqp) {
    int np = blockIdx.x;               // 0..4095
    int h = np >> 8, dd = (np >> 6) & 3, v = np & 63;
    int j = dd * 1024 + v * 16 + h;
    const float4* src = (const float4*)(Wq + (size_t)j * HID);
    __half2* dst = (__half2*)(wqp + (size_t)np * HID);
    int tid = threadIdx.x;
#pragma unroll
    for (int it = 0; it < 4; it++) {
        int i = tid + it * 256;        // 0..1023 float4s
        float4 x = src[i];
        dst[2 * i] = __floats2half2_rn(x.x, x.y);
        dst[2 * i + 1] = __floats2half2_rn(x.z, x.w);
    }
}

// ---------------------------------------------------------------------------
// KV prep: 4 n-rows per CTA (512 CTAs), 32KB smem
// ---------------------------------------------------------------------------
#define KVP_SMEM (2 * 4 * 1024 * 4)
__global__ __launch_bounds__(256)
void kvprep_kernel(const float* __restrict__ keys, const float* __restrict__ vals,
                   __half* __restrict__ khi, __half* __restrict__ vhi) {
    extern __shared__ float smf[];
    float* sk = smf;
    float* sv = smf + 4 * 1024;
    const int bid = blockIdx.x;
    const int b = bid >> 7, nc = bid & 127;
    const int n0 = nc * 4;
    const int tid = threadIdx.x;

    const float* ksrc = keys + ((size_t)b * NKV + n0) * 1024;
    const float* vsrc = vals + ((size_t)b * NKV + n0) * 1024;
#pragma unroll
    for (int it = 0; it < 4; it++) {
        int i = tid + it * 256;
        *(float4*)&sk[i * 4] = *(const float4*)(ksrc + i * 4);
        *(float4*)&sv[i * 4] = *(const float4*)(vsrc + i * 4);
    }
    __syncthreads();

#pragma unroll
    for (int it = 0; it < 2; it++) {
        int task = tid + it * 256;
        int vg = task & 7, n = (task >> 3) & 3, h = task >> 5;
        uint32_t hhx[4];
#pragma unroll
        for (int j = 0; j < 4; j++) {
            float x0 = sk[n * 1024 + (vg * 8 + j * 2 + 0) * 16 + h];
            float x1 = sk[n * 1024 + (vg * 8 + j * 2 + 1) * 16 + h];
            hhx[j] = pack_h2(x0, x1);
        }
        size_t dst = ((size_t)(b * 16 + h) * NKV + n0 + n) * VECD + vg * 8;
        *(uint4*)(khi + dst) = make_uint4(hhx[0], hhx[1], hhx[2], hhx[3]);
    }

#pragma unroll
    for (int it = 0; it < 4; it++) {
        int task = tid + it * 256;
        int v = task & 63, h = task >> 6;
        uint32_t p0 = pack_h2(sv[0 * 1024 + v * 16 + h], sv[1 * 1024 + v * 16 + h]);
        uint32_t p1 = pack_h2(sv[2 * 1024 + v * 16 + h], sv[3 * 1024 + v * 16 + h]);
        size_t dst = ((size_t)(b * 16 + h) * VECD + v) * NKV + n0;
        *(uint2*)(vhi + dst) = make_uint2(p0, p1);
    }
}

// ---------------------------------------------------------------------------
// Flash attention, fp16 single-product (unchanged from R12)
// ---------------------------------------------------------------------------
#define ATT_SMEM (16384 + 2 * 32768)
__global__ __launch_bounds__(256)
void attn_mma_kernel(const __half* __restrict__ qhi,
                     const __half* __restrict__ khi, const __half* __restrict__ vhi,
                     float* __restrict__ outT) {
    extern __shared__ char smraw[];
    const uint32_t sQ = smem_u32(smraw);
    const uint32_t sKV = sQ + 16384;

    const int tid = threadIdx.x;
    const int lane = tid & 31;
    const int warp = tid >> 5;
    const int g = lane >> 2;
    const int tq = lane & 3;
    const int bh = blockIdx.y;
    const int tile = blockIdx.x;
    const int wrow0 = warp * 16;

    const __half* qh = qhi + ((size_t)bh * SDUP + tile * 128) * VECD;
    const __half* kh = khi + (size_t)bh * NKV * VECD;
    const __half* vh = vhi + (size_t)bh * VECD * NKV;

    auto load_kv = [&](int ck, int buf) {
        const int n0 = ck * 128;
        const uint32_t sK = sKV + buf * 32768;
        const uint32_t sV = sK + 16384;
#pragma unroll
        for (int it = 0; it < 4; it++) {
            int idx = tid + it * 256;
            int r = idx >> 3, c = idx & 7;
            CP_ASYNC16(sK + sw128(r, c), kh + (size_t)(n0 + r) * VECD + c * 8);
            int v = idx >> 4, cc = idx & 15;
            CP_ASYNC16(sV + sw256(v, cc), vh + (size_t)v * NKV + n0 + cc * 8);
        }
    };

#pragma unroll
    for (int it = 0; it < 4; it++) {
        int idx = tid + it * 256;
        int r = idx >> 3, c = idx & 7;
        CP_ASYNC16(sQ + sw128(r, c), qh + (size_t)r * VECD + c * 8);
    }
    load_kv(0, 0);
    CP_COMMIT();

    float oa[8][4];
#pragma unroll
    for (int i = 0; i < 8; i++)
#pragma unroll
        for (int j = 0; j < 4; j++) oa[i][j] = 0.f;
    float m0 = -1e30f, m1 = -1e30f, l0 = 0.f, l1 = 0.f;

    for (int ck = 0; ck < 4; ck++) {
        CP_WAIT0();
        __syncthreads();
        if (ck < 3) {
            load_kv(ck + 1, (ck + 1) & 1);
            CP_COMMIT();
        }
        const uint32_t sK = sKV + (ck & 1) * 32768;
        const uint32_t sV = sK + 16384;

        float S[16][4];
#pragma unroll
        for (int jt = 0; jt < 16; jt++)
#pragma unroll
            for (int j = 0; j < 4; j++) S[jt][j] = 0.f;

#pragma unroll
        for (int ks = 0; ks < 4; ks++) {
            uint32_t ah[4];
            int arow = wrow0 + (lane & 15);
            int ac = ks * 2 + (lane >> 4);
            LDSM4(ah[0], ah[1], ah[2], ah[3], sQ + sw128(arow, ac));
#pragma unroll
            for (int jt = 0; jt < 16; jt++) {
                int brow = jt * 8 + (lane & 7);
                int bc = ks * 2 + ((lane >> 3) & 1);
                uint32_t b2[2];
                LDSM2(b2[0], b2[1], sK + sw128(brow, bc));
                mma16816h(S[jt], ah, b2);
            }
        }

        float cm0 = -1e30f, cm1 = -1e30f;
#pragma unroll
        for (int jt = 0; jt < 16; jt++) {
            S[jt][0] *= 0.125f; S[jt][1] *= 0.125f;
            S[jt][2] *= 0.125f; S[jt][3] *= 0.125f;
            cm0 = fmaxf(cm0, fmaxf(S[jt][0], S[jt][1]));
            cm1 = fmaxf(cm1, fmaxf(S[jt][2], S[jt][3]));
        }
        cm0 = fmaxf(cm0, __shfl_xor_sync(0xffffffffu, cm0, 1));
        cm0 = fmaxf(cm0, __shfl_xor_sync(0xffffffffu, cm0, 2));
        cm1 = fmaxf(cm1, __shfl_xor_sync(0xffffffffu, cm1, 1));
        cm1 = fmaxf(cm1, __shfl_xor_sync(0xffffffffu, cm1, 2));
        float mn0 = fmaxf(m0, cm0), mn1 = fmaxf(m1, cm1);
        float sc0 = __expf(m0 - mn0), sc1 = __expf(m1 - mn1);
        m0 = mn0; m1 = mn1;
        l0 *= sc0; l1 *= sc1;
#pragma unroll
        for (int vt = 0; vt < 8; vt++) {
            oa[vt][0] *= sc0; oa[vt][1] *= sc0;
            oa[vt][2] *= sc1; oa[vt][3] *= sc1;
        }

        float cs0 = 0.f, cs1 = 0.f;
#pragma unroll
        for (int ks = 0; ks < 8; ks++) {
            uint32_t pah[4];
#pragma unroll
            for (int half = 0; half < 2; half++) {
                int jt = ks * 2 + half;
                float p0 = __expf(S[jt][0] - m0);
                float p1 = __expf(S[jt][1] - m0);
                float p2 = __expf(S[jt][2] - m1);
                float p3 = __expf(S[jt][3] - m1);
                cs0 += p0 + p1;
                cs1 += p2 + p3;
                pah[half * 2 + 0] = pack_h2(p0, p1);
                pah[half * 2 + 1] = pack_h2(p2, p3);
            }
#pragma unroll
            for (int vt = 0; vt < 8; vt++) {
                int brow = vt * 8 + (lane & 7);
                int bc = ks * 2 + ((lane >> 3) & 1);
                uint32_t b2[2];
                LDSM2(b2[0], b2[1], sV + sw256(brow, bc));
                mma16816h(oa[vt], pah, b2);
            }
        }
        cs0 += __shfl_xor_sync(0xffffffffu, cs0, 1);
        cs0 += __shfl_xor_sync(0xffffffffu, cs0, 2);
        cs1 += __shfl_xor_sync(0xffffffffu, cs1, 1);
        cs1 += __shfl_xor_sync(0xffffffffu, cs1, 2);
        l0 += cs0; l1 += cs1;
    }

    float inv0 = 1.f / l0, inv1 = 1.f / l1;
    float* orow0 = outT + ((size_t)bh * SDUP + tile * 128 + wrow0 + g) * VECD;
    float* orow1 = orow0 + 8 * VECD;
#pragma unroll
    for (int vt = 0; vt < 8; vt++) {
        int v = vt * 8 + tq * 2;
        *(float2*)(orow0 + v) = make_float2(oa[vt][0] * inv0, oa[vt][1] * inv0);
        *(float2*)(orow1 + v) = make_float2(oa[vt][2] * inv1, oa[vt][3] * inv1);
    }
}

// ---------------------------------------------------------------------------
// LayerNorm gather -> fp16 (hi only)
// ---------------------------------------------------------------------------
__global__ __launch_bounds__(256)
void ln_gather_kernel(const float* __restrict__ attnT, const float* __restrict__ gam,
                      const float* __restrict__ bet, __half* __restrict__ hi) {
    __shared__ float xs[HID];
    __shared__ float red[8];
    __shared__ float red2[8];
    const int row = blockIdx.x;
    const int b = row >> 9, s = row & 511;
    const int tid = threadIdx.x;
    const int lane = tid & 31, w = tid >> 5;

    float lsum = 0.f;
#pragma unroll
    for (int it = 0; it < 4; it++) {
        int i = it * 1024 + tid * 4;
        int h = i >> 8, d = (i >> 6) & 3, v = i & 63;
        const float* src = attnT + ((size_t)(b * 16 + h) * SDUP + (s * 4 + d)) * VECD + v;
        float4 x = *(const float4*)src;
        *(float4*)&xs[i] = x;
        lsum += x.x + x.y + x.z + x.w;
    }
#pragma unroll
    for (int o = 16; o > 0; o >>= 1) lsum += __shfl_xor_sync(0xffffffffu, lsum, o);
    if (lane == 0) red[w] = lsum;
    __syncthreads();
    float tot = 0.f;
#pragma unroll
    for (int j = 0; j < 8; j++) tot += red[j];
    float mu = tot * (1.f / HID);

    float lv = 0.f;
    for (int i = tid; i < HID; i += 256) {
        float d = xs[i] - mu;
        lv += d * d;
    }
#pragma unroll
    for (int o = 16; o > 0; o >>= 1) lv += __shfl_xor_sync(0xffffffffu, lv, o);
    if (lane == 0) red2[w] = lv;
    __syncthreads();
    float tv = 0.f;
#pragma unroll
    for (int j = 0; j < 8; j++) tv += red2[j];
    float inv = rsqrtf(tv * (1.f / HID) + 1e-12f);

#pragma unroll
    for (int it = 0; it < 4; it++) {
        int i = it * 1024 + tid * 4;
        float4 xv = *(const float4*)&xs[i];
        float4 gv = *(const float4*)&gam[i];
        float4 bv = *(const float4*)&bet[i];
        float y0 = (xv.x - mu) * inv * gv.x + bv.x;
        float y1 = (xv.y - mu) * inv * gv.y + bv.y;
        float y2 = (xv.z - mu) * inv * gv.z + bv.z;
        float y3 = (xv.w - mu) * inv * gv.w + bv.w;
        size_t o = (size_t)row * HID + i;
        *(__half2*)(hi + o) = __floats2half2_rn(y0, y1);
        *(__half2*)(hi + o + 2) = __floats2half2_rn(y2, y3);
    }
}

// ---------------------------------------------------------------------------
extern "C" void kernel_launch(void* const* d_in, const int* in_sizes, int n_in,
                              void* d_out, int out_size) {
    const float* emb  = (const float*)d_in[0];
    const float* keys = (const float*)d_in[1];
    const float* vals = (const float*)d_in[2];
    const float* Wq   = (const float*)d_in[3];
    const float* bq   = (const float*)d_in[4];
    const float* Wre  = (const float*)d_in[5];
    const float* bre  = (const float*)d_in[6];
    const float* ln_g = (const float*)d_in[7];
    const float* ln_b = (const float*)d_in[8];
    float* out = (float*)d_out;

    float* aT;
    __half *ehi, *lnhi, *wqp, *wrehi, *qhi, *khi, *vhi;
    cudaGetSymbolAddress((void**)&aT, g_attnT);
    cudaGetSymbolAddress((void**)&ehi, g_ehi);
    cudaGetSymbolAddress((void**)&lnhi, g_lnhi);
    cudaGetSymbolAddress((void**)&wqp, g_wqp);
    cudaGetSymbolAddress((void**)&wrehi, g_wrehi);
    cudaGetSymbolAddress((void**)&qhi, g_qhi);
    cudaGetSymbolAddress((void**)&khi, g_khi);
    cudaGetSymbolAddress((void**)&vhi, g_vhi);

    cudaFuncSetAttribute((const void*)gemm_mma_kernel<__half, true>,
                         cudaFuncAttributeMaxDynamicSharedMemorySize, G1P_SMEM);
    cudaFuncSetAttribute((const void*)gemm_mma_kernel<float, false>,
                         cudaFuncAttributeMaxDynamicSharedMemorySize, G1P_SMEM);
    cudaFuncSetAttribute(attn_mma_kernel, cudaFuncAttributeMaxDynamicSharedMemorySize, ATT_SMEM);
    cudaFuncSetAttribute(kvprep_kernel, cudaFuncAttributeMaxDynamicSharedMemorySize, KVP_SMEM);

    static cudaStream_t sA = nullptr, sB = nullptr;
    static cudaEvent_t evRoot = nullptr, evKV = nullptr, evWq = nullptr, evWre = nullptr;
    if (sA == nullptr) {
        cudaStreamCreateWithFlags(&sA, cudaStreamNonBlocking);
        cudaStreamCreateWithFlags(&sB, cudaStreamNonBlocking);
        cudaEventCreateWithFlags(&evRoot, cudaEventDisableTiming);
        cudaEventCreateWithFlags(&evKV, cudaEventDisableTiming);
        cudaEventCreateWithFlags(&evWq, cudaEventDisableTiming);
        cudaEventCreateWithFlags(&evWre, cudaEventDisableTiming);
    }

    cudaEventRecord(evRoot, 0);
    cudaStreamWaitEvent(sA, evRoot, 0);
    cudaStreamWaitEvent(sB, evRoot, 0);

    kvprep_kernel<<<4 * 128, 256, KVP_SMEM, sA>>>(keys, vals, khi, vhi);
    cudaEventRecord(evKV, sA);

    convq_kernel<<<HID, 256, 0, sB>>>(Wq, wqp);
    cudaEventRecord(evWq, sB);
    conv16_kernel<<<(HID * HID / 4 + 255) / 256, 256, 0, sB>>>(
        (const float4*)Wre, (__half2*)wrehi, HID * HID / 4);
    cudaEventRecord(evWre, sB);

    conv16_kernel<<<(MROWS * HID / 4 + 255) / 256, 256>>>(
        (const float4*)emb, (__half2*)ehi, MROWS * HID / 4);

    cudaStreamWaitEvent(0, evWq, 0);
    gemm_mma_kernel<__half, true><<<dim3(HID / 128, MROWS / 256), 256, G1P_SMEM>>>(
        ehi, wqp, bq, qhi, MROWS, HID, HID);

    cudaStreamWaitEvent(0, evKV, 0);
    attn_mma_kernel<<<dim3(16, 64), 256, ATT_SMEM>>>(qhi, khi, vhi, aT);
    ln_gather_kernel<<<MROWS, 256>>>(aT, ln_g, ln_b, lnhi);

    cudaStreamWaitEvent(0, evWre, 0);
    gemm_mma_kernel<float, false><<<dim3(HID / 128, MROWS / 256), 256, G1P_SMEM>>>(
        lnhi, wrehi, bre, out, MROWS, HID, HID);
}